// round 1
// baseline (speedup 1.0000x reference)
#include <cuda_runtime.h>
#include <math.h>

#define HID 4096
#define SD 256
#define NS 64           // slots
#define NB 4            // batch
#define NT 4096         // tokens
#define BT (NB*NT)      // 16384
#define LN_EPS 1e-5f
#define ATT_SCALE 0.0625f  // 256^-0.5

// ---------------- scratch (static device globals; no runtime alloc) ----------------
__device__ float g_kvr[BT * 768];          // [b*T+t][ k(0:256) | v(256:512) | rq(512:768) ]
__device__ float g_q[NS * SD];             // slot queries (batch-independent)
__device__ float g_out_sd[NB * NS * SD];   // attn1 output before Wo
__device__ float g_rkv[NB * NS * 512];     // [b*S+s][ rk(0:256) | rv(256:512) ]
__device__ float g_rout_sd[BT * SD];       // attn2 output before Wro
__device__ float g_rout_full[67108864];    // [BT][HID] rout before LN (256 MB)
__device__ double g_loss;

// ---------------- helpers ----------------
__device__ __forceinline__ float block_reduce_sum256(float v, float* red) {
    int tid = threadIdx.x;
    red[tid] = v; __syncthreads();
    #pragma unroll
    for (int o = 128; o > 0; o >>= 1) {
        if (tid < o) red[tid] += red[tid + o];
        __syncthreads();
    }
    float r = red[0];
    __syncthreads();
    return r;
}

__global__ void init_loss_kernel() { g_loss = 0.0; }

// ---------------- tiled SGEMM: A[M,4096] @ {W0,W1,W2}[4096,256] -> C[M, nW*256] ----
// 64x64 tile, BK=16, 256 threads, 4x4 per thread. M, grid sizes are exact multiples.
__global__ __launch_bounds__(256) void gemm_k4096(
    const float* __restrict__ A,
    const float* __restrict__ W0, const float* __restrict__ W1, const float* __restrict__ W2,
    float* __restrict__ C, int ldc)
{
    __shared__ float As[16][64];
    __shared__ float Bs[16][64];
    int tid = threadIdx.x;
    int m0 = blockIdx.x << 6;
    int n0 = blockIdx.y << 6;
    int wsel = n0 >> 8;
    int col0 = n0 & 255;
    const float* W = (wsel == 0) ? W0 : ((wsel == 1) ? W1 : W2);

    int arow = tid >> 2, acol = (tid & 3) << 2;   // A: 64 rows x 16 cols
    int brow = tid >> 4, bcol = (tid & 15) << 2;  // B: 16 rows x 64 cols
    int tx = (tid & 15) << 2, ty = (tid >> 4) << 2;

    const float* Aptr = A + (size_t)(m0 + arow) * 4096 + acol;
    const float* Wptr = W + (size_t)brow * 256 + col0 + bcol;

    float acc[4][4] = {};
    for (int k0 = 0; k0 < 4096; k0 += 16) {
        float4 av = *(const float4*)(Aptr + k0);
        As[acol + 0][arow] = av.x;
        As[acol + 1][arow] = av.y;
        As[acol + 2][arow] = av.z;
        As[acol + 3][arow] = av.w;
        *(float4*)&Bs[brow][bcol] = *(const float4*)(Wptr + (size_t)k0 * 256);
        __syncthreads();
        #pragma unroll
        for (int kk = 0; kk < 16; kk++) {
            float4 a = *(const float4*)&As[kk][ty];
            float4 b = *(const float4*)&Bs[kk][tx];
            acc[0][0] += a.x * b.x; acc[0][1] += a.x * b.y; acc[0][2] += a.x * b.z; acc[0][3] += a.x * b.w;
            acc[1][0] += a.y * b.x; acc[1][1] += a.y * b.y; acc[1][2] += a.y * b.z; acc[1][3] += a.y * b.w;
            acc[2][0] += a.z * b.x; acc[2][1] += a.z * b.y; acc[2][2] += a.z * b.z; acc[2][3] += a.z * b.w;
            acc[3][0] += a.w * b.x; acc[3][1] += a.w * b.y; acc[3][2] += a.w * b.z; acc[3][3] += a.w * b.w;
        }
        __syncthreads();
    }
    #pragma unroll
    for (int i = 0; i < 4; i++) {
        float* cp = C + (size_t)(m0 + ty + i) * ldc + n0 + tx;
        cp[0] = acc[i][0]; cp[1] = acc[i][1]; cp[2] = acc[i][2]; cp[3] = acc[i][3];
    }
}

// ---------------- tiled SGEMM: A[16384,256] @ B[256,4096] -> C[16384,4096] ----------
__global__ __launch_bounds__(256) void gemm_wro(
    const float* __restrict__ A, const float* __restrict__ Bm, float* __restrict__ C)
{
    __shared__ float As[16][64];
    __shared__ float Bs[16][64];
    int tid = threadIdx.x;
    int m0 = blockIdx.x << 6;
    int n0 = blockIdx.y << 6;

    int arow = tid >> 2, acol = (tid & 3) << 2;
    int brow = tid >> 4, bcol = (tid & 15) << 2;
    int tx = (tid & 15) << 2, ty = (tid >> 4) << 2;

    const float* Aptr = A + (size_t)(m0 + arow) * 256 + acol;
    const float* Wptr = Bm + (size_t)brow * 4096 + n0 + bcol;

    float acc[4][4] = {};
    for (int k0 = 0; k0 < 256; k0 += 16) {
        float4 av = *(const float4*)(Aptr + k0);
        As[acol + 0][arow] = av.x;
        As[acol + 1][arow] = av.y;
        As[acol + 2][arow] = av.z;
        As[acol + 3][arow] = av.w;
        *(float4*)&Bs[brow][bcol] = *(const float4*)(Wptr + (size_t)k0 * 4096);
        __syncthreads();
        #pragma unroll
        for (int kk = 0; kk < 16; kk++) {
            float4 a = *(const float4*)&As[kk][ty];
            float4 b = *(const float4*)&Bs[kk][tx];
            acc[0][0] += a.x * b.x; acc[0][1] += a.x * b.y; acc[0][2] += a.x * b.z; acc[0][3] += a.x * b.w;
            acc[1][0] += a.y * b.x; acc[1][1] += a.y * b.y; acc[1][2] += a.y * b.z; acc[1][3] += a.y * b.w;
            acc[2][0] += a.z * b.x; acc[2][1] += a.z * b.y; acc[2][2] += a.z * b.z; acc[2][3] += a.z * b.w;
            acc[3][0] += a.w * b.x; acc[3][1] += a.w * b.y; acc[3][2] += a.w * b.z; acc[3][3] += a.w * b.w;
        }
        __syncthreads();
    }
    #pragma unroll
    for (int i = 0; i < 4; i++) {
        float* cp = C + (size_t)(m0 + ty + i) * 4096 + n0 + tx;
        cp[0] = acc[i][0]; cp[1] = acc[i][1]; cp[2] = acc[i][2]; cp[3] = acc[i][3];
    }
}

// ---------------- attention 1: slots attend to segment ------------------------------
// grid (S, B), 256 threads. scores over T=4096, weighted sum of v -> out_sd[b,s,:]
__global__ __launch_bounds__(256) void attn1_kernel(float* __restrict__ out_sd)
{
    __shared__ float qrow[SD];
    __shared__ float sc[NT];
    __shared__ float red[256];
    int tid = threadIdx.x, s = blockIdx.x, b = blockIdx.y;

    qrow[tid] = g_q[s * SD + tid];
    __syncthreads();
    const float4* q4 = (const float4*)qrow;

    for (int t = tid; t < NT; t += 256) {
        const float4* k4 = (const float4*)(g_kvr + (size_t)(b * NT + t) * 768);
        float acc = 0.f;
        #pragma unroll 8
        for (int i = 0; i < 64; i++) {
            float4 kk = k4[i]; float4 qq = q4[i];
            acc += kk.x * qq.x + kk.y * qq.y + kk.z * qq.z + kk.w * qq.w;
        }
        sc[t] = acc * ATT_SCALE;
    }
    __syncthreads();

    float m = -1e30f;
    for (int t = tid; t < NT; t += 256) m = fmaxf(m, sc[t]);
    red[tid] = m; __syncthreads();
    #pragma unroll
    for (int o = 128; o > 0; o >>= 1) { if (tid < o) red[tid] = fmaxf(red[tid], red[tid + o]); __syncthreads(); }
    m = red[0]; __syncthreads();

    float sum = 0.f;
    for (int t = tid; t < NT; t += 256) { float e = expf(sc[t] - m); sc[t] = e; sum += e; }
    float tot = block_reduce_sum256(sum, red);
    float inv = 1.0f / tot;

    // weighted sum over v; d = tid (coalesced across threads)
    float acc0 = 0.f, acc1 = 0.f;
    const float* vb = g_kvr + (size_t)b * NT * 768 + 256 + tid;
    for (int t = 0; t < NT; t += 2) {
        acc0 += sc[t]     * vb[(size_t)t * 768];
        acc1 += sc[t + 1] * vb[(size_t)(t + 1) * 768];
    }
    out_sd[(b * NS + s) * SD + tid] = (acc0 + acc1) * inv;
}

// ---------------- per-row: out_sd@Wo + slots, layernorm -> updated_slots (d_out) ----
__global__ __launch_bounds__(256) void row_wo_ln(
    const float* __restrict__ Wo, const float* __restrict__ slot_emb,
    const float* __restrict__ lnw, const float* __restrict__ lnb,
    float* __restrict__ outp)
{
    __shared__ float x[SD];
    __shared__ float red[256];
    int tid = threadIdx.x, r = blockIdx.x;  // r = b*NS + s
    int s = r & 63;
    x[tid] = g_out_sd[r * SD + tid];
    __syncthreads();

    float h[16];
    #pragma unroll
    for (int i = 0; i < 16; i++) h[i] = slot_emb[(size_t)s * HID + tid + (i << 8)];
    for (int k = 0; k < 256; k++) {
        float xv = x[k];
        const float* wrow = Wo + (size_t)k * HID + tid;
        #pragma unroll
        for (int i = 0; i < 16; i++) h[i] += xv * wrow[i << 8];
    }
    float sum = 0.f, sq = 0.f;
    #pragma unroll
    for (int i = 0; i < 16; i++) { sum += h[i]; sq += h[i] * h[i]; }
    float tsum = block_reduce_sum256(sum, red);
    float tsq  = block_reduce_sum256(sq, red);
    float mu = tsum * (1.0f / HID);
    float var = tsq * (1.0f / HID) - mu * mu;
    float invs = rsqrtf(var + LN_EPS);
    #pragma unroll
    for (int i = 0; i < 16; i++) {
        int col = tid + (i << 8);
        outp[(size_t)r * HID + col] = (h[i] - mu) * invs * lnw[col] + lnb[col];
    }
}

// ---------------- attention 2: tokens attend to updated slots -----------------------
// grid (T, B), 128 threads
__global__ __launch_bounds__(128) void attn2_kernel()
{
    __shared__ float rq[SD];
    __shared__ float sc[NS];
    __shared__ float red[2];
    int tid = threadIdx.x, t = blockIdx.x, b = blockIdx.y;

    const float* rqsrc = g_kvr + (size_t)(b * NT + t) * 768 + 512;
    rq[tid] = rqsrc[tid];
    rq[tid + 128] = rqsrc[tid + 128];
    __syncthreads();

    if (tid < 64) {
        const float4* rk4 = (const float4*)(g_rkv + (size_t)(b * NS + tid) * 512);
        const float4* q4 = (const float4*)rq;
        float acc = 0.f;
        #pragma unroll 8
        for (int i = 0; i < 64; i++) {
            float4 a = q4[i]; float4 c = rk4[i];
            acc += a.x * c.x + a.y * c.y + a.z * c.z + a.w * c.w;
        }
        sc[tid] = acc * ATT_SCALE;
    }
    __syncthreads();
    if (tid < 32) {
        float m = fmaxf(sc[tid], sc[tid + 32]);
        #pragma unroll
        for (int o = 16; o > 0; o >>= 1) m = fmaxf(m, __shfl_down_sync(0xffffffff, m, o));
        if (tid == 0) red[0] = m;
    }
    __syncthreads();
    float m = red[0];
    if (tid < 64) sc[tid] = expf(sc[tid] - m);
    __syncthreads();
    if (tid < 32) {
        float su = sc[tid] + sc[tid + 32];
        #pragma unroll
        for (int o = 16; o > 0; o >>= 1) su += __shfl_down_sync(0xffffffff, su, o);
        if (tid == 0) red[1] = su;
    }
    __syncthreads();
    float inv = 1.0f / red[1];

    float acc0 = 0.f, acc1 = 0.f;
    #pragma unroll 8
    for (int s = 0; s < 64; s++) {
        float p = sc[s];
        const float* rv = g_rkv + (size_t)(b * NS + s) * 512 + 256;
        acc0 += p * rv[tid];
        acc1 += p * rv[tid + 128];
    }
    size_t o = (size_t)(b * NT + t) * SD;
    g_rout_sd[o + tid] = acc0 * inv;
    g_rout_sd[o + tid + 128] = acc1 * inv;
}

// ---------------- per-row LN + gate + squared-error accumulation --------------------
__global__ __launch_bounds__(256) void loss_ln_kernel(
    const float* __restrict__ seg, const float* __restrict__ lnw,
    const float* __restrict__ lnb, const float* __restrict__ gate_bias)
{
    __shared__ float red[256];
    __shared__ float gsh;
    int tid = threadIdx.x, r = blockIdx.x;
    const float* row = g_rout_full + (size_t)r * HID;

    float v[16];
    #pragma unroll
    for (int i = 0; i < 16; i++) v[i] = row[tid + (i << 8)];

    if (tid == 0) {
        float sg = 0.f;
        for (int i = 0; i < 64; i++) sg += gate_bias[i];
        sg *= (1.0f / 64.0f);
        gsh = 1.0f / (1.0f + expf(-sg));
    }

    float sum = 0.f, sq = 0.f;
    #pragma unroll
    for (int i = 0; i < 16; i++) { sum += v[i]; sq += v[i] * v[i]; }
    float tsum = block_reduce_sum256(sum, red);
    float tsq  = block_reduce_sum256(sq, red);
    float mu = tsum * (1.0f / HID);
    float var = tsq * (1.0f / HID) - mu * mu;
    float invs = rsqrtf(var + LN_EPS);
    float g = gsh;

    const float* segrow = seg + (size_t)r * HID;
    float acc = 0.f;
    #pragma unroll
    for (int i = 0; i < 16; i++) {
        int col = tid + (i << 8);
        float rec = g * ((v[i] - mu) * invs * lnw[col] + lnb[col]);
        float d = rec - segrow[col];
        acc += d * d;
    }
    float bsum = block_reduce_sum256(acc, red);
    if (tid == 0) atomicAdd(&g_loss, (double)bsum);
}

__global__ void finalize_kernel(const float* __restrict__ gate_bias, float* __restrict__ outp)
{
    float sg = 0.f;
    for (int i = 0; i < 64; i++) sg += gate_bias[i];
    sg *= (1.0f / 64.0f);
    float g = 1.0f / (1.0f + expf(-sg));
    outp[NB * NS * HID]     = (float)(g_loss / (double)((size_t)NB * NT * HID));
    outp[NB * NS * HID + 1] = g;
}

// ---------------- launch ------------------------------------------------------------
extern "C" void kernel_launch(void* const* d_in, const int* in_sizes, int n_in,
                              void* d_out, int out_size)
{
    const float* seg      = (const float*)d_in[0];   // [B,T,HID]
    const float* slot_emb = (const float*)d_in[1];   // [S,HID]
    const float* Wq       = (const float*)d_in[2];
    const float* Wk       = (const float*)d_in[3];
    const float* Wv       = (const float*)d_in[4];
    const float* Wo       = (const float*)d_in[5];
    const float* Wrq      = (const float*)d_in[6];
    const float* Wro      = (const float*)d_in[7];
    const float* gateb    = (const float*)d_in[8];
    const float* snw      = (const float*)d_in[9];
    const float* snb      = (const float*)d_in[10];
    const float* rnw      = (const float*)d_in[11];
    const float* rnb      = (const float*)d_in[12];
    float* outp = (float*)d_out;

    float* kvr;      cudaGetSymbolAddress((void**)&kvr, g_kvr);
    float* qbuf;     cudaGetSymbolAddress((void**)&qbuf, g_q);
    float* out_sd;   cudaGetSymbolAddress((void**)&out_sd, g_out_sd);
    float* rkv;      cudaGetSymbolAddress((void**)&rkv, g_rkv);
    float* rout_sd;  cudaGetSymbolAddress((void**)&rout_sd, g_rout_sd);
    float* rout_full;cudaGetSymbolAddress((void**)&rout_full, g_rout_full);

    init_loss_kernel<<<1, 1>>>();

    // k | v | rq = segment_hidden @ {Wk, Wv, Wrq}   (fused: X read once)
    gemm_k4096<<<dim3(BT / 64, 12), 256>>>(seg, Wk, Wv, Wrq, kvr, 768);

    // q = slot_embeddings @ Wq  (batch independent)
    gemm_k4096<<<dim3(1, 4), 256>>>(slot_emb, Wq, nullptr, nullptr, qbuf, 256);

    // slot attention over segment
    attn1_kernel<<<dim3(NS, NB), 256>>>(out_sd);

    // @Wo + residual + layernorm -> updated_slots, written directly to d_out
    row_wo_ln<<<NB * NS, 256>>>(Wo, slot_emb, snw, snb, outp);

    // rk | rv = updated_slots @ {Wk, Wv}
    gemm_k4096<<<dim3((NB * NS) / 64, 8), 256>>>(outp, Wk, Wv, nullptr, rkv, 512);

    // reconstruction attention over slots
    attn2_kernel<<<dim3(NT, NB), 128>>>();

    // rout = rout_sd @ Wro
    gemm_wro<<<dim3(BT / 64, HID / 64), 256>>>(rout_sd, Wro, rout_full);

    // layernorm + gate + MSE accumulation
    loss_ln_kernel<<<BT, 256>>>(seg, rnw, rnb, gateb);

    finalize_kernel<<<1, 1>>>(gateb, outp);
}

// round 2
// speedup vs baseline: 1.5408x; 1.5408x over previous
#include <cuda_runtime.h>
#include <math.h>

#define HID 4096
#define SD 256
#define NS 64           // slots
#define NB 4            // batch
#define NT 4096         // tokens
#define BT (NB*NT)      // 16384
#define LN_EPS 1e-5f
#define ATT_SCALE 0.0625f  // 256^-0.5
#define KC 512          // split-K chunk for skinny GEMMs

// ---------------- scratch (static device globals; no runtime alloc) ----------------
__device__ float g_kvr[BT * 768];          // [b*T+t][ k(0:256) | v(256:512) | rq(512:768) ]
__device__ float g_q[NS * SD];             // slot queries (batch-independent)
__device__ float g_s1[NB * NS * NT];       // attn1 scores/probs [b][s][t]
__device__ float g_out_sd[NB * NS * SD];   // attn1 output before Wo
__device__ float g_spre[NB * NS * HID];    // slots + out@Wo, before LN
__device__ float g_rkv[NB * NS * 512];     // [b*S+s][ rk(0:256) | rv(256:512) ]
__device__ float g_s2[NB * NT * NS];       // attn2 scores/probs [b][t][s]
__device__ float g_rout_sd[BT * SD];       // attn2 output before Wro
__device__ float g_rout_full[67108864];    // [BT][HID] rout before LN (256 MB)
__device__ double g_loss;

// ---------------- helpers ----------------
__device__ __forceinline__ float block_reduce_sum256(float v, float* red) {
    int tid = threadIdx.x;
    red[tid] = v; __syncthreads();
    #pragma unroll
    for (int o = 128; o > 0; o >>= 1) {
        if (tid < o) red[tid] += red[tid + o];
        __syncthreads();
    }
    float r = red[0];
    __syncthreads();
    return r;
}

__global__ void init_loss_kernel() { g_loss = 0.0; }

// ===================================================================================
// Big SGEMM: 128x128 tile, BK=8, 256 threads, 8x8 per thread, double-buffered smem.
// A[M,K] row-major with lda == K. B = one of up to 3 weight matrices.
// If W1 == nullptr: single weight, col0 = n0, ldb as given.
// Else: weights are 256 wide each, wsel = n0>>8, col0 = n0&255, ldb = 256.
// ===================================================================================
__global__ __launch_bounds__(256) void sgemm128(
    const float* __restrict__ A,
    const float* __restrict__ W0, const float* __restrict__ W1, const float* __restrict__ W2,
    float* __restrict__ C, int K, int ldb, int ldc)
{
    __shared__ float As[2][8][128];
    __shared__ float Bs[2][8][128];
    int tid = threadIdx.x;
    int m0 = blockIdx.x << 7;
    int n0 = blockIdx.y << 7;

    const float* W;
    int col0;
    if (W1 == nullptr) { W = W0; col0 = n0; }
    else {
        int wsel = n0 >> 8;
        W = (wsel == 0) ? W0 : ((wsel == 1) ? W1 : W2);
        col0 = n0 & 255;
    }

    int ar = tid >> 1, ac = (tid & 1) << 2;   // A tile: 128 rows x 8 k
    int br = tid >> 5, bc = (tid & 31) << 2;  // B tile: 8 k x 128 cols
    int tx = (tid & 15) << 3, ty = (tid >> 4) << 3;

    const float* Ap = A + (size_t)(m0 + ar) * K + ac;
    const float* Bp = W + (size_t)br * ldb + col0 + bc;

    float4 av = *(const float4*)Ap;
    float4 bv = *(const float4*)Bp;
    As[0][ac + 0][ar] = av.x; As[0][ac + 1][ar] = av.y;
    As[0][ac + 2][ar] = av.z; As[0][ac + 3][ar] = av.w;
    *(float4*)&Bs[0][br][bc] = bv;
    __syncthreads();

    float acc[8][8] = {};
    int buf = 0;
    for (int k0 = 0; k0 < K; k0 += 8) {
        int nxt = k0 + 8;
        if (nxt < K) {
            av = *(const float4*)(Ap + nxt);
            bv = *(const float4*)(Bp + (size_t)nxt * ldb);
        }
        #pragma unroll
        for (int kk = 0; kk < 8; kk++) {
            float a[8], b[8];
            *(float4*)&a[0] = *(const float4*)&As[buf][kk][ty];
            *(float4*)&a[4] = *(const float4*)&As[buf][kk][ty + 4];
            *(float4*)&b[0] = *(const float4*)&Bs[buf][kk][tx];
            *(float4*)&b[4] = *(const float4*)&Bs[buf][kk][tx + 4];
            #pragma unroll
            for (int i = 0; i < 8; i++)
                #pragma unroll
                for (int j = 0; j < 8; j++) acc[i][j] += a[i] * b[j];
        }
        if (nxt < K) {
            int nb = buf ^ 1;
            As[nb][ac + 0][ar] = av.x; As[nb][ac + 1][ar] = av.y;
            As[nb][ac + 2][ar] = av.z; As[nb][ac + 3][ar] = av.w;
            *(float4*)&Bs[nb][br][bc] = bv;
            __syncthreads();
            buf = nb;
        }
    }
    #pragma unroll
    for (int i = 0; i < 8; i++) {
        float* cp = C + (size_t)(m0 + ty + i) * ldc + n0 + tx;
        *(float4*)cp = *(float4*)&acc[i][0];
        *(float4*)(cp + 4) = *(float4*)&acc[i][4];
    }
}

// ===================================================================================
// Skinny split-K GEMM: 64x64 tile over a K-chunk of KC, atomicAdd into pre-zeroed C.
// A[lda-strided], weights 256-wide (wsel by n0). grid (mtiles, ntiles, ksplit)
// ===================================================================================
__global__ __launch_bounds__(256) void gemm_small(
    const float* __restrict__ A, int lda,
    const float* __restrict__ W0, const float* __restrict__ W1,
    float* __restrict__ C, int ldc)
{
    __shared__ float As[16][64];
    __shared__ float Bs[16][64];
    int tid = threadIdx.x;
    int m0 = blockIdx.x << 6;
    int n0 = blockIdx.y << 6;
    int kbase = blockIdx.z * KC;
    const float* W = (n0 >> 8) ? W1 : W0;
    int col0 = n0 & 255;

    int r = tid >> 2, c = (tid & 3) << 2;
    int br = tid >> 4, bc = (tid & 15) << 2;
    int tx = (tid & 15) << 2, ty = (tid >> 4) << 2;

    float acc[4][4] = {};
    for (int k0 = kbase; k0 < kbase + KC; k0 += 16) {
        float4 av = *(const float4*)(A + (size_t)(m0 + r) * lda + k0 + c);
        As[c + 0][r] = av.x; As[c + 1][r] = av.y; As[c + 2][r] = av.z; As[c + 3][r] = av.w;
        *(float4*)&Bs[br][bc] = *(const float4*)(W + (size_t)(k0 + br) * 256 + col0 + bc);
        __syncthreads();
        #pragma unroll
        for (int kk = 0; kk < 16; kk++) {
            float4 a = *(const float4*)&As[kk][ty];
            float4 b = *(const float4*)&Bs[kk][tx];
            acc[0][0] += a.x * b.x; acc[0][1] += a.x * b.y; acc[0][2] += a.x * b.z; acc[0][3] += a.x * b.w;
            acc[1][0] += a.y * b.x; acc[1][1] += a.y * b.y; acc[1][2] += a.y * b.z; acc[1][3] += a.y * b.w;
            acc[2][0] += a.z * b.x; acc[2][1] += a.z * b.y; acc[2][2] += a.z * b.z; acc[2][3] += a.z * b.w;
            acc[3][0] += a.w * b.x; acc[3][1] += a.w * b.y; acc[3][2] += a.w * b.z; acc[3][3] += a.w * b.w;
        }
        __syncthreads();
    }
    #pragma unroll
    for (int i = 0; i < 4; i++)
        #pragma unroll
        for (int j = 0; j < 4; j++)
            atomicAdd(C + (size_t)(m0 + ty + i) * ldc + n0 + tx + j, acc[i][j]);
}

// ===================================================================================
// attn1 scores: S1[b][s][t] = scale * q[s]·k[b,t].  grid (t_tiles=64, b)
// ===================================================================================
__global__ __launch_bounds__(256) void scores1_kernel()
{
    __shared__ float Qs[16][64];
    __shared__ float Ks[16][64];
    int tid = threadIdx.x;
    int t0 = blockIdx.x << 6;
    int b = blockIdx.y;
    int r = tid >> 2, c = (tid & 3) << 2;
    int tx = (tid & 15) << 2, ty = (tid >> 4) << 2;

    float acc[4][4] = {};
    for (int k0 = 0; k0 < SD; k0 += 16) {
        float4 qv = *(const float4*)(g_q + (size_t)r * SD + k0 + c);
        Qs[c + 0][r] = qv.x; Qs[c + 1][r] = qv.y; Qs[c + 2][r] = qv.z; Qs[c + 3][r] = qv.w;
        float4 kv = *(const float4*)(g_kvr + (size_t)(b * NT + t0 + r) * 768 + k0 + c);
        Ks[c + 0][r] = kv.x; Ks[c + 1][r] = kv.y; Ks[c + 2][r] = kv.z; Ks[c + 3][r] = kv.w;
        __syncthreads();
        #pragma unroll
        for (int kk = 0; kk < 16; kk++) {
            float4 a = *(const float4*)&Qs[kk][ty];
            float4 d = *(const float4*)&Ks[kk][tx];
            acc[0][0] += a.x * d.x; acc[0][1] += a.x * d.y; acc[0][2] += a.x * d.z; acc[0][3] += a.x * d.w;
            acc[1][0] += a.y * d.x; acc[1][1] += a.y * d.y; acc[1][2] += a.y * d.z; acc[1][3] += a.y * d.w;
            acc[2][0] += a.z * d.x; acc[2][1] += a.z * d.y; acc[2][2] += a.z * d.z; acc[2][3] += a.z * d.w;
            acc[3][0] += a.w * d.x; acc[3][1] += a.w * d.y; acc[3][2] += a.w * d.z; acc[3][3] += a.w * d.w;
        }
        __syncthreads();
    }
    #pragma unroll
    for (int i = 0; i < 4; i++)
        #pragma unroll
        for (int j = 0; j < 4; j++)
            g_s1[((size_t)b * NS + ty + i) * NT + t0 + tx + j] = acc[i][j] * ATT_SCALE;
}

// softmax over t for each (b,s) row of length 4096; normalizes in place
__global__ __launch_bounds__(256) void softmax1_kernel()
{
    __shared__ float red[256];
    int tid = threadIdx.x;
    float* row = g_s1 + (size_t)blockIdx.x * NT;

    float m = -1e30f;
    for (int t = tid; t < NT; t += 256) m = fmaxf(m, row[t]);
    red[tid] = m; __syncthreads();
    #pragma unroll
    for (int o = 128; o > 0; o >>= 1) { if (tid < o) red[tid] = fmaxf(red[tid], red[tid + o]); __syncthreads(); }
    m = red[0]; __syncthreads();

    float sum = 0.f;
    for (int t = tid; t < NT; t += 256) { float e = expf(row[t] - m); row[t] = e; sum += e; }
    float tot = block_reduce_sum256(sum, red);
    float inv = 1.0f / tot;
    for (int t = tid; t < NT; t += 256) row[t] *= inv;
}

// out_sd[b,s,d] += sum_t P1[b,s,t] v[b,t,d].  grid (ntiles=4, ksplit=8, b=4)
__global__ __launch_bounds__(256) void pv1_kernel()
{
    __shared__ float As[16][64];
    __shared__ float Bs[16][64];
    int tid = threadIdx.x;
    int n0 = blockIdx.x << 6;
    int kbase = blockIdx.y * KC;
    int b = blockIdx.z;
    int r = tid >> 2, c = (tid & 3) << 2;
    int br = tid >> 4, bc = (tid & 15) << 2;
    int tx = (tid & 15) << 2, ty = (tid >> 4) << 2;

    float acc[4][4] = {};
    for (int k0 = kbase; k0 < kbase + KC; k0 += 16) {
        float4 av = *(const float4*)(g_s1 + ((size_t)b * NS + r) * NT + k0 + c);
        As[c + 0][r] = av.x; As[c + 1][r] = av.y; As[c + 2][r] = av.z; As[c + 3][r] = av.w;
        *(float4*)&Bs[br][bc] = *(const float4*)(g_kvr + (size_t)(b * NT + k0 + br) * 768 + 256 + n0 + bc);
        __syncthreads();
        #pragma unroll
        for (int kk = 0; kk < 16; kk++) {
            float4 a = *(const float4*)&As[kk][ty];
            float4 d = *(const float4*)&Bs[kk][tx];
            acc[0][0] += a.x * d.x; acc[0][1] += a.x * d.y; acc[0][2] += a.x * d.z; acc[0][3] += a.x * d.w;
            acc[1][0] += a.y * d.x; acc[1][1] += a.y * d.y; acc[1][2] += a.y * d.z; acc[1][3] += a.y * d.w;
            acc[2][0] += a.z * d.x; acc[2][1] += a.z * d.y; acc[2][2] += a.z * d.z; acc[2][3] += a.z * d.w;
            acc[3][0] += a.w * d.x; acc[3][1] += a.w * d.y; acc[3][2] += a.w * d.z; acc[3][3] += a.w * d.w;
        }
        __syncthreads();
    }
    #pragma unroll
    for (int i = 0; i < 4; i++)
        #pragma unroll
        for (int j = 0; j < 4; j++)
            atomicAdd(g_out_sd + ((size_t)b * NS + ty + i) * SD + n0 + tx + j, acc[i][j]);
}

// g_spre[r][n] = slot_emb[r&63][n] + sum_k out_sd[r][k] * Wo[k][n].  grid (4, 64)
__global__ __launch_bounds__(256) void wo_gemm(
    const float* __restrict__ Wo, const float* __restrict__ slot_emb)
{
    __shared__ float As[16][64];
    __shared__ float Bs[16][64];
    int tid = threadIdx.x;
    int m0 = blockIdx.x << 6;
    int n0 = blockIdx.y << 6;
    int r = tid >> 2, c = (tid & 3) << 2;
    int br = tid >> 4, bc = (tid & 15) << 2;
    int tx = (tid & 15) << 2, ty = (tid >> 4) << 2;

    float acc[4][4] = {};
    for (int k0 = 0; k0 < SD; k0 += 16) {
        float4 av = *(const float4*)(g_out_sd + (size_t)(m0 + r) * SD + k0 + c);
        As[c + 0][r] = av.x; As[c + 1][r] = av.y; As[c + 2][r] = av.z; As[c + 3][r] = av.w;
        *(float4*)&Bs[br][bc] = *(const float4*)(Wo + (size_t)(k0 + br) * HID + n0 + bc);
        __syncthreads();
        #pragma unroll
        for (int kk = 0; kk < 16; kk++) {
            float4 a = *(const float4*)&As[kk][ty];
            float4 d = *(const float4*)&Bs[kk][tx];
            acc[0][0] += a.x * d.x; acc[0][1] += a.x * d.y; acc[0][2] += a.x * d.z; acc[0][3] += a.x * d.w;
            acc[1][0] += a.y * d.x; acc[1][1] += a.y * d.y; acc[1][2] += a.y * d.z; acc[1][3] += a.y * d.w;
            acc[2][0] += a.z * d.x; acc[2][1] += a.z * d.y; acc[2][2] += a.z * d.z; acc[2][3] += a.z * d.w;
            acc[3][0] += a.w * d.x; acc[3][1] += a.w * d.y; acc[3][2] += a.w * d.z; acc[3][3] += a.w * d.w;
        }
        __syncthreads();
    }
    #pragma unroll
    for (int i = 0; i < 4; i++) {
        int row = m0 + ty + i;
        int s = row & 63;
        #pragma unroll
        for (int j = 0; j < 4; j++) {
            int col = n0 + tx + j;
            g_spre[(size_t)row * HID + col] = acc[i][j] + slot_emb[(size_t)s * HID + col];
        }
    }
}

// generic row-LN over HID=4096: dst[row] = LN(src[row]) * w + b
__global__ __launch_bounds__(256) void ln_rows_kernel(
    const float* __restrict__ src, const float* __restrict__ w,
    const float* __restrict__ bb, float* __restrict__ dst)
{
    __shared__ float red[256];
    int tid = threadIdx.x, rrow = blockIdx.x;
    const float* row = src + (size_t)rrow * HID;

    float v[16];
    #pragma unroll
    for (int i = 0; i < 16; i++) v[i] = row[tid + (i << 8)];
    float sum = 0.f, sq = 0.f;
    #pragma unroll
    for (int i = 0; i < 16; i++) { sum += v[i]; sq += v[i] * v[i]; }
    float tsum = block_reduce_sum256(sum, red);
    float tsq  = block_reduce_sum256(sq, red);
    float mu = tsum * (1.0f / HID);
    float var = tsq * (1.0f / HID) - mu * mu;
    float invs = rsqrtf(var + LN_EPS);
    #pragma unroll
    for (int i = 0; i < 16; i++) {
        int col = tid + (i << 8);
        dst[(size_t)rrow * HID + col] = (v[i] - mu) * invs * w[col] + bb[col];
    }
}

// ===================================================================================
// attn2 scores: S2[b][t][s] = scale * rq[b,t]·rk[b,s].  grid (t_tiles=64, b)
// ===================================================================================
__global__ __launch_bounds__(256) void scores2_kernel()
{
    __shared__ float As[16][64];
    __shared__ float Bs[16][64];
    int tid = threadIdx.x;
    int t0 = blockIdx.x << 6;
    int b = blockIdx.y;
    int r = tid >> 2, c = (tid & 3) << 2;
    int tx = (tid & 15) << 2, ty = (tid >> 4) << 2;

    float acc[4][4] = {};
    for (int k0 = 0; k0 < SD; k0 += 16) {
        float4 av = *(const float4*)(g_kvr + (size_t)(b * NT + t0 + r) * 768 + 512 + k0 + c);
        As[c + 0][r] = av.x; As[c + 1][r] = av.y; As[c + 2][r] = av.z; As[c + 3][r] = av.w;
        float4 kv = *(const float4*)(g_rkv + (size_t)(b * NS + r) * 512 + k0 + c);
        Bs[c + 0][r] = kv.x; Bs[c + 1][r] = kv.y; Bs[c + 2][r] = kv.z; Bs[c + 3][r] = kv.w;
        __syncthreads();
        #pragma unroll
        for (int kk = 0; kk < 16; kk++) {
            float4 a = *(const float4*)&As[kk][ty];
            float4 d = *(const float4*)&Bs[kk][tx];
            acc[0][0] += a.x * d.x; acc[0][1] += a.x * d.y; acc[0][2] += a.x * d.z; acc[0][3] += a.x * d.w;
            acc[1][0] += a.y * d.x; acc[1][1] += a.y * d.y; acc[1][2] += a.y * d.z; acc[1][3] += a.y * d.w;
            acc[2][0] += a.z * d.x; acc[2][1] += a.z * d.y; acc[2][2] += a.z * d.z; acc[2][3] += a.z * d.w;
            acc[3][0] += a.w * d.x; acc[3][1] += a.w * d.y; acc[3][2] += a.w * d.z; acc[3][3] += a.w * d.w;
        }
        __syncthreads();
    }
    #pragma unroll
    for (int i = 0; i < 4; i++)
        #pragma unroll
        for (int j = 0; j < 4; j++)
            g_s2[((size_t)b * NT + t0 + ty + i) * NS + tx + j] = acc[i][j] * ATT_SCALE;
}

// softmax over s (64) per (b,t) row; one warp per row, 2 values/lane; normalize in place
__global__ __launch_bounds__(256) void softmax2_kernel()
{
    int tid = threadIdx.x;
    int row = (blockIdx.x << 3) + (tid >> 5);
    int lane = tid & 31;
    float* p = g_s2 + (size_t)row * NS;
    float v0 = p[lane], v1 = p[lane + 32];
    float m = fmaxf(v0, v1);
    #pragma unroll
    for (int o = 16; o > 0; o >>= 1) m = fmaxf(m, __shfl_xor_sync(0xffffffffu, m, o));
    float e0 = expf(v0 - m), e1 = expf(v1 - m);
    float s = e0 + e1;
    #pragma unroll
    for (int o = 16; o > 0; o >>= 1) s += __shfl_xor_sync(0xffffffffu, s, o);
    float inv = 1.0f / s;
    p[lane] = e0 * inv;
    p[lane + 32] = e1 * inv;
}

// rout_sd[b,t,d] = sum_s P2[b,t,s] rv[b,s,d].  grid (t_tiles=64, ntiles=4, b)
__global__ __launch_bounds__(256) void pv2_kernel()
{
    __shared__ float As[16][64];
    __shared__ float Bs[16][64];
    int tid = threadIdx.x;
    int t0 = blockIdx.x << 6;
    int n0 = blockIdx.y << 6;
    int b = blockIdx.z;
    int r = tid >> 2, c = (tid & 3) << 2;
    int br = tid >> 4, bc = (tid & 15) << 2;
    int tx = (tid & 15) << 2, ty = (tid >> 4) << 2;

    float acc[4][4] = {};
    for (int k0 = 0; k0 < NS; k0 += 16) {
        float4 av = *(const float4*)(g_s2 + ((size_t)b * NT + t0 + r) * NS + k0 + c);
        As[c + 0][r] = av.x; As[c + 1][r] = av.y; As[c + 2][r] = av.z; As[c + 3][r] = av.w;
        *(float4*)&Bs[br][bc] = *(const float4*)(g_rkv + (size_t)(b * NS + k0 + br) * 512 + 256 + n0 + bc);
        __syncthreads();
        #pragma unroll
        for (int kk = 0; kk < 16; kk++) {
            float4 a = *(const float4*)&As[kk][ty];
            float4 d = *(const float4*)&Bs[kk][tx];
            acc[0][0] += a.x * d.x; acc[0][1] += a.x * d.y; acc[0][2] += a.x * d.z; acc[0][3] += a.x * d.w;
            acc[1][0] += a.y * d.x; acc[1][1] += a.y * d.y; acc[1][2] += a.y * d.z; acc[1][3] += a.y * d.w;
            acc[2][0] += a.z * d.x; acc[2][1] += a.z * d.y; acc[2][2] += a.z * d.z; acc[2][3] += a.z * d.w;
            acc[3][0] += a.w * d.x; acc[3][1] += a.w * d.y; acc[3][2] += a.w * d.z; acc[3][3] += a.w * d.w;
        }
        __syncthreads();
    }
    #pragma unroll
    for (int i = 0; i < 4; i++)
        #pragma unroll
        for (int j = 0; j < 4; j++)
            g_rout_sd[((size_t)b * NT + t0 + ty + i) * SD + n0 + tx + j] = acc[i][j];
}

// ---------------- per-row LN + gate + squared-error accumulation --------------------
__global__ __launch_bounds__(256) void loss_ln_kernel(
    const float* __restrict__ seg, const float* __restrict__ lnw,
    const float* __restrict__ lnb, const float* __restrict__ gate_bias)
{
    __shared__ float red[256];
    __shared__ float gsh;
    int tid = threadIdx.x, rrow = blockIdx.x;
    const float* row = g_rout_full + (size_t)rrow * HID;

    float v[16];
    #pragma unroll
    for (int i = 0; i < 16; i++) v[i] = row[tid + (i << 8)];

    if (tid == 0) {
        float sg = 0.f;
        for (int i = 0; i < 64; i++) sg += gate_bias[i];
        sg *= (1.0f / 64.0f);
        gsh = 1.0f / (1.0f + expf(-sg));
    }

    float sum = 0.f, sq = 0.f;
    #pragma unroll
    for (int i = 0; i < 16; i++) { sum += v[i]; sq += v[i] * v[i]; }
    float tsum = block_reduce_sum256(sum, red);
    float tsq  = block_reduce_sum256(sq, red);
    float mu = tsum * (1.0f / HID);
    float var = tsq * (1.0f / HID) - mu * mu;
    float invs = rsqrtf(var + LN_EPS);
    float g = gsh;

    const float* segrow = seg + (size_t)rrow * HID;
    float acc = 0.f;
    #pragma unroll
    for (int i = 0; i < 16; i++) {
        int col = tid + (i << 8);
        float rec = g * ((v[i] - mu) * invs * lnw[col] + lnb[col]);
        float d = rec - segrow[col];
        acc += d * d;
    }
    float bsum = block_reduce_sum256(acc, red);
    if (tid == 0) atomicAdd(&g_loss, (double)bsum);
}

__global__ void finalize_kernel(const float* __restrict__ gate_bias, float* __restrict__ outp)
{
    float sg = 0.f;
    for (int i = 0; i < 64; i++) sg += gate_bias[i];
    sg *= (1.0f / 64.0f);
    float g = 1.0f / (1.0f + expf(-sg));
    outp[NB * NS * HID]     = (float)(g_loss / (double)((size_t)NB * NT * HID));
    outp[NB * NS * HID + 1] = g;
}

// ---------------- launch ------------------------------------------------------------
extern "C" void kernel_launch(void* const* d_in, const int* in_sizes, int n_in,
                              void* d_out, int out_size)
{
    const float* seg      = (const float*)d_in[0];   // [B,T,HID]
    const float* slot_emb = (const float*)d_in[1];   // [S,HID]
    const float* Wq       = (const float*)d_in[2];
    const float* Wk       = (const float*)d_in[3];
    const float* Wv       = (const float*)d_in[4];
    const float* Wo       = (const float*)d_in[5];
    const float* Wrq      = (const float*)d_in[6];
    const float* Wro      = (const float*)d_in[7];
    const float* gateb    = (const float*)d_in[8];
    const float* snw      = (const float*)d_in[9];
    const float* snb      = (const float*)d_in[10];
    const float* rnw      = (const float*)d_in[11];
    const float* rnb      = (const float*)d_in[12];
    float* outp = (float*)d_out;

    float* kvr;      cudaGetSymbolAddress((void**)&kvr, g_kvr);
    float* qbuf;     cudaGetSymbolAddress((void**)&qbuf, g_q);
    float* out_sd;   cudaGetSymbolAddress((void**)&out_sd, g_out_sd);
    float* spre;     cudaGetSymbolAddress((void**)&spre, g_spre);
    float* rkv;      cudaGetSymbolAddress((void**)&rkv, g_rkv);
    float* rout_sd;  cudaGetSymbolAddress((void**)&rout_sd, g_rout_sd);
    float* rout_full;cudaGetSymbolAddress((void**)&rout_full, g_rout_full);

    init_loss_kernel<<<1, 1>>>();
    cudaMemsetAsync(qbuf, 0, (size_t)NS * SD * sizeof(float));
    cudaMemsetAsync(out_sd, 0, (size_t)NB * NS * SD * sizeof(float));
    cudaMemsetAsync(rkv, 0, (size_t)NB * NS * 512 * sizeof(float));

    // k | v | rq = segment_hidden @ {Wk, Wv, Wrq}
    sgemm128<<<dim3(BT / 128, 6), 256>>>(seg, Wk, Wv, Wrq, kvr, HID, 256, 768);

    // q = slot_embeddings @ Wq  (split-K 8-way)
    gemm_small<<<dim3(1, 4, 8), 256>>>(slot_emb, HID, Wq, nullptr, qbuf, SD);

    // attn1: scores, softmax, P@V
    scores1_kernel<<<dim3(64, NB), 256>>>();
    softmax1_kernel<<<NB * NS, 256>>>();
    pv1_kernel<<<dim3(4, 8, NB), 256>>>();

    // slots + out@Wo, then LN -> updated_slots in d_out
    wo_gemm<<<dim3(4, 64), 256>>>(Wo, slot_emb);
    ln_rows_kernel<<<NB * NS, 256>>>(spre, snw, snb, outp);

    // rk | rv = updated_slots @ {Wk, Wv}  (split-K 8-way)
    gemm_small<<<dim3(4, 8, 8), 256>>>(outp, HID, Wk, Wv, rkv, 512);

    // attn2: scores, softmax, P@V
    scores2_kernel<<<dim3(64, NB), 256>>>();
    softmax2_kernel<<<BT / 8, 256>>>();
    pv2_kernel<<<dim3(64, 4, NB), 256>>>();

    // rout = rout_sd @ Wro
    sgemm128<<<dim3(BT / 128, HID / 128), 256>>>(rout_sd, Wro, nullptr, nullptr, rout_full, SD, HID, HID);

    // layernorm + gate + MSE accumulation
    loss_ln_kernel<<<BT, 256>>>(seg, rnw, rnb, gateb);

    finalize_kernel<<<1, 1>>>(gateb, outp);
}

// round 4
// speedup vs baseline: 3.7051x; 2.4047x over previous
#include <cuda_runtime.h>
#include <cuda_bf16.h>
#include <math.h>
#include <stdint.h>

#define HID 4096
#define SD 256
#define NS 64           // slots
#define NB 4            // batch
#define NT 4096         // tokens
#define BT (NB*NT)      // 16384
#define LN_EPS 1e-5f
#define ATT_SCALE 0.0625f  // 256^-0.5
#define KC 512          // split-K chunk for skinny GEMMs

// ---------------- scratch (static device globals; no runtime alloc) ----------------
__device__ float g_kvr[BT * 768];          // [b*T+t][ k(0:256) | v(256:512) | rq(512:768) ]
__device__ float g_q[NS * SD];             // slot queries (batch-independent)
__device__ float g_s1[NB * NS * NT];       // attn1 scores/probs [b][s][t]
__device__ float g_out_sd[NB * NS * SD];   // attn1 output before Wo
__device__ float g_spre[NB * NS * HID];    // slots + out@Wo, before LN
__device__ float g_rkv[NB * NS * 512];     // [b*S+s][ rk(0:256) | rv(256:512) ]
__device__ float g_s2[NB * NT * NS];       // attn2 scores/probs [b][t][s]
__device__ float g_rout_sd[BT * SD];       // attn2 output before Wro
__device__ float g_rout_full[67108864];    // [BT][HID] rout before LN (256 MB)
__device__ double g_loss;

// bf16 split operands for tensor-core GEMMs
__device__ __nv_bfloat16 g_segh[(size_t)BT * HID];   // seg hi
__device__ __nv_bfloat16 g_segl[(size_t)BT * HID];   // seg lo
__device__ __nv_bfloat16 g_WTh[768 * HID];           // [Wk|Wv|Wrq]^T  [768][4096]
__device__ __nv_bfloat16 g_WTl[768 * HID];
__device__ __nv_bfloat16 g_WroTh[HID * SD];          // Wro^T [4096][256]
__device__ __nv_bfloat16 g_WroTl[HID * SD];
__device__ __nv_bfloat16 g_Rh[BT * SD];              // rout_sd hi
__device__ __nv_bfloat16 g_Rl[BT * SD];              // rout_sd lo

// ================= ptx helpers (sm_80-era: valid on base sm_103 target) =================
__device__ __forceinline__ uint32_t s2u(const void* p) {
    uint32_t a;
    asm("{ .reg .u64 t; cvta.to.shared.u64 t, %1; cvt.u32.u64 %0, t; }" : "=r"(a) : "l"(p));
    return a;
}
__device__ __forceinline__ void cpa16(uint32_t dst, const void* src) {
    asm volatile("cp.async.cg.shared.global [%0], [%1], 16;" :: "r"(dst), "l"(src) : "memory");
}
__device__ __forceinline__ void ldsm_x4(uint32_t* r, uint32_t addr) {
    asm volatile("ldmatrix.sync.aligned.m8n8.x4.shared.b16 {%0,%1,%2,%3}, [%4];"
        : "=r"(r[0]), "=r"(r[1]), "=r"(r[2]), "=r"(r[3]) : "r"(addr));
}
__device__ __forceinline__ void ldsm_x2(uint32_t* r, uint32_t addr) {
    asm volatile("ldmatrix.sync.aligned.m8n8.x2.shared.b16 {%0,%1}, [%2];"
        : "=r"(r[0]), "=r"(r[1]) : "r"(addr));
}
__device__ __forceinline__ void mma16816(float* d, const uint32_t* a, const uint32_t* b) {
    asm volatile("mma.sync.aligned.m16n8k16.row.col.f32.bf16.bf16.f32 "
        "{%0,%1,%2,%3}, {%4,%5,%6,%7}, {%8,%9}, {%0,%1,%2,%3};"
        : "+f"(d[0]), "+f"(d[1]), "+f"(d[2]), "+f"(d[3])
        : "r"(a[0]), "r"(a[1]), "r"(a[2]), "r"(a[3]), "r"(b[0]), "r"(b[1]));
}
__device__ __forceinline__ uint32_t sw128(uint32_t off) { return off ^ ((off >> 3) & 0x70); }

#define STAGE_BYTES 65536
#define TC_SMEM_BYTES (2 * STAGE_BYTES)

// ===================================================================================
// HMMA split-bf16 GEMM: C[M,N] = Ah@Bh^T + Ah@Bl^T + Al@Bh^T  (fp32 accum)
// A*: [Mtot][K] K-major bf16.  B*: [Ntot][K] K-major bf16 (pre-transposed weights).
// Block tile 128x128, K-chunk 64, 8 warps (each 64x32), 2-stage cp.async pipeline.
// grid (Ntot/128, Mtot/128). K multiple of 64.
// ===================================================================================
__global__ void __launch_bounds__(256, 1) hmma_gemm(
    const __nv_bfloat16* __restrict__ Ah, const __nv_bfloat16* __restrict__ Al,
    const __nv_bfloat16* __restrict__ Bh, const __nv_bfloat16* __restrict__ Bl,
    float* __restrict__ C, int ldc, int K)
{
    extern __shared__ char smem[];
    uint32_t sb = s2u(smem);
    int tid = threadIdx.x, wid = tid >> 5, lane = tid & 31;
    int n0 = blockIdx.x << 7, m0 = blockIdx.y << 7;
    const int nch = K >> 6;
    int wm = (wid & 1) << 6;        // warp m offset within tile (0 or 64)
    int wn = (wid >> 1) << 5;       // warp n offset within tile (0..96)

    // stage layout: [Ah 16K][Al 16K][Bh 16K][Bl 16K], each 128 rows x 128 bytes, sw128
    #define LOAD_CHUNK(s, c) do { \
        uint32_t base = sb + (uint32_t)(s) * STAGE_BYTES; \
        int k0 = (c) << 6; \
        _Pragma("unroll") \
        for (int i = 0; i < 4; i++) { \
            int u = tid + (i << 8); \
            int row = u >> 3, cu = u & 7; \
            uint32_t sw = sw128((uint32_t)u << 4); \
            size_t ao = (size_t)(m0 + row) * K + k0 + (cu << 3); \
            size_t bo = (size_t)(n0 + row) * K + k0 + (cu << 3); \
            cpa16(base + sw,         Ah + ao); \
            cpa16(base + 16384 + sw, Al + ao); \
            cpa16(base + 32768 + sw, Bh + bo); \
            cpa16(base + 49152 + sw, Bl + bo); \
        } \
        asm volatile("cp.async.commit_group;" ::: "memory"); \
    } while (0)

    float acc[4][4][4] = {};   // [mi][ni][reg]

    LOAD_CHUNK(0, 0);

    for (int c = 0; c < nch; c++) {
        if (c + 1 < nch) {
            LOAD_CHUNK((c + 1) & 1, c + 1);
            asm volatile("cp.async.wait_group 1;" ::: "memory");
        } else {
            asm volatile("cp.async.wait_group 0;" ::: "memory");
        }
        __syncthreads();

        uint32_t base = sb + (uint32_t)(c & 1) * STAGE_BYTES;
        #pragma unroll
        for (int ks = 0; ks < 4; ks++) {
            uint32_t ah[4][4], al[4][4], bh[4][2], bl[4][2];
            // A fragments: 16x16 tiles at rows wm+mi*16, cols ks*16
            uint32_t acb = (uint32_t)((ks << 4) + ((lane >> 4) << 3)) << 1;  // byte col
            #pragma unroll
            for (int mi = 0; mi < 4; mi++) {
                uint32_t r = (uint32_t)(wm + (mi << 4) + (lane & 15));
                uint32_t sw = sw128((r << 7) + acb);
                ldsm_x4(ah[mi], base + sw);
                ldsm_x4(al[mi], base + 16384 + sw);
            }
            // B fragments: n8 k16 tiles at rows wn+ni*8, cols ks*16
            uint32_t bcb = (uint32_t)((ks << 4) + (((lane >> 3) & 1) << 3)) << 1;
            #pragma unroll
            for (int ni = 0; ni < 4; ni++) {
                uint32_t r = (uint32_t)(wn + (ni << 3) + (lane & 7));
                uint32_t sw = sw128((r << 7) + bcb);
                ldsm_x2(bh[ni], base + 32768 + sw);
                ldsm_x2(bl[ni], base + 49152 + sw);
            }
            #pragma unroll
            for (int mi = 0; mi < 4; mi++)
                #pragma unroll
                for (int ni = 0; ni < 4; ni++) {
                    mma16816(acc[mi][ni], ah[mi], bh[ni]);
                    mma16816(acc[mi][ni], ah[mi], bl[ni]);
                    mma16816(acc[mi][ni], al[mi], bh[ni]);
                }
        }
        __syncthreads();
    }

    // epilogue: fragment d: rows lane>>2 and +8, cols (lane&3)*2, +1
    int rbase = m0 + wm + (lane >> 2);
    int cbase = n0 + wn + ((lane & 3) << 1);
    #pragma unroll
    for (int mi = 0; mi < 4; mi++)
        #pragma unroll
        for (int ni = 0; ni < 4; ni++) {
            int row = rbase + (mi << 4);
            int col = cbase + (ni << 3);
            *(float2*)(C + (size_t)row * ldc + col)       = make_float2(acc[mi][ni][0], acc[mi][ni][1]);
            *(float2*)(C + (size_t)(row + 8) * ldc + col) = make_float2(acc[mi][ni][2], acc[mi][ni][3]);
        }
    #undef LOAD_CHUNK
}

// ---------------- fp32 -> (hi, lo) bf16 split, elementwise ----------------
__global__ void __launch_bounds__(256) conv_hilo(
    const float* __restrict__ src, __nv_bfloat16* __restrict__ h, __nv_bfloat16* __restrict__ l)
{
    size_t i = ((size_t)blockIdx.x * 256 + threadIdx.x) * 4;
    float4 v = *(const float4*)(src + i);
    __nv_bfloat16 h0 = __float2bfloat16(v.x), h1 = __float2bfloat16(v.y);
    __nv_bfloat16 h2 = __float2bfloat16(v.z), h3 = __float2bfloat16(v.w);
    __nv_bfloat16 l0 = __float2bfloat16(v.x - __bfloat162float(h0));
    __nv_bfloat16 l1 = __float2bfloat16(v.y - __bfloat162float(h1));
    __nv_bfloat16 l2 = __float2bfloat16(v.z - __bfloat162float(h2));
    __nv_bfloat16 l3 = __float2bfloat16(v.w - __bfloat162float(h3));
    *(__nv_bfloat162*)(h + i)     = __nv_bfloat162(h0, h1);
    *(__nv_bfloat162*)(h + i + 2) = __nv_bfloat162(h2, h3);
    *(__nv_bfloat162*)(l + i)     = __nv_bfloat162(l0, l1);
    *(__nv_bfloat162*)(l + i + 2) = __nv_bfloat162(l2, l3);
}

// ---------------- transpose + split: W[K][N] fp32 -> dst[N][K] bf16 hi/lo ----------
__global__ void __launch_bounds__(256) transpose_conv(
    const float* __restrict__ W, __nv_bfloat16* __restrict__ dh,
    __nv_bfloat16* __restrict__ dl, int K, int N)
{
    __shared__ float t[32][33];
    int n0 = blockIdx.x << 5, k0 = blockIdx.y << 5;
    int tx = threadIdx.x & 31, ty = threadIdx.x >> 5;  // 32 x 8
    #pragma unroll
    for (int i = 0; i < 32; i += 8)
        t[ty + i][tx] = W[(size_t)(k0 + ty + i) * N + n0 + tx];
    __syncthreads();
    #pragma unroll
    for (int i = 0; i < 32; i += 8) {
        float x = t[tx][ty + i];           // = W[k0+tx][n0+ty+i]
        int n = n0 + ty + i, k = k0 + tx;
        __nv_bfloat16 hh = __float2bfloat16(x);
        dh[(size_t)n * K + k] = hh;
        dl[(size_t)n * K + k] = __float2bfloat16(x - __bfloat162float(hh));
    }
}

// ---------------- helpers ----------------
__device__ __forceinline__ float block_reduce_sum256(float v, float* red) {
    int tid = threadIdx.x;
    red[tid] = v; __syncthreads();
    #pragma unroll
    for (int o = 128; o > 0; o >>= 1) {
        if (tid < o) red[tid] += red[tid + o];
        __syncthreads();
    }
    float r = red[0];
    __syncthreads();
    return r;
}

__global__ void init_loss_kernel() { g_loss = 0.0; }

// ===================================================================================
// Skinny split-K GEMM: 64x64 tile over a K-chunk of KC, atomicAdd into pre-zeroed C.
// ===================================================================================
__global__ __launch_bounds__(256) void gemm_small(
    const float* __restrict__ A, int lda,
    const float* __restrict__ W0, const float* __restrict__ W1,
    float* __restrict__ C, int ldc)
{
    __shared__ float As[16][64];
    __shared__ float Bs[16][64];
    int tid = threadIdx.x;
    int m0 = blockIdx.x << 6;
    int n0 = blockIdx.y << 6;
    int kbase = blockIdx.z * KC;
    const float* W = (n0 >> 8) ? W1 : W0;
    int col0 = n0 & 255;

    int r = tid >> 2, c = (tid & 3) << 2;
    int br = tid >> 4, bc = (tid & 15) << 2;
    int tx = (tid & 15) << 2, ty = (tid >> 4) << 2;

    float acc[4][4] = {};
    for (int k0 = kbase; k0 < kbase + KC; k0 += 16) {
        float4 av = *(const float4*)(A + (size_t)(m0 + r) * lda + k0 + c);
        As[c + 0][r] = av.x; As[c + 1][r] = av.y; As[c + 2][r] = av.z; As[c + 3][r] = av.w;
        *(float4*)&Bs[br][bc] = *(const float4*)(W + (size_t)(k0 + br) * 256 + col0 + bc);
        __syncthreads();
        #pragma unroll
        for (int kk = 0; kk < 16; kk++) {
            float4 a = *(const float4*)&As[kk][ty];
            float4 b = *(const float4*)&Bs[kk][tx];
            acc[0][0] += a.x * b.x; acc[0][1] += a.x * b.y; acc[0][2] += a.x * b.z; acc[0][3] += a.x * b.w;
            acc[1][0] += a.y * b.x; acc[1][1] += a.y * b.y; acc[1][2] += a.y * b.z; acc[1][3] += a.y * b.w;
            acc[2][0] += a.z * b.x; acc[2][1] += a.z * b.y; acc[2][2] += a.z * b.z; acc[2][3] += a.z * b.w;
            acc[3][0] += a.w * b.x; acc[3][1] += a.w * b.y; acc[3][2] += a.w * b.z; acc[3][3] += a.w * b.w;
        }
        __syncthreads();
    }
    #pragma unroll
    for (int i = 0; i < 4; i++)
        #pragma unroll
        for (int j = 0; j < 4; j++)
            atomicAdd(C + (size_t)(m0 + ty + i) * ldc + n0 + tx + j, acc[i][j]);
}

// ---------------- attn1 scores ----------------
__global__ __launch_bounds__(256) void scores1_kernel()
{
    __shared__ float Qs[16][64];
    __shared__ float Ks[16][64];
    int tid = threadIdx.x;
    int t0 = blockIdx.x << 6;
    int b = blockIdx.y;
    int r = tid >> 2, c = (tid & 3) << 2;
    int tx = (tid & 15) << 2, ty = (tid >> 4) << 2;

    float acc[4][4] = {};
    for (int k0 = 0; k0 < SD; k0 += 16) {
        float4 qv = *(const float4*)(g_q + (size_t)r * SD + k0 + c);
        Qs[c + 0][r] = qv.x; Qs[c + 1][r] = qv.y; Qs[c + 2][r] = qv.z; Qs[c + 3][r] = qv.w;
        float4 kv = *(const float4*)(g_kvr + (size_t)(b * NT + t0 + r) * 768 + k0 + c);
        Ks[c + 0][r] = kv.x; Ks[c + 1][r] = kv.y; Ks[c + 2][r] = kv.z; Ks[c + 3][r] = kv.w;
        __syncthreads();
        #pragma unroll
        for (int kk = 0; kk < 16; kk++) {
            float4 a = *(const float4*)&Qs[kk][ty];
            float4 d = *(const float4*)&Ks[kk][tx];
            acc[0][0] += a.x * d.x; acc[0][1] += a.x * d.y; acc[0][2] += a.x * d.z; acc[0][3] += a.x * d.w;
            acc[1][0] += a.y * d.x; acc[1][1] += a.y * d.y; acc[1][2] += a.y * d.z; acc[1][3] += a.y * d.w;
            acc[2][0] += a.z * d.x; acc[2][1] += a.z * d.y; acc[2][2] += a.z * d.z; acc[2][3] += a.z * d.w;
            acc[3][0] += a.w * d.x; acc[3][1] += a.w * d.y; acc[3][2] += a.w * d.z; acc[3][3] += a.w * d.w;
        }
        __syncthreads();
    }
    #pragma unroll
    for (int i = 0; i < 4; i++)
        #pragma unroll
        for (int j = 0; j < 4; j++)
            g_s1[((size_t)b * NS + ty + i) * NT + t0 + tx + j] = acc[i][j] * ATT_SCALE;
}

__global__ __launch_bounds__(256) void softmax1_kernel()
{
    __shared__ float red[256];
    int tid = threadIdx.x;
    float* row = g_s1 + (size_t)blockIdx.x * NT;

    float m = -1e30f;
    for (int t = tid; t < NT; t += 256) m = fmaxf(m, row[t]);
    red[tid] = m; __syncthreads();
    #pragma unroll
    for (int o = 128; o > 0; o >>= 1) { if (tid < o) red[tid] = fmaxf(red[tid], red[tid + o]); __syncthreads(); }
    m = red[0]; __syncthreads();

    float sum = 0.f;
    for (int t = tid; t < NT; t += 256) { float e = expf(row[t] - m); row[t] = e; sum += e; }
    float tot = block_reduce_sum256(sum, red);
    float inv = 1.0f / tot;
    for (int t = tid; t < NT; t += 256) row[t] *= inv;
}

__global__ __launch_bounds__(256) void pv1_kernel()
{
    __shared__ float As[16][64];
    __shared__ float Bs[16][64];
    int tid = threadIdx.x;
    int n0 = blockIdx.x << 6;
    int kbase = blockIdx.y * KC;
    int b = blockIdx.z;
    int r = tid >> 2, c = (tid & 3) << 2;
    int br = tid >> 4, bc = (tid & 15) << 2;
    int tx = (tid & 15) << 2, ty = (tid >> 4) << 2;

    float acc[4][4] = {};
    for (int k0 = kbase; k0 < kbase + KC; k0 += 16) {
        float4 av = *(const float4*)(g_s1 + ((size_t)b * NS + r) * NT + k0 + c);
        As[c + 0][r] = av.x; As[c + 1][r] = av.y; As[c + 2][r] = av.z; As[c + 3][r] = av.w;
        *(float4*)&Bs[br][bc] = *(const float4*)(g_kvr + (size_t)(b * NT + k0 + br) * 768 + 256 + n0 + bc);
        __syncthreads();
        #pragma unroll
        for (int kk = 0; kk < 16; kk++) {
            float4 a = *(const float4*)&As[kk][ty];
            float4 d = *(const float4*)&Bs[kk][tx];
            acc[0][0] += a.x * d.x; acc[0][1] += a.x * d.y; acc[0][2] += a.x * d.z; acc[0][3] += a.x * d.w;
            acc[1][0] += a.y * d.x; acc[1][1] += a.y * d.y; acc[1][2] += a.y * d.z; acc[1][3] += a.y * d.w;
            acc[2][0] += a.z * d.x; acc[2][1] += a.z * d.y; acc[2][2] += a.z * d.z; acc[2][3] += a.z * d.w;
            acc[3][0] += a.w * d.x; acc[3][1] += a.w * d.y; acc[3][2] += a.w * d.z; acc[3][3] += a.w * d.w;
        }
        __syncthreads();
    }
    #pragma unroll
    for (int i = 0; i < 4; i++)
        #pragma unroll
        for (int j = 0; j < 4; j++)
            atomicAdd(g_out_sd + ((size_t)b * NS + ty + i) * SD + n0 + tx + j, acc[i][j]);
}

__global__ __launch_bounds__(256) void wo_gemm(
    const float* __restrict__ Wo, const float* __restrict__ slot_emb)
{
    __shared__ float As[16][64];
    __shared__ float Bs[16][64];
    int tid = threadIdx.x;
    int m0 = blockIdx.x << 6;
    int n0 = blockIdx.y << 6;
    int r = tid >> 2, c = (tid & 3) << 2;
    int br = tid >> 4, bc = (tid & 15) << 2;
    int tx = (tid & 15) << 2, ty = (tid >> 4) << 2;

    float acc[4][4] = {};
    for (int k0 = 0; k0 < SD; k0 += 16) {
        float4 av = *(const float4*)(g_out_sd + (size_t)(m0 + r) * SD + k0 + c);
        As[c + 0][r] = av.x; As[c + 1][r] = av.y; As[c + 2][r] = av.z; As[c + 3][r] = av.w;
        *(float4*)&Bs[br][bc] = *(const float4*)(Wo + (size_t)(k0 + br) * HID + n0 + bc);
        __syncthreads();
        #pragma unroll
        for (int kk = 0; kk < 16; kk++) {
            float4 a = *(const float4*)&As[kk][ty];
            float4 d = *(const float4*)&Bs[kk][tx];
            acc[0][0] += a.x * d.x; acc[0][1] += a.x * d.y; acc[0][2] += a.x * d.z; acc[0][3] += a.x * d.w;
            acc[1][0] += a.y * d.x; acc[1][1] += a.y * d.y; acc[1][2] += a.y * d.z; acc[1][3] += a.y * d.w;
            acc[2][0] += a.z * d.x; acc[2][1] += a.z * d.y; acc[2][2] += a.z * d.z; acc[2][3] += a.z * d.w;
            acc[3][0] += a.w * d.x; acc[3][1] += a.w * d.y; acc[3][2] += a.w * d.z; acc[3][3] += a.w * d.w;
        }
        __syncthreads();
    }
    #pragma unroll
    for (int i = 0; i < 4; i++) {
        int row = m0 + ty + i;
        int s = row & 63;
        #pragma unroll
        for (int j = 0; j < 4; j++) {
            int col = n0 + tx + j;
            g_spre[(size_t)row * HID + col] = acc[i][j] + slot_emb[(size_t)s * HID + col];
        }
    }
}

__global__ __launch_bounds__(256) void ln_rows_kernel(
    const float* __restrict__ src, const float* __restrict__ w,
    const float* __restrict__ bb, float* __restrict__ dst)
{
    __shared__ float red[256];
    int tid = threadIdx.x, rrow = blockIdx.x;
    const float* row = src + (size_t)rrow * HID;

    float v[16];
    #pragma unroll
    for (int i = 0; i < 16; i++) v[i] = row[tid + (i << 8)];
    float sum = 0.f, sq = 0.f;
    #pragma unroll
    for (int i = 0; i < 16; i++) { sum += v[i]; sq += v[i] * v[i]; }
    float tsum = block_reduce_sum256(sum, red);
    float tsq  = block_reduce_sum256(sq, red);
    float mu = tsum * (1.0f / HID);
    float var = tsq * (1.0f / HID) - mu * mu;
    float invs = rsqrtf(var + LN_EPS);
    #pragma unroll
    for (int i = 0; i < 16; i++) {
        int col = tid + (i << 8);
        dst[(size_t)rrow * HID + col] = (v[i] - mu) * invs * w[col] + bb[col];
    }
}

__global__ __launch_bounds__(256) void scores2_kernel()
{
    __shared__ float As[16][64];
    __shared__ float Bs[16][64];
    int tid = threadIdx.x;
    int t0 = blockIdx.x << 6;
    int b = blockIdx.y;
    int r = tid >> 2, c = (tid & 3) << 2;
    int tx = (tid & 15) << 2, ty = (tid >> 4) << 2;

    float acc[4][4] = {};
    for (int k0 = 0; k0 < SD; k0 += 16) {
        float4 av = *(const float4*)(g_kvr + (size_t)(b * NT + t0 + r) * 768 + 512 + k0 + c);
        As[c + 0][r] = av.x; As[c + 1][r] = av.y; As[c + 2][r] = av.z; As[c + 3][r] = av.w;
        float4 kv = *(const float4*)(g_rkv + (size_t)(b * NS + r) * 512 + k0 + c);
        Bs[c + 0][r] = kv.x; Bs[c + 1][r] = kv.y; Bs[c + 2][r] = kv.z; Bs[c + 3][r] = kv.w;
        __syncthreads();
        #pragma unroll
        for (int kk = 0; kk < 16; kk++) {
            float4 a = *(const float4*)&As[kk][ty];
            float4 d = *(const float4*)&Bs[kk][tx];
            acc[0][0] += a.x * d.x; acc[0][1] += a.x * d.y; acc[0][2] += a.x * d.z; acc[0][3] += a.x * d.w;
            acc[1][0] += a.y * d.x; acc[1][1] += a.y * d.y; acc[1][2] += a.y * d.z; acc[1][3] += a.y * d.w;
            acc[2][0] += a.z * d.x; acc[2][1] += a.z * d.y; acc[2][2] += a.z * d.z; acc[2][3] += a.z * d.w;
            acc[3][0] += a.w * d.x; acc[3][1] += a.w * d.y; acc[3][2] += a.w * d.z; acc[3][3] += a.w * d.w;
        }
        __syncthreads();
    }
    #pragma unroll
    for (int i = 0; i < 4; i++)
        #pragma unroll
        for (int j = 0; j < 4; j++)
            g_s2[((size_t)b * NT + t0 + ty + i) * NS + tx + j] = acc[i][j] * ATT_SCALE;
}

__global__ __launch_bounds__(256) void softmax2_kernel()
{
    int tid = threadIdx.x;
    int row = (blockIdx.x << 3) + (tid >> 5);
    int lane = tid & 31;
    float* p = g_s2 + (size_t)row * NS;
    float v0 = p[lane], v1 = p[lane + 32];
    float m = fmaxf(v0, v1);
    #pragma unroll
    for (int o = 16; o > 0; o >>= 1) m = fmaxf(m, __shfl_xor_sync(0xffffffffu, m, o));
    float e0 = expf(v0 - m), e1 = expf(v1 - m);
    float s = e0 + e1;
    #pragma unroll
    for (int o = 16; o > 0; o >>= 1) s += __shfl_xor_sync(0xffffffffu, s, o);
    float inv = 1.0f / s;
    p[lane] = e0 * inv;
    p[lane + 32] = e1 * inv;
}

__global__ __launch_bounds__(256) void pv2_kernel()
{
    __shared__ float As[16][64];
    __shared__ float Bs[16][64];
    int tid = threadIdx.x;
    int t0 = blockIdx.x << 6;
    int n0 = blockIdx.y << 6;
    int b = blockIdx.z;
    int r = tid >> 2, c = (tid & 3) << 2;
    int br = tid >> 4, bc = (tid & 15) << 2;
    int tx = (tid & 15) << 2, ty = (tid >> 4) << 2;

    float acc[4][4] = {};
    for (int k0 = 0; k0 < NS; k0 += 16) {
        float4 av = *(const float4*)(g_s2 + ((size_t)b * NT + t0 + r) * NS + k0 + c);
        As[c + 0][r] = av.x; As[c + 1][r] = av.y; As[c + 2][r] = av.z; As[c + 3][r] = av.w;
        *(float4*)&Bs[br][bc] = *(const float4*)(g_rkv + (size_t)(b * NS + k0 + br) * 512 + 256 + n0 + bc);
        __syncthreads();
        #pragma unroll
        for (int kk = 0; kk < 16; kk++) {
            float4 a = *(const float4*)&As[kk][ty];
            float4 d = *(const float4*)&Bs[kk][tx];
            acc[0][0] += a.x * d.x; acc[0][1] += a.x * d.y; acc[0][2] += a.x * d.z; acc[0][3] += a.x * d.w;
            acc[1][0] += a.y * d.x; acc[1][1] += a.y * d.y; acc[1][2] += a.y * d.z; acc[1][3] += a.y * d.w;
            acc[2][0] += a.z * d.x; acc[2][1] += a.z * d.y; acc[2][2] += a.z * d.z; acc[2][3] += a.z * d.w;
            acc[3][0] += a.w * d.x; acc[3][1] += a.w * d.y; acc[3][2] += a.w * d.z; acc[3][3] += a.w * d.w;
        }
        __syncthreads();
    }
    #pragma unroll
    for (int i = 0; i < 4; i++)
        #pragma unroll
        for (int j = 0; j < 4; j++)
            g_rout_sd[((size_t)b * NT + t0 + ty + i) * SD + n0 + tx + j] = acc[i][j];
}

__global__ __launch_bounds__(256) void loss_ln_kernel(
    const float* __restrict__ seg, const float* __restrict__ lnw,
    const float* __restrict__ lnb, const float* __restrict__ gate_bias)
{
    __shared__ float red[256];
    __shared__ float gsh;
    int tid = threadIdx.x, rrow = blockIdx.x;
    const float* row = g_rout_full + (size_t)rrow * HID;

    float v[16];
    #pragma unroll
    for (int i = 0; i < 16; i++) v[i] = row[tid + (i << 8)];

    if (tid == 0) {
        float sg = 0.f;
        for (int i = 0; i < 64; i++) sg += gate_bias[i];
        sg *= (1.0f / 64.0f);
        gsh = 1.0f / (1.0f + expf(-sg));
    }

    float sum = 0.f, sq = 0.f;
    #pragma unroll
    for (int i = 0; i < 16; i++) { sum += v[i]; sq += v[i] * v[i]; }
    float tsum = block_reduce_sum256(sum, red);
    float tsq  = block_reduce_sum256(sq, red);
    float mu = tsum * (1.0f / HID);
    float var = tsq * (1.0f / HID) - mu * mu;
    float invs = rsqrtf(var + LN_EPS);
    float g = gsh;

    const float* segrow = seg + (size_t)rrow * HID;
    float acc = 0.f;
    #pragma unroll
    for (int i = 0; i < 16; i++) {
        int col = tid + (i << 8);
        float rec = g * ((v[i] - mu) * invs * lnw[col] + lnb[col]);
        float d = rec - segrow[col];
        acc += d * d;
    }
    float bsum = block_reduce_sum256(acc, red);
    if (tid == 0) atomicAdd(&g_loss, (double)bsum);
}

__global__ void finalize_kernel(const float* __restrict__ gate_bias, float* __restrict__ outp)
{
    float sg = 0.f;
    for (int i = 0; i < 64; i++) sg += gate_bias[i];
    sg *= (1.0f / 64.0f);
    float g = 1.0f / (1.0f + expf(-sg));
    outp[NB * NS * HID]     = (float)(g_loss / (double)((size_t)NB * NT * HID));
    outp[NB * NS * HID + 1] = g;
}

// ---------------- launch ------------------------------------------------------------
extern "C" void kernel_launch(void* const* d_in, const int* in_sizes, int n_in,
                              void* d_out, int out_size)
{
    const float* seg      = (const float*)d_in[0];
    const float* slot_emb = (const float*)d_in[1];
    const float* Wq       = (const float*)d_in[2];
    const float* Wk       = (const float*)d_in[3];
    const float* Wv       = (const float*)d_in[4];
    const float* Wo       = (const float*)d_in[5];
    const float* Wrq      = (const float*)d_in[6];
    const float* Wro      = (const float*)d_in[7];
    const float* gateb    = (const float*)d_in[8];
    const float* snw      = (const float*)d_in[9];
    const float* snb      = (const float*)d_in[10];
    const float* rnw      = (const float*)d_in[11];
    const float* rnb      = (const float*)d_in[12];
    float* outp = (float*)d_out;

    float* kvr;      cudaGetSymbolAddress((void**)&kvr, g_kvr);
    float* qbuf;     cudaGetSymbolAddress((void**)&qbuf, g_q);
    float* out_sd;   cudaGetSymbolAddress((void**)&out_sd, g_out_sd);
    float* spre;     cudaGetSymbolAddress((void**)&spre, g_spre);
    float* rkv;      cudaGetSymbolAddress((void**)&rkv, g_rkv);
    float* rout_sd;  cudaGetSymbolAddress((void**)&rout_sd, g_rout_sd);
    float* rout_full;cudaGetSymbolAddress((void**)&rout_full, g_rout_full);
    __nv_bfloat16 *segh, *segl, *WTh, *WTl, *WroTh, *WroTl, *Rh, *Rl;
    cudaGetSymbolAddress((void**)&segh, g_segh);
    cudaGetSymbolAddress((void**)&segl, g_segl);
    cudaGetSymbolAddress((void**)&WTh, g_WTh);
    cudaGetSymbolAddress((void**)&WTl, g_WTl);
    cudaGetSymbolAddress((void**)&WroTh, g_WroTh);
    cudaGetSymbolAddress((void**)&WroTl, g_WroTl);
    cudaGetSymbolAddress((void**)&Rh, g_Rh);
    cudaGetSymbolAddress((void**)&Rl, g_Rl);

    cudaFuncSetAttribute(hmma_gemm, cudaFuncAttributeMaxDynamicSharedMemorySize, TC_SMEM_BYTES);

    init_loss_kernel<<<1, 1>>>();
    cudaMemsetAsync(qbuf, 0, (size_t)NS * SD * sizeof(float));
    cudaMemsetAsync(out_sd, 0, (size_t)NB * NS * SD * sizeof(float));
    cudaMemsetAsync(rkv, 0, (size_t)NB * NS * 512 * sizeof(float));

    // bf16 splits: seg, and transposed weights Wk|Wv|Wrq -> WT[768][4096], Wro -> WroT[4096][256]
    conv_hilo<<<(size_t)BT * HID / 1024, 256>>>(seg, segh, segl);
    transpose_conv<<<dim3(SD / 32, HID / 32), 256>>>(Wk,  WTh,             WTl,             HID, SD);
    transpose_conv<<<dim3(SD / 32, HID / 32), 256>>>(Wv,  WTh + 256 * HID, WTl + 256 * HID, HID, SD);
    transpose_conv<<<dim3(SD / 32, HID / 32), 256>>>(Wrq, WTh + 512 * HID, WTl + 512 * HID, HID, SD);
    transpose_conv<<<dim3(HID / 32, SD / 32), 256>>>(Wro, WroTh,           WroTl,           SD, HID);

    // k | v | rq = seg @ {Wk,Wv,Wrq}  — HMMA split-bf16
    hmma_gemm<<<dim3(6, BT / 128), 256, TC_SMEM_BYTES>>>(segh, segl, WTh, WTl, kvr, 768, HID);

    // q = slot_embeddings @ Wq  (split-K fp32)
    gemm_small<<<dim3(1, 4, 8), 256>>>(slot_emb, HID, Wq, nullptr, qbuf, SD);

    // attn1
    scores1_kernel<<<dim3(64, NB), 256>>>();
    softmax1_kernel<<<NB * NS, 256>>>();
    pv1_kernel<<<dim3(4, 8, NB), 256>>>();

    // slots + out@Wo, LN -> updated_slots in d_out
    wo_gemm<<<dim3(4, 64), 256>>>(Wo, slot_emb);
    ln_rows_kernel<<<NB * NS, 256>>>(spre, snw, snb, outp);

    // rk | rv = updated_slots @ {Wk, Wv}
    gemm_small<<<dim3(4, 8, 8), 256>>>(outp, HID, Wk, Wv, rkv, 512);

    // attn2
    scores2_kernel<<<dim3(64, NB), 256>>>();
    softmax2_kernel<<<BT / 8, 256>>>();
    pv2_kernel<<<dim3(64, 4, NB), 256>>>();

    // rout = rout_sd @ Wro — HMMA split-bf16
    conv_hilo<<<(size_t)BT * SD / 1024, 256>>>(rout_sd, Rh, Rl);
    hmma_gemm<<<dim3(HID / 128, BT / 128), 256, TC_SMEM_BYTES>>>(Rh, Rl, WroTh, WroTl, rout_full, HID, SD);

    // LN + gate + MSE
    loss_ln_kernel<<<BT, 256>>>(seg, rnw, rnb, gateb);
    finalize_kernel<<<1, 1>>>(gateb, outp);
}

// round 5
// speedup vs baseline: 4.5082x; 1.2167x over previous
#include <cuda_runtime.h>
#include <cuda_bf16.h>
#include <math.h>
#include <stdint.h>

#define HID 4096
#define SD 256
#define NS 64           // slots
#define NB 4            // batch
#define NT 4096         // tokens
#define BT (NB*NT)      // 16384
#define LN_EPS 1e-5f
#define ATT_SCALE 0.0625f  // 256^-0.5
#define KC 512          // split-K chunk for skinny GEMMs

// ---------------- scratch (static device globals; no runtime alloc) ----------------
__device__ float g_kvr[BT * 768];          // [b*T+t][ k(0:256) | v(256:512) | rq(512:768) ]
__device__ float g_q[NS * SD];             // slot queries (batch-independent)
__device__ float g_s1[NB * NS * NT];       // attn1 scores/probs [b][s][t]
__device__ float g_out_sd[NB * NS * SD];   // attn1 output before Wo
__device__ float g_spre[NB * NS * HID];    // slots + out@Wo, before LN
__device__ float g_rkv[NB * NS * 512];     // [b*S+s][ rk(0:256) | rv(256:512) ]
__device__ float g_s2[NB * NT * NS];       // attn2 scores/probs [b][t][s]
__device__ float g_rout_sd[BT * SD];       // attn2 output before Wro
__device__ float g_rout_full[67108864];    // [BT][HID] rout before LN (256 MB)
__device__ double g_loss;

// bf16 split operands for tensor-core GEMMs
__device__ __nv_bfloat16 g_segh[(size_t)BT * HID];   // seg hi
__device__ __nv_bfloat16 g_segl[(size_t)BT * HID];   // seg lo
__device__ __nv_bfloat16 g_WTh[768 * HID];           // [Wk|Wv|Wrq]^T  [768][4096]
__device__ __nv_bfloat16 g_WTl[768 * HID];
__device__ __nv_bfloat16 g_WroTh[HID * SD];          // Wro^T [4096][256]
__device__ __nv_bfloat16 g_WroTl[HID * SD];
__device__ __nv_bfloat16 g_Rh[BT * SD];              // rout_sd hi
__device__ __nv_bfloat16 g_Rl[BT * SD];              // rout_sd lo

// ================= ptx helpers (sm_80-era: valid on base sm_103 target) =================
__device__ __forceinline__ uint32_t s2u(const void* p) {
    uint32_t a;
    asm("{ .reg .u64 t; cvta.to.shared.u64 t, %1; cvt.u32.u64 %0, t; }" : "=r"(a) : "l"(p));
    return a;
}
__device__ __forceinline__ void cpa16(uint32_t dst, const void* src) {
    asm volatile("cp.async.cg.shared.global [%0], [%1], 16;" :: "r"(dst), "l"(src) : "memory");
}
__device__ __forceinline__ void ldsm_x4(uint32_t* r, uint32_t addr) {
    asm volatile("ldmatrix.sync.aligned.m8n8.x4.shared.b16 {%0,%1,%2,%3}, [%4];"
        : "=r"(r[0]), "=r"(r[1]), "=r"(r[2]), "=r"(r[3]) : "r"(addr));
}
__device__ __forceinline__ void ldsm_x2(uint32_t* r, uint32_t addr) {
    asm volatile("ldmatrix.sync.aligned.m8n8.x2.shared.b16 {%0,%1}, [%2];"
        : "=r"(r[0]), "=r"(r[1]) : "r"(addr));
}
__device__ __forceinline__ void mma16816(float* d, const uint32_t* a, const uint32_t* b) {
    asm volatile("mma.sync.aligned.m16n8k16.row.col.f32.bf16.bf16.f32 "
        "{%0,%1,%2,%3}, {%4,%5,%6,%7}, {%8,%9}, {%0,%1,%2,%3};"
        : "+f"(d[0]), "+f"(d[1]), "+f"(d[2]), "+f"(d[3])
        : "r"(a[0]), "r"(a[1]), "r"(a[2]), "r"(a[3]), "r"(b[0]), "r"(b[1]));
}
__device__ __forceinline__ uint32_t sw128(uint32_t off) { return off ^ ((off >> 3) & 0x70); }

#define STAGE_BYTES 65536
#define TC_SMEM_BYTES (2 * STAGE_BYTES)

// ===================================================================================
// HMMA split-bf16 GEMM (templated on number of split terms):
//   TERMS==3: C = Ah@Bh^T + Ah@Bl^T + Al@Bh^T  (error-compensated, ~2^-17 rel)
//   TERMS==1: C = Ah@Bh^T                      (plain bf16, ~2^-9 rel)
// A*: [Mtot][K] K-major bf16.  B*: [Ntot][K] K-major bf16 (pre-transposed weights).
// Block tile 128x128, K-chunk 64, 8 warps (each 64x32), 2-stage cp.async pipeline.
// grid (Ntot/128, Mtot/128). K multiple of 64.
// ===================================================================================
template<int TERMS>
__global__ void __launch_bounds__(256, 1) hmma_gemm(
    const __nv_bfloat16* __restrict__ Ah, const __nv_bfloat16* __restrict__ Al,
    const __nv_bfloat16* __restrict__ Bh, const __nv_bfloat16* __restrict__ Bl,
    float* __restrict__ C, int ldc, int K)
{
    extern __shared__ char smem[];
    uint32_t sb = s2u(smem);
    int tid = threadIdx.x, wid = tid >> 5, lane = tid & 31;
    int n0 = blockIdx.x << 7, m0 = blockIdx.y << 7;
    const int nch = K >> 6;
    int wm = (wid & 1) << 6;        // warp m offset within tile (0 or 64)
    int wn = (wid >> 1) << 5;       // warp n offset within tile (0..96)

    // stage layout: [Ah 16K][Al 16K][Bh 16K][Bl 16K], each 128 rows x 128 bytes, sw128
    #define LOAD_CHUNK(s, c) do { \
        uint32_t base = sb + (uint32_t)(s) * STAGE_BYTES; \
        int k0 = (c) << 6; \
        _Pragma("unroll") \
        for (int i = 0; i < 4; i++) { \
            int u = tid + (i << 8); \
            int row = u >> 3, cu = u & 7; \
            uint32_t sw = sw128((uint32_t)u << 4); \
            size_t ao = (size_t)(m0 + row) * K + k0 + (cu << 3); \
            size_t bo = (size_t)(n0 + row) * K + k0 + (cu << 3); \
            cpa16(base + sw,         Ah + ao); \
            cpa16(base + 32768 + sw, Bh + bo); \
            if (TERMS == 3) { \
                cpa16(base + 16384 + sw, Al + ao); \
                cpa16(base + 49152 + sw, Bl + bo); \
            } \
        } \
        asm volatile("cp.async.commit_group;" ::: "memory"); \
    } while (0)

    float acc[4][4][4] = {};   // [mi][ni][reg]

    LOAD_CHUNK(0, 0);

    for (int c = 0; c < nch; c++) {
        if (c + 1 < nch) {
            LOAD_CHUNK((c + 1) & 1, c + 1);
            asm volatile("cp.async.wait_group 1;" ::: "memory");
        } else {
            asm volatile("cp.async.wait_group 0;" ::: "memory");
        }
        __syncthreads();

        uint32_t base = sb + (uint32_t)(c & 1) * STAGE_BYTES;
        #pragma unroll
        for (int ks = 0; ks < 4; ks++) {
            uint32_t ah[4][4], al[4][4], bh[4][2], bl[4][2];
            // A fragments: 16x16 tiles at rows wm+mi*16, cols ks*16
            uint32_t acb = (uint32_t)((ks << 4) + ((lane >> 4) << 3)) << 1;  // byte col
            #pragma unroll
            for (int mi = 0; mi < 4; mi++) {
                uint32_t r = (uint32_t)(wm + (mi << 4) + (lane & 15));
                uint32_t sw = sw128((r << 7) + acb);
                ldsm_x4(ah[mi], base + sw);
                if (TERMS == 3) ldsm_x4(al[mi], base + 16384 + sw);
            }
            // B fragments: n8 k16 tiles at rows wn+ni*8, cols ks*16
            uint32_t bcb = (uint32_t)((ks << 4) + (((lane >> 3) & 1) << 3)) << 1;
            #pragma unroll
            for (int ni = 0; ni < 4; ni++) {
                uint32_t r = (uint32_t)(wn + (ni << 3) + (lane & 7));
                uint32_t sw = sw128((r << 7) + bcb);
                ldsm_x2(bh[ni], base + 32768 + sw);
                if (TERMS == 3) ldsm_x2(bl[ni], base + 49152 + sw);
            }
            #pragma unroll
            for (int mi = 0; mi < 4; mi++)
                #pragma unroll
                for (int ni = 0; ni < 4; ni++) {
                    mma16816(acc[mi][ni], ah[mi], bh[ni]);
                    if (TERMS == 3) {
                        mma16816(acc[mi][ni], ah[mi], bl[ni]);
                        mma16816(acc[mi][ni], al[mi], bh[ni]);
                    }
                }
        }
        __syncthreads();
    }

    // epilogue: fragment d: rows lane>>2 and +8, cols (lane&3)*2, +1
    int rbase = m0 + wm + (lane >> 2);
    int cbase = n0 + wn + ((lane & 3) << 1);
    #pragma unroll
    for (int mi = 0; mi < 4; mi++)
        #pragma unroll
        for (int ni = 0; ni < 4; ni++) {
            int row = rbase + (mi << 4);
            int col = cbase + (ni << 3);
            *(float2*)(C + (size_t)row * ldc + col)       = make_float2(acc[mi][ni][0], acc[mi][ni][1]);
            *(float2*)(C + (size_t)(row + 8) * ldc + col) = make_float2(acc[mi][ni][2], acc[mi][ni][3]);
        }
    #undef LOAD_CHUNK
}

// ---------------- fp32 -> (hi, lo) bf16 split, elementwise ----------------
__global__ void __launch_bounds__(256) conv_hilo(
    const float* __restrict__ src, __nv_bfloat16* __restrict__ h, __nv_bfloat16* __restrict__ l)
{
    size_t i = ((size_t)blockIdx.x * 256 + threadIdx.x) * 4;
    float4 v = *(const float4*)(src + i);
    __nv_bfloat16 h0 = __float2bfloat16(v.x), h1 = __float2bfloat16(v.y);
    __nv_bfloat16 h2 = __float2bfloat16(v.z), h3 = __float2bfloat16(v.w);
    __nv_bfloat16 l0 = __float2bfloat16(v.x - __bfloat162float(h0));
    __nv_bfloat16 l1 = __float2bfloat16(v.y - __bfloat162float(h1));
    __nv_bfloat16 l2 = __float2bfloat16(v.z - __bfloat162float(h2));
    __nv_bfloat16 l3 = __float2bfloat16(v.w - __bfloat162float(h3));
    *(__nv_bfloat162*)(h + i)     = __nv_bfloat162(h0, h1);
    *(__nv_bfloat162*)(h + i + 2) = __nv_bfloat162(h2, h3);
    *(__nv_bfloat162*)(l + i)     = __nv_bfloat162(l0, l1);
    *(__nv_bfloat162*)(l + i + 2) = __nv_bfloat162(l2, l3);
}

// ---------------- transpose + split: W[K][N] fp32 -> dst[N][K] bf16 hi/lo ----------
__global__ void __launch_bounds__(256) transpose_conv(
    const float* __restrict__ W, __nv_bfloat16* __restrict__ dh,
    __nv_bfloat16* __restrict__ dl, int K, int N)
{
    __shared__ float t[32][33];
    int n0 = blockIdx.x << 5, k0 = blockIdx.y << 5;
    int tx = threadIdx.x & 31, ty = threadIdx.x >> 5;  // 32 x 8
    #pragma unroll
    for (int i = 0; i < 32; i += 8)
        t[ty + i][tx] = W[(size_t)(k0 + ty + i) * N + n0 + tx];
    __syncthreads();
    #pragma unroll
    for (int i = 0; i < 32; i += 8) {
        float x = t[tx][ty + i];           // = W[k0+tx][n0+ty+i]
        int n = n0 + ty + i, k = k0 + tx;
        __nv_bfloat16 hh = __float2bfloat16(x);
        dh[(size_t)n * K + k] = hh;
        dl[(size_t)n * K + k] = __float2bfloat16(x - __bfloat162float(hh));
    }
}

// ---------------- helpers ----------------
__device__ __forceinline__ float block_reduce_sum256(float v, float* red) {
    int tid = threadIdx.x;
    red[tid] = v; __syncthreads();
    #pragma unroll
    for (int o = 128; o > 0; o >>= 1) {
        if (tid < o) red[tid] += red[tid + o];
        __syncthreads();
    }
    float r = red[0];
    __syncthreads();
    return r;
}

__global__ void init_loss_kernel() { g_loss = 0.0; }

// ===================================================================================
// Skinny split-K GEMM: 64x64 tile over a K-chunk of KC, atomicAdd into pre-zeroed C.
// ===================================================================================
__global__ __launch_bounds__(256) void gemm_small(
    const float* __restrict__ A, int lda,
    const float* __restrict__ W0, const float* __restrict__ W1,
    float* __restrict__ C, int ldc)
{
    __shared__ float As[16][64];
    __shared__ float Bs[16][64];
    int tid = threadIdx.x;
    int m0 = blockIdx.x << 6;
    int n0 = blockIdx.y << 6;
    int kbase = blockIdx.z * KC;
    const float* W = (n0 >> 8) ? W1 : W0;
    int col0 = n0 & 255;

    int r = tid >> 2, c = (tid & 3) << 2;
    int br = tid >> 4, bc = (tid & 15) << 2;
    int tx = (tid & 15) << 2, ty = (tid >> 4) << 2;

    float acc[4][4] = {};
    for (int k0 = kbase; k0 < kbase + KC; k0 += 16) {
        float4 av = *(const float4*)(A + (size_t)(m0 + r) * lda + k0 + c);
        As[c + 0][r] = av.x; As[c + 1][r] = av.y; As[c + 2][r] = av.z; As[c + 3][r] = av.w;
        *(float4*)&Bs[br][bc] = *(const float4*)(W + (size_t)(k0 + br) * 256 + col0 + bc);
        __syncthreads();
        #pragma unroll
        for (int kk = 0; kk < 16; kk++) {
            float4 a = *(const float4*)&As[kk][ty];
            float4 b = *(const float4*)&Bs[kk][tx];
            acc[0][0] += a.x * b.x; acc[0][1] += a.x * b.y; acc[0][2] += a.x * b.z; acc[0][3] += a.x * b.w;
            acc[1][0] += a.y * b.x; acc[1][1] += a.y * b.y; acc[1][2] += a.y * b.z; acc[1][3] += a.y * b.w;
            acc[2][0] += a.z * b.x; acc[2][1] += a.z * b.y; acc[2][2] += a.z * b.z; acc[2][3] += a.z * b.w;
            acc[3][0] += a.w * b.x; acc[3][1] += a.w * b.y; acc[3][2] += a.w * b.z; acc[3][3] += a.w * b.w;
        }
        __syncthreads();
    }
    #pragma unroll
    for (int i = 0; i < 4; i++)
        #pragma unroll
        for (int j = 0; j < 4; j++)
            atomicAdd(C + (size_t)(m0 + ty + i) * ldc + n0 + tx + j, acc[i][j]);
}

// ---------------- attn1 scores ----------------
__global__ __launch_bounds__(256) void scores1_kernel()
{
    __shared__ float Qs[16][64];
    __shared__ float Ks[16][64];
    int tid = threadIdx.x;
    int t0 = blockIdx.x << 6;
    int b = blockIdx.y;
    int r = tid >> 2, c = (tid & 3) << 2;
    int tx = (tid & 15) << 2, ty = (tid >> 4) << 2;

    float acc[4][4] = {};
    for (int k0 = 0; k0 < SD; k0 += 16) {
        float4 qv = *(const float4*)(g_q + (size_t)r * SD + k0 + c);
        Qs[c + 0][r] = qv.x; Qs[c + 1][r] = qv.y; Qs[c + 2][r] = qv.z; Qs[c + 3][r] = qv.w;
        float4 kv = *(const float4*)(g_kvr + (size_t)(b * NT + t0 + r) * 768 + k0 + c);
        Ks[c + 0][r] = kv.x; Ks[c + 1][r] = kv.y; Ks[c + 2][r] = kv.z; Ks[c + 3][r] = kv.w;
        __syncthreads();
        #pragma unroll
        for (int kk = 0; kk < 16; kk++) {
            float4 a = *(const float4*)&Qs[kk][ty];
            float4 d = *(const float4*)&Ks[kk][tx];
            acc[0][0] += a.x * d.x; acc[0][1] += a.x * d.y; acc[0][2] += a.x * d.z; acc[0][3] += a.x * d.w;
            acc[1][0] += a.y * d.x; acc[1][1] += a.y * d.y; acc[1][2] += a.y * d.z; acc[1][3] += a.y * d.w;
            acc[2][0] += a.z * d.x; acc[2][1] += a.z * d.y; acc[2][2] += a.z * d.z; acc[2][3] += a.z * d.w;
            acc[3][0] += a.w * d.x; acc[3][1] += a.w * d.y; acc[3][2] += a.w * d.z; acc[3][3] += a.w * d.w;
        }
        __syncthreads();
    }
    #pragma unroll
    for (int i = 0; i < 4; i++)
        #pragma unroll
        for (int j = 0; j < 4; j++)
            g_s1[((size_t)b * NS + ty + i) * NT + t0 + tx + j] = acc[i][j] * ATT_SCALE;
}

__global__ __launch_bounds__(256) void softmax1_kernel()
{
    __shared__ float red[256];
    int tid = threadIdx.x;
    float* row = g_s1 + (size_t)blockIdx.x * NT;

    float m = -1e30f;
    for (int t = tid; t < NT; t += 256) m = fmaxf(m, row[t]);
    red[tid] = m; __syncthreads();
    #pragma unroll
    for (int o = 128; o > 0; o >>= 1) { if (tid < o) red[tid] = fmaxf(red[tid], red[tid + o]); __syncthreads(); }
    m = red[0]; __syncthreads();

    float sum = 0.f;
    for (int t = tid; t < NT; t += 256) { float e = expf(row[t] - m); row[t] = e; sum += e; }
    float tot = block_reduce_sum256(sum, red);
    float inv = 1.0f / tot;
    for (int t = tid; t < NT; t += 256) row[t] *= inv;
}

__global__ __launch_bounds__(256) void pv1_kernel()
{
    __shared__ float As[16][64];
    __shared__ float Bs[16][64];
    int tid = threadIdx.x;
    int n0 = blockIdx.x << 6;
    int kbase = blockIdx.y * KC;
    int b = blockIdx.z;
    int r = tid >> 2, c = (tid & 3) << 2;
    int br = tid >> 4, bc = (tid & 15) << 2;
    int tx = (tid & 15) << 2, ty = (tid >> 4) << 2;

    float acc[4][4] = {};
    for (int k0 = kbase; k0 < kbase + KC; k0 += 16) {
        float4 av = *(const float4*)(g_s1 + ((size_t)b * NS + r) * NT + k0 + c);
        As[c + 0][r] = av.x; As[c + 1][r] = av.y; As[c + 2][r] = av.z; As[c + 3][r] = av.w;
        *(float4*)&Bs[br][bc] = *(const float4*)(g_kvr + (size_t)(b * NT + k0 + br) * 768 + 256 + n0 + bc);
        __syncthreads();
        #pragma unroll
        for (int kk = 0; kk < 16; kk++) {
            float4 a = *(const float4*)&As[kk][ty];
            float4 d = *(const float4*)&Bs[kk][tx];
            acc[0][0] += a.x * d.x; acc[0][1] += a.x * d.y; acc[0][2] += a.x * d.z; acc[0][3] += a.x * d.w;
            acc[1][0] += a.y * d.x; acc[1][1] += a.y * d.y; acc[1][2] += a.y * d.z; acc[1][3] += a.y * d.w;
            acc[2][0] += a.z * d.x; acc[2][1] += a.z * d.y; acc[2][2] += a.z * d.z; acc[2][3] += a.z * d.w;
            acc[3][0] += a.w * d.x; acc[3][1] += a.w * d.y; acc[3][2] += a.w * d.z; acc[3][3] += a.w * d.w;
        }
        __syncthreads();
    }
    #pragma unroll
    for (int i = 0; i < 4; i++)
        #pragma unroll
        for (int j = 0; j < 4; j++)
            atomicAdd(g_out_sd + ((size_t)b * NS + ty + i) * SD + n0 + tx + j, acc[i][j]);
}

__global__ __launch_bounds__(256) void wo_gemm(
    const float* __restrict__ Wo, const float* __restrict__ slot_emb)
{
    __shared__ float As[16][64];
    __shared__ float Bs[16][64];
    int tid = threadIdx.x;
    int m0 = blockIdx.x << 6;
    int n0 = blockIdx.y << 6;
    int r = tid >> 2, c = (tid & 3) << 2;
    int br = tid >> 4, bc = (tid & 15) << 2;
    int tx = (tid & 15) << 2, ty = (tid >> 4) << 2;

    float acc[4][4] = {};
    for (int k0 = 0; k0 < SD; k0 += 16) {
        float4 av = *(const float4*)(g_out_sd + (size_t)(m0 + r) * SD + k0 + c);
        As[c + 0][r] = av.x; As[c + 1][r] = av.y; As[c + 2][r] = av.z; As[c + 3][r] = av.w;
        *(float4*)&Bs[br][bc] = *(const float4*)(Wo + (size_t)(k0 + br) * HID + n0 + bc);
        __syncthreads();
        #pragma unroll
        for (int kk = 0; kk < 16; kk++) {
            float4 a = *(const float4*)&As[kk][ty];
            float4 d = *(const float4*)&Bs[kk][tx];
            acc[0][0] += a.x * d.x; acc[0][1] += a.x * d.y; acc[0][2] += a.x * d.z; acc[0][3] += a.x * d.w;
            acc[1][0] += a.y * d.x; acc[1][1] += a.y * d.y; acc[1][2] += a.y * d.z; acc[1][3] += a.y * d.w;
            acc[2][0] += a.z * d.x; acc[2][1] += a.z * d.y; acc[2][2] += a.z * d.z; acc[2][3] += a.z * d.w;
            acc[3][0] += a.w * d.x; acc[3][1] += a.w * d.y; acc[3][2] += a.w * d.z; acc[3][3] += a.w * d.w;
        }
        __syncthreads();
    }
    #pragma unroll
    for (int i = 0; i < 4; i++) {
        int row = m0 + ty + i;
        int s = row & 63;
        #pragma unroll
        for (int j = 0; j < 4; j++) {
            int col = n0 + tx + j;
            g_spre[(size_t)row * HID + col] = acc[i][j] + slot_emb[(size_t)s * HID + col];
        }
    }
}

__global__ __launch_bounds__(256) void ln_rows_kernel(
    const float* __restrict__ src, const float* __restrict__ w,
    const float* __restrict__ bb, float* __restrict__ dst)
{
    __shared__ float red[256];
    int tid = threadIdx.x, rrow = blockIdx.x;
    const float* row = src + (size_t)rrow * HID;

    float v[16];
    #pragma unroll
    for (int i = 0; i < 16; i++) v[i] = row[tid + (i << 8)];
    float sum = 0.f, sq = 0.f;
    #pragma unroll
    for (int i = 0; i < 16; i++) { sum += v[i]; sq += v[i] * v[i]; }
    float tsum = block_reduce_sum256(sum, red);
    float tsq  = block_reduce_sum256(sq, red);
    float mu = tsum * (1.0f / HID);
    float var = tsq * (1.0f / HID) - mu * mu;
    float invs = rsqrtf(var + LN_EPS);
    #pragma unroll
    for (int i = 0; i < 16; i++) {
        int col = tid + (i << 8);
        dst[(size_t)rrow * HID + col] = (v[i] - mu) * invs * w[col] + bb[col];
    }
}

__global__ __launch_bounds__(256) void scores2_kernel()
{
    __shared__ float As[16][64];
    __shared__ float Bs[16][64];
    int tid = threadIdx.x;
    int t0 = blockIdx.x << 6;
    int b = blockIdx.y;
    int r = tid >> 2, c = (tid & 3) << 2;
    int tx = (tid & 15) << 2, ty = (tid >> 4) << 2;

    float acc[4][4] = {};
    for (int k0 = 0; k0 < SD; k0 += 16) {
        float4 av = *(const float4*)(g_kvr + (size_t)(b * NT + t0 + r) * 768 + 512 + k0 + c);
        As[c + 0][r] = av.x; As[c + 1][r] = av.y; As[c + 2][r] = av.z; As[c + 3][r] = av.w;
        float4 kv = *(const float4*)(g_rkv + (size_t)(b * NS + r) * 512 + k0 + c);
        Bs[c + 0][r] = kv.x; Bs[c + 1][r] = kv.y; Bs[c + 2][r] = kv.z; Bs[c + 3][r] = kv.w;
        __syncthreads();
        #pragma unroll
        for (int kk = 0; kk < 16; kk++) {
            float4 a = *(const float4*)&As[kk][ty];
            float4 d = *(const float4*)&Bs[kk][tx];
            acc[0][0] += a.x * d.x; acc[0][1] += a.x * d.y; acc[0][2] += a.x * d.z; acc[0][3] += a.x * d.w;
            acc[1][0] += a.y * d.x; acc[1][1] += a.y * d.y; acc[1][2] += a.y * d.z; acc[1][3] += a.y * d.w;
            acc[2][0] += a.z * d.x; acc[2][1] += a.z * d.y; acc[2][2] += a.z * d.z; acc[2][3] += a.z * d.w;
            acc[3][0] += a.w * d.x; acc[3][1] += a.w * d.y; acc[3][2] += a.w * d.z; acc[3][3] += a.w * d.w;
        }
        __syncthreads();
    }
    #pragma unroll
    for (int i = 0; i < 4; i++)
        #pragma unroll
        for (int j = 0; j < 4; j++)
            g_s2[((size_t)b * NT + t0 + ty + i) * NS + tx + j] = acc[i][j] * ATT_SCALE;
}

__global__ __launch_bounds__(256) void softmax2_kernel()
{
    int tid = threadIdx.x;
    int row = (blockIdx.x << 3) + (tid >> 5);
    int lane = tid & 31;
    float* p = g_s2 + (size_t)row * NS;
    float v0 = p[lane], v1 = p[lane + 32];
    float m = fmaxf(v0, v1);
    #pragma unroll
    for (int o = 16; o > 0; o >>= 1) m = fmaxf(m, __shfl_xor_sync(0xffffffffu, m, o));
    float e0 = expf(v0 - m), e1 = expf(v1 - m);
    float s = e0 + e1;
    #pragma unroll
    for (int o = 16; o > 0; o >>= 1) s += __shfl_xor_sync(0xffffffffu, s, o);
    float inv = 1.0f / s;
    p[lane] = e0 * inv;
    p[lane + 32] = e1 * inv;
}

__global__ __launch_bounds__(256) void pv2_kernel()
{
    __shared__ float As[16][64];
    __shared__ float Bs[16][64];
    int tid = threadIdx.x;
    int t0 = blockIdx.x << 6;
    int n0 = blockIdx.y << 6;
    int b = blockIdx.z;
    int r = tid >> 2, c = (tid & 3) << 2;
    int br = tid >> 4, bc = (tid & 15) << 2;
    int tx = (tid & 15) << 2, ty = (tid >> 4) << 2;

    float acc[4][4] = {};
    for (int k0 = 0; k0 < NS; k0 += 16) {
        float4 av = *(const float4*)(g_s2 + ((size_t)b * NT + t0 + r) * NS + k0 + c);
        As[c + 0][r] = av.x; As[c + 1][r] = av.y; As[c + 2][r] = av.z; As[c + 3][r] = av.w;
        *(float4*)&Bs[br][bc] = *(const float4*)(g_rkv + (size_t)(b * NS + k0 + br) * 512 + 256 + n0 + bc);
        __syncthreads();
        #pragma unroll
        for (int kk = 0; kk < 16; kk++) {
            float4 a = *(const float4*)&As[kk][ty];
            float4 d = *(const float4*)&Bs[kk][tx];
            acc[0][0] += a.x * d.x; acc[0][1] += a.x * d.y; acc[0][2] += a.x * d.z; acc[0][3] += a.x * d.w;
            acc[1][0] += a.y * d.x; acc[1][1] += a.y * d.y; acc[1][2] += a.y * d.z; acc[1][3] += a.y * d.w;
            acc[2][0] += a.z * d.x; acc[2][1] += a.z * d.y; acc[2][2] += a.z * d.z; acc[2][3] += a.z * d.w;
            acc[3][0] += a.w * d.x; acc[3][1] += a.w * d.y; acc[3][2] += a.w * d.z; acc[3][3] += a.w * d.w;
        }
        __syncthreads();
    }
    #pragma unroll
    for (int i = 0; i < 4; i++)
        #pragma unroll
        for (int j = 0; j < 4; j++)
            g_rout_sd[((size_t)b * NT + t0 + ty + i) * SD + n0 + tx + j] = acc[i][j];
}

__global__ __launch_bounds__(256) void loss_ln_kernel(
    const float* __restrict__ seg, const float* __restrict__ lnw,
    const float* __restrict__ lnb, const float* __restrict__ gate_bias)
{
    __shared__ float red[256];
    __shared__ float gsh;
    int tid = threadIdx.x, rrow = blockIdx.x;
    const float* row = g_rout_full + (size_t)rrow * HID;

    float v[16];
    #pragma unroll
    for (int i = 0; i < 16; i++) v[i] = row[tid + (i << 8)];

    if (tid == 0) {
        float sg = 0.f;
        for (int i = 0; i < 64; i++) sg += gate_bias[i];
        sg *= (1.0f / 64.0f);
        gsh = 1.0f / (1.0f + expf(-sg));
    }

    float sum = 0.f, sq = 0.f;
    #pragma unroll
    for (int i = 0; i < 16; i++) { sum += v[i]; sq += v[i] * v[i]; }
    float tsum = block_reduce_sum256(sum, red);
    float tsq  = block_reduce_sum256(sq, red);
    float mu = tsum * (1.0f / HID);
    float var = tsq * (1.0f / HID) - mu * mu;
    float invs = rsqrtf(var + LN_EPS);
    float g = gsh;

    const float* segrow = seg + (size_t)rrow * HID;
    float acc = 0.f;
    #pragma unroll
    for (int i = 0; i < 16; i++) {
        int col = tid + (i << 8);
        float rec = g * ((v[i] - mu) * invs * lnw[col] + lnb[col]);
        float d = rec - segrow[col];
        acc += d * d;
    }
    float bsum = block_reduce_sum256(acc, red);
    if (tid == 0) atomicAdd(&g_loss, (double)bsum);
}

__global__ void finalize_kernel(const float* __restrict__ gate_bias, float* __restrict__ outp)
{
    float sg = 0.f;
    for (int i = 0; i < 64; i++) sg += gate_bias[i];
    sg *= (1.0f / 64.0f);
    float g = 1.0f / (1.0f + expf(-sg));
    outp[NB * NS * HID]     = (float)(g_loss / (double)((size_t)NB * NT * HID));
    outp[NB * NS * HID + 1] = g;
}

// ---------------- launch ------------------------------------------------------------
extern "C" void kernel_launch(void* const* d_in, const int* in_sizes, int n_in,
                              void* d_out, int out_size)
{
    const float* seg      = (const float*)d_in[0];
    const float* slot_emb = (const float*)d_in[1];
    const float* Wq       = (const float*)d_in[2];
    const float* Wk       = (const float*)d_in[3];
    const float* Wv       = (const float*)d_in[4];
    const float* Wo       = (const float*)d_in[5];
    const float* Wrq      = (const float*)d_in[6];
    const float* Wro      = (const float*)d_in[7];
    const float* gateb    = (const float*)d_in[8];
    const float* snw      = (const float*)d_in[9];
    const float* snb      = (const float*)d_in[10];
    const float* rnw      = (const float*)d_in[11];
    const float* rnb      = (const float*)d_in[12];
    float* outp = (float*)d_out;

    float* kvr;      cudaGetSymbolAddress((void**)&kvr, g_kvr);
    float* qbuf;     cudaGetSymbolAddress((void**)&qbuf, g_q);
    float* out_sd;   cudaGetSymbolAddress((void**)&out_sd, g_out_sd);
    float* spre;     cudaGetSymbolAddress((void**)&spre, g_spre);
    float* rkv;      cudaGetSymbolAddress((void**)&rkv, g_rkv);
    float* rout_sd;  cudaGetSymbolAddress((void**)&rout_sd, g_rout_sd);
    float* rout_full;cudaGetSymbolAddress((void**)&rout_full, g_rout_full);
    __nv_bfloat16 *segh, *segl, *WTh, *WTl, *WroTh, *WroTl, *Rh, *Rl;
    cudaGetSymbolAddress((void**)&segh, g_segh);
    cudaGetSymbolAddress((void**)&segl, g_segl);
    cudaGetSymbolAddress((void**)&WTh, g_WTh);
    cudaGetSymbolAddress((void**)&WTl, g_WTl);
    cudaGetSymbolAddress((void**)&WroTh, g_WroTh);
    cudaGetSymbolAddress((void**)&WroTl, g_WroTl);
    cudaGetSymbolAddress((void**)&Rh, g_Rh);
    cudaGetSymbolAddress((void**)&Rl, g_Rl);

    cudaFuncSetAttribute(hmma_gemm<3>, cudaFuncAttributeMaxDynamicSharedMemorySize, TC_SMEM_BYTES);
    cudaFuncSetAttribute(hmma_gemm<1>, cudaFuncAttributeMaxDynamicSharedMemorySize, TC_SMEM_BYTES);

    init_loss_kernel<<<1, 1>>>();
    cudaMemsetAsync(qbuf, 0, (size_t)NS * SD * sizeof(float));
    cudaMemsetAsync(out_sd, 0, (size_t)NB * NS * SD * sizeof(float));
    cudaMemsetAsync(rkv, 0, (size_t)NB * NS * 512 * sizeof(float));

    // bf16 splits: seg, and transposed weights Wk|Wv|Wrq -> WT[768][4096], Wro -> WroT[4096][256]
    conv_hilo<<<(size_t)BT * HID / 1024, 256>>>(seg, segh, segl);
    transpose_conv<<<dim3(SD / 32, HID / 32), 256>>>(Wk,  WTh,             WTl,             HID, SD);
    transpose_conv<<<dim3(SD / 32, HID / 32), 256>>>(Wv,  WTh + 256 * HID, WTl + 256 * HID, HID, SD);
    transpose_conv<<<dim3(SD / 32, HID / 32), 256>>>(Wrq, WTh + 512 * HID, WTl + 512 * HID, HID, SD);
    transpose_conv<<<dim3(HID / 32, SD / 32), 256>>>(Wro, WroTh,           WroTl,           SD, HID);

    // k | v = seg @ {Wk,Wv}  — 3-pass split (feeds updated_slots: needs accuracy)
    hmma_gemm<3><<<dim3(4, BT / 128), 256, TC_SMEM_BYTES>>>(segh, segl, WTh, WTl, kvr, 768, HID);
    // rq = seg @ Wrq — 1-pass bf16 (feeds loss only)
    hmma_gemm<1><<<dim3(2, BT / 128), 256, TC_SMEM_BYTES>>>(segh, segl, WTh + 512 * HID, WTl + 512 * HID, kvr + 512, 768, HID);

    // q = slot_embeddings @ Wq  (split-K fp32)
    gemm_small<<<dim3(1, 4, 8), 256>>>(slot_emb, HID, Wq, nullptr, qbuf, SD);

    // attn1
    scores1_kernel<<<dim3(64, NB), 256>>>();
    softmax1_kernel<<<NB * NS, 256>>>();
    pv1_kernel<<<dim3(4, 8, NB), 256>>>();

    // slots + out@Wo, LN -> updated_slots in d_out
    wo_gemm<<<dim3(4, 64), 256>>>(Wo, slot_emb);
    ln_rows_kernel<<<NB * NS, 256>>>(spre, snw, snb, outp);

    // rk | rv = updated_slots @ {Wk, Wv}
    gemm_small<<<dim3(4, 8, 8), 256>>>(outp, HID, Wk, Wv, rkv, 512);

    // attn2
    scores2_kernel<<<dim3(64, NB), 256>>>();
    softmax2_kernel<<<BT / 8, 256>>>();
    pv2_kernel<<<dim3(64, 4, NB), 256>>>();

    // rout = rout_sd @ Wro — 1-pass bf16 (feeds loss only)
    conv_hilo<<<(size_t)BT * SD / 1024, 256>>>(rout_sd, Rh, Rl);
    hmma_gemm<1><<<dim3(HID / 128, BT / 128), 256, TC_SMEM_BYTES>>>(Rh, Rl, WroTh, WroTl, rout_full, HID, SD);

    // LN + gate + MSE
    loss_ln_kernel<<<BT, 256>>>(seg, rnw, rnb, gateb);
    finalize_kernel<<<1, 1>>>(gateb, outp);
}

// round 6
// speedup vs baseline: 4.8817x; 1.0829x over previous
#include <cuda_runtime.h>
#include <cuda_bf16.h>
#include <math.h>
#include <stdint.h>

#define HID 4096
#define SD 256
#define NS 64           // slots
#define NB 4            // batch
#define NT 4096         // tokens
#define BT (NB*NT)      // 16384
#define LN_EPS 1e-5f
#define ATT_SCALE 0.0625f  // 256^-0.5
#define KC 512          // split-K chunk for skinny GEMMs

// ---------------- scratch (static device globals; no runtime alloc) ----------------
__device__ float g_kvr[BT * 768];          // [b*T+t][ k(0:256) | v(256:512) | rq(512:768) ]
__device__ float g_q[NS * SD];             // slot queries (batch-independent)
__device__ float g_s1[NB * NS * NT];       // attn1 scores/probs [b][s][t]
__device__ float g_out_sd[NB * NS * SD];   // attn1 output before Wo
__device__ float g_spre[NB * NS * HID];    // slots + out@Wo, before LN
__device__ float g_rkv[NB * NS * 512];     // [b*S+s][ rk(0:256) | rv(256:512) ]
__device__ float g_s2[NB * NT * NS];       // attn2 scores [b][t][s]
__device__ __nv_bfloat16 g_p2h[NB * NT * NS];      // attn2 probs bf16 [b*T+t][s]
__device__ __nv_bfloat16 g_rvwt[NB * HID * NS];    // (rv@Wro)^T per batch: [b][n][s]
__device__ __nv_bfloat16 g_routb[(size_t)BT * HID];// rout before LN, bf16 (128 MB)
__device__ double g_loss;

// bf16 split operands for tensor-core GEMMs
__device__ __nv_bfloat16 g_segh[(size_t)BT * HID];   // seg hi
__device__ __nv_bfloat16 g_segl[(size_t)BT * HID];   // seg lo
__device__ __nv_bfloat16 g_WTh[768 * HID];           // [Wk|Wv|Wrq]^T  [768][4096]
__device__ __nv_bfloat16 g_WTl[768 * HID];

// ================= ptx helpers (sm_80-era: valid on base sm_103 target) =================
__device__ __forceinline__ uint32_t s2u(const void* p) {
    uint32_t a;
    asm("{ .reg .u64 t; cvta.to.shared.u64 t, %1; cvt.u32.u64 %0, t; }" : "=r"(a) : "l"(p));
    return a;
}
__device__ __forceinline__ void cpa16(uint32_t dst, const void* src) {
    asm volatile("cp.async.cg.shared.global [%0], [%1], 16;" :: "r"(dst), "l"(src) : "memory");
}
__device__ __forceinline__ void ldsm_x4(uint32_t* r, uint32_t addr) {
    asm volatile("ldmatrix.sync.aligned.m8n8.x4.shared.b16 {%0,%1,%2,%3}, [%4];"
        : "=r"(r[0]), "=r"(r[1]), "=r"(r[2]), "=r"(r[3]) : "r"(addr));
}
__device__ __forceinline__ void ldsm_x2(uint32_t* r, uint32_t addr) {
    asm volatile("ldmatrix.sync.aligned.m8n8.x2.shared.b16 {%0,%1}, [%2];"
        : "=r"(r[0]), "=r"(r[1]) : "r"(addr));
}
__device__ __forceinline__ void mma16816(float* d, const uint32_t* a, const uint32_t* b) {
    asm volatile("mma.sync.aligned.m16n8k16.row.col.f32.bf16.bf16.f32 "
        "{%0,%1,%2,%3}, {%4,%5,%6,%7}, {%8,%9}, {%0,%1,%2,%3};"
        : "+f"(d[0]), "+f"(d[1]), "+f"(d[2]), "+f"(d[3])
        : "r"(a[0]), "r"(a[1]), "r"(a[2]), "r"(a[3]), "r"(b[0]), "r"(b[1]));
}
__device__ __forceinline__ uint32_t sw128(uint32_t off) { return off ^ ((off >> 3) & 0x70); }

// ===================================================================================
// HMMA split-bf16 GEMM.
//   TERMS==3: C = Ah@Bh^T + Ah@Bl^T + Al@Bh^T   TERMS==1: C = Ah@Bh^T
//   OUTBF16:  C written as bf16 (packed bf16x2) instead of fp32.
// A*: [Mtot][K] K-major bf16.  B*: [Ntot][K] K-major bf16.
// Block tile 128x128, K-chunk 64, 8 warps (64x32 each), 3-stage cp.async pipeline.
// grid (Ntot/128, Mtot/128). K multiple of 64.
// ===================================================================================
template<int TERMS, int OUTBF16>
__global__ void __launch_bounds__(256, 1) hmma_gemm(
    const __nv_bfloat16* __restrict__ Ah, const __nv_bfloat16* __restrict__ Al,
    const __nv_bfloat16* __restrict__ Bh, const __nv_bfloat16* __restrict__ Bl,
    void* __restrict__ Cv, int ldc, int K)
{
    constexpr uint32_t STAGE = (TERMS == 3) ? 65536u : 32768u;
    constexpr uint32_t AL_OFF = 16384u;
    constexpr uint32_t BH_OFF = (TERMS == 3) ? 32768u : 16384u;
    constexpr uint32_t BL_OFF = 49152u;
    extern __shared__ char smem[];
    uint32_t sb = s2u(smem);
    int tid = threadIdx.x, wid = tid >> 5, lane = tid & 31;
    int n0 = blockIdx.x << 7, m0 = blockIdx.y << 7;
    const int nch = K >> 6;
    int wm = (wid & 1) << 6;
    int wn = (wid >> 1) << 5;

    #define LOAD_CHUNK(s, c) do { \
        uint32_t base = sb + (uint32_t)(s) * STAGE; \
        int k0 = (c) << 6; \
        _Pragma("unroll") \
        for (int i = 0; i < 4; i++) { \
            int u = tid + (i << 8); \
            int row = u >> 3, cu = u & 7; \
            uint32_t sw = sw128((uint32_t)u << 4); \
            size_t ao = (size_t)(m0 + row) * K + k0 + (cu << 3); \
            size_t bo = (size_t)(n0 + row) * K + k0 + (cu << 3); \
            cpa16(base + sw,          Ah + ao); \
            cpa16(base + BH_OFF + sw, Bh + bo); \
            if (TERMS == 3) { \
                cpa16(base + AL_OFF + sw, Al + ao); \
                cpa16(base + BL_OFF + sw, Bl + bo); \
            } \
        } \
        asm volatile("cp.async.commit_group;" ::: "memory"); \
    } while (0)

    float acc[4][4][4] = {};

    LOAD_CHUNK(0, 0);
    if (nch > 1) LOAD_CHUNK(1, 1);

    for (int c = 0; c < nch; c++) {
        if (c + 2 < nch) {
            LOAD_CHUNK((c + 2) % 3, c + 2);
            asm volatile("cp.async.wait_group 2;" ::: "memory");
        } else if (c + 1 < nch) {
            asm volatile("cp.async.wait_group 1;" ::: "memory");
        } else {
            asm volatile("cp.async.wait_group 0;" ::: "memory");
        }
        __syncthreads();

        uint32_t base = sb + (uint32_t)(c % 3) * STAGE;
        #pragma unroll
        for (int ks = 0; ks < 4; ks++) {
            uint32_t ah[4][4], al[4][4], bh[4][2], bl[4][2];
            uint32_t acb = (uint32_t)((ks << 4) + ((lane >> 4) << 3)) << 1;
            #pragma unroll
            for (int mi = 0; mi < 4; mi++) {
                uint32_t r = (uint32_t)(wm + (mi << 4) + (lane & 15));
                uint32_t sw = sw128((r << 7) + acb);
                ldsm_x4(ah[mi], base + sw);
                if (TERMS == 3) ldsm_x4(al[mi], base + AL_OFF + sw);
            }
            uint32_t bcb = (uint32_t)((ks << 4) + (((lane >> 3) & 1) << 3)) << 1;
            #pragma unroll
            for (int ni = 0; ni < 4; ni++) {
                uint32_t r = (uint32_t)(wn + (ni << 3) + (lane & 7));
                uint32_t sw = sw128((r << 7) + bcb);
                ldsm_x2(bh[ni], base + BH_OFF + sw);
                if (TERMS == 3) ldsm_x2(bl[ni], base + BL_OFF + sw);
            }
            #pragma unroll
            for (int mi = 0; mi < 4; mi++)
                #pragma unroll
                for (int ni = 0; ni < 4; ni++) {
                    mma16816(acc[mi][ni], ah[mi], bh[ni]);
                    if (TERMS == 3) {
                        mma16816(acc[mi][ni], ah[mi], bl[ni]);
                        mma16816(acc[mi][ni], al[mi], bh[ni]);
                    }
                }
        }
        __syncthreads();
    }

    int rbase = m0 + wm + (lane >> 2);
    int cbase = n0 + wn + ((lane & 3) << 1);
    #pragma unroll
    for (int mi = 0; mi < 4; mi++)
        #pragma unroll
        for (int ni = 0; ni < 4; ni++) {
            int row = rbase + (mi << 4);
            int col = cbase + (ni << 3);
            if (OUTBF16) {
                __nv_bfloat16* C = (__nv_bfloat16*)Cv;
                *(__nv_bfloat162*)(C + (size_t)row * ldc + col) =
                    __nv_bfloat162(__float2bfloat16(acc[mi][ni][0]), __float2bfloat16(acc[mi][ni][1]));
                *(__nv_bfloat162*)(C + (size_t)(row + 8) * ldc + col) =
                    __nv_bfloat162(__float2bfloat16(acc[mi][ni][2]), __float2bfloat16(acc[mi][ni][3]));
            } else {
                float* C = (float*)Cv;
                *(float2*)(C + (size_t)row * ldc + col)       = make_float2(acc[mi][ni][0], acc[mi][ni][1]);
                *(float2*)(C + (size_t)(row + 8) * ldc + col) = make_float2(acc[mi][ni][2], acc[mi][ni][3]);
            }
        }
    #undef LOAD_CHUNK
}

// ---------------- fp32 -> (hi, lo) bf16 split, elementwise ----------------
__global__ void __launch_bounds__(256) conv_hilo(
    const float* __restrict__ src, __nv_bfloat16* __restrict__ h, __nv_bfloat16* __restrict__ l)
{
    size_t i = ((size_t)blockIdx.x * 256 + threadIdx.x) * 4;
    float4 v = *(const float4*)(src + i);
    __nv_bfloat16 h0 = __float2bfloat16(v.x), h1 = __float2bfloat16(v.y);
    __nv_bfloat16 h2 = __float2bfloat16(v.z), h3 = __float2bfloat16(v.w);
    __nv_bfloat16 l0 = __float2bfloat16(v.x - __bfloat162float(h0));
    __nv_bfloat16 l1 = __float2bfloat16(v.y - __bfloat162float(h1));
    __nv_bfloat16 l2 = __float2bfloat16(v.z - __bfloat162float(h2));
    __nv_bfloat16 l3 = __float2bfloat16(v.w - __bfloat162float(h3));
    *(__nv_bfloat162*)(h + i)     = __nv_bfloat162(h0, h1);
    *(__nv_bfloat162*)(h + i + 2) = __nv_bfloat162(h2, h3);
    *(__nv_bfloat162*)(l + i)     = __nv_bfloat162(l0, l1);
    *(__nv_bfloat162*)(l + i + 2) = __nv_bfloat162(l2, l3);
}

// ---------------- transpose + split: W[K][N] fp32 -> dst[N][K] bf16 hi/lo ----------
__global__ void __launch_bounds__(256) transpose_conv(
    const float* __restrict__ W, __nv_bfloat16* __restrict__ dh,
    __nv_bfloat16* __restrict__ dl, int K, int N)
{
    __shared__ float t[32][33];
    int n0 = blockIdx.x << 5, k0 = blockIdx.y << 5;
    int tx = threadIdx.x & 31, ty = threadIdx.x >> 5;
    #pragma unroll
    for (int i = 0; i < 32; i += 8)
        t[ty + i][tx] = W[(size_t)(k0 + ty + i) * N + n0 + tx];
    __syncthreads();
    #pragma unroll
    for (int i = 0; i < 32; i += 8) {
        float x = t[tx][ty + i];
        int n = n0 + ty + i, k = k0 + tx;
        __nv_bfloat16 hh = __float2bfloat16(x);
        dh[(size_t)n * K + k] = hh;
        dl[(size_t)n * K + k] = __float2bfloat16(x - __bfloat162float(hh));
    }
}

// ---------------- helpers ----------------
__device__ __forceinline__ float block_reduce_sum256(float v, float* red) {
    int tid = threadIdx.x;
    red[tid] = v; __syncthreads();
    #pragma unroll
    for (int o = 128; o > 0; o >>= 1) {
        if (tid < o) red[tid] += red[tid + o];
        __syncthreads();
    }
    float r = red[0];
    __syncthreads();
    return r;
}

__global__ void init_loss_kernel() { g_loss = 0.0; }

// ===================================================================================
// Skinny split-K GEMM: 64x64 tile over a K-chunk of KC, atomicAdd into pre-zeroed C.
// ===================================================================================
__global__ __launch_bounds__(256) void gemm_small(
    const float* __restrict__ A, int lda,
    const float* __restrict__ W0, const float* __restrict__ W1,
    float* __restrict__ C, int ldc)
{
    __shared__ float As[16][64];
    __shared__ float Bs[16][64];
    int tid = threadIdx.x;
    int m0 = blockIdx.x << 6;
    int n0 = blockIdx.y << 6;
    int kbase = blockIdx.z * KC;
    const float* W = (n0 >> 8) ? W1 : W0;
    int col0 = n0 & 255;

    int r = tid >> 2, c = (tid & 3) << 2;
    int br = tid >> 4, bc = (tid & 15) << 2;
    int tx = (tid & 15) << 2, ty = (tid >> 4) << 2;

    float acc[4][4] = {};
    for (int k0 = kbase; k0 < kbase + KC; k0 += 16) {
        float4 av = *(const float4*)(A + (size_t)(m0 + r) * lda + k0 + c);
        As[c + 0][r] = av.x; As[c + 1][r] = av.y; As[c + 2][r] = av.z; As[c + 3][r] = av.w;
        *(float4*)&Bs[br][bc] = *(const float4*)(W + (size_t)(k0 + br) * 256 + col0 + bc);
        __syncthreads();
        #pragma unroll
        for (int kk = 0; kk < 16; kk++) {
            float4 a = *(const float4*)&As[kk][ty];
            float4 b = *(const float4*)&Bs[kk][tx];
            acc[0][0] += a.x * b.x; acc[0][1] += a.x * b.y; acc[0][2] += a.x * b.z; acc[0][3] += a.x * b.w;
            acc[1][0] += a.y * b.x; acc[1][1] += a.y * b.y; acc[1][2] += a.y * b.z; acc[1][3] += a.y * b.w;
            acc[2][0] += a.z * b.x; acc[2][1] += a.z * b.y; acc[2][2] += a.z * b.z; acc[2][3] += a.z * b.w;
            acc[3][0] += a.w * b.x; acc[3][1] += a.w * b.y; acc[3][2] += a.w * b.z; acc[3][3] += a.w * b.w;
        }
        __syncthreads();
    }
    #pragma unroll
    for (int i = 0; i < 4; i++)
        #pragma unroll
        for (int j = 0; j < 4; j++)
            atomicAdd(C + (size_t)(m0 + ty + i) * ldc + n0 + tx + j, acc[i][j]);
}

// ---------------- attn1 scores ----------------
__global__ __launch_bounds__(256) void scores1_kernel()
{
    __shared__ float Qs[16][64];
    __shared__ float Ks[16][64];
    int tid = threadIdx.x;
    int t0 = blockIdx.x << 6;
    int b = blockIdx.y;
    int r = tid >> 2, c = (tid & 3) << 2;
    int tx = (tid & 15) << 2, ty = (tid >> 4) << 2;

    float acc[4][4] = {};
    for (int k0 = 0; k0 < SD; k0 += 16) {
        float4 qv = *(const float4*)(g_q + (size_t)r * SD + k0 + c);
        Qs[c + 0][r] = qv.x; Qs[c + 1][r] = qv.y; Qs[c + 2][r] = qv.z; Qs[c + 3][r] = qv.w;
        float4 kv = *(const float4*)(g_kvr + (size_t)(b * NT + t0 + r) * 768 + k0 + c);
        Ks[c + 0][r] = kv.x; Ks[c + 1][r] = kv.y; Ks[c + 2][r] = kv.z; Ks[c + 3][r] = kv.w;
        __syncthreads();
        #pragma unroll
        for (int kk = 0; kk < 16; kk++) {
            float4 a = *(const float4*)&Qs[kk][ty];
            float4 d = *(const float4*)&Ks[kk][tx];
            acc[0][0] += a.x * d.x; acc[0][1] += a.x * d.y; acc[0][2] += a.x * d.z; acc[0][3] += a.x * d.w;
            acc[1][0] += a.y * d.x; acc[1][1] += a.y * d.y; acc[1][2] += a.y * d.z; acc[1][3] += a.y * d.w;
            acc[2][0] += a.z * d.x; acc[2][1] += a.z * d.y; acc[2][2] += a.z * d.z; acc[2][3] += a.z * d.w;
            acc[3][0] += a.w * d.x; acc[3][1] += a.w * d.y; acc[3][2] += a.w * d.z; acc[3][3] += a.w * d.w;
        }
        __syncthreads();
    }
    #pragma unroll
    for (int i = 0; i < 4; i++)
        #pragma unroll
        for (int j = 0; j < 4; j++)
            g_s1[((size_t)b * NS + ty + i) * NT + t0 + tx + j] = acc[i][j] * ATT_SCALE;
}

__global__ __launch_bounds__(256) void softmax1_kernel()
{
    __shared__ float red[256];
    int tid = threadIdx.x;
    float* row = g_s1 + (size_t)blockIdx.x * NT;

    float m = -1e30f;
    for (int t = tid; t < NT; t += 256) m = fmaxf(m, row[t]);
    red[tid] = m; __syncthreads();
    #pragma unroll
    for (int o = 128; o > 0; o >>= 1) { if (tid < o) red[tid] = fmaxf(red[tid], red[tid + o]); __syncthreads(); }
    m = red[0]; __syncthreads();

    float sum = 0.f;
    for (int t = tid; t < NT; t += 256) { float e = expf(row[t] - m); row[t] = e; sum += e; }
    float tot = block_reduce_sum256(sum, red);
    float inv = 1.0f / tot;
    for (int t = tid; t < NT; t += 256) row[t] *= inv;
}

__global__ __launch_bounds__(256) void pv1_kernel()
{
    __shared__ float As[16][64];
    __shared__ float Bs[16][64];
    int tid = threadIdx.x;
    int n0 = blockIdx.x << 6;
    int kbase = blockIdx.y * KC;
    int b = blockIdx.z;
    int r = tid >> 2, c = (tid & 3) << 2;
    int br = tid >> 4, bc = (tid & 15) << 2;
    int tx = (tid & 15) << 2, ty = (tid >> 4) << 2;

    float acc[4][4] = {};
    for (int k0 = kbase; k0 < kbase + KC; k0 += 16) {
        float4 av = *(const float4*)(g_s1 + ((size_t)b * NS + r) * NT + k0 + c);
        As[c + 0][r] = av.x; As[c + 1][r] = av.y; As[c + 2][r] = av.z; As[c + 3][r] = av.w;
        *(float4*)&Bs[br][bc] = *(const float4*)(g_kvr + (size_t)(b * NT + k0 + br) * 768 + 256 + n0 + bc);
        __syncthreads();
        #pragma unroll
        for (int kk = 0; kk < 16; kk++) {
            float4 a = *(const float4*)&As[kk][ty];
            float4 d = *(const float4*)&Bs[kk][tx];
            acc[0][0] += a.x * d.x; acc[0][1] += a.x * d.y; acc[0][2] += a.x * d.z; acc[0][3] += a.x * d.w;
            acc[1][0] += a.y * d.x; acc[1][1] += a.y * d.y; acc[1][2] += a.y * d.z; acc[1][3] += a.y * d.w;
            acc[2][0] += a.z * d.x; acc[2][1] += a.z * d.y; acc[2][2] += a.z * d.z; acc[2][3] += a.z * d.w;
            acc[3][0] += a.w * d.x; acc[3][1] += a.w * d.y; acc[3][2] += a.w * d.z; acc[3][3] += a.w * d.w;
        }
        __syncthreads();
    }
    #pragma unroll
    for (int i = 0; i < 4; i++)
        #pragma unroll
        for (int j = 0; j < 4; j++)
            atomicAdd(g_out_sd + ((size_t)b * NS + ty + i) * SD + n0 + tx + j, acc[i][j]);
}

__global__ __launch_bounds__(256) void wo_gemm(
    const float* __restrict__ Wo, const float* __restrict__ slot_emb)
{
    __shared__ float As[16][64];
    __shared__ float Bs[16][64];
    int tid = threadIdx.x;
    int m0 = blockIdx.x << 6;
    int n0 = blockIdx.y << 6;
    int r = tid >> 2, c = (tid & 3) << 2;
    int br = tid >> 4, bc = (tid & 15) << 2;
    int tx = (tid & 15) << 2, ty = (tid >> 4) << 2;

    float acc[4][4] = {};
    for (int k0 = 0; k0 < SD; k0 += 16) {
        float4 av = *(const float4*)(g_out_sd + (size_t)(m0 + r) * SD + k0 + c);
        As[c + 0][r] = av.x; As[c + 1][r] = av.y; As[c + 2][r] = av.z; As[c + 3][r] = av.w;
        *(float4*)&Bs[br][bc] = *(const float4*)(Wo + (size_t)(k0 + br) * HID + n0 + bc);
        __syncthreads();
        #pragma unroll
        for (int kk = 0; kk < 16; kk++) {
            float4 a = *(const float4*)&As[kk][ty];
            float4 d = *(const float4*)&Bs[kk][tx];
            acc[0][0] += a.x * d.x; acc[0][1] += a.x * d.y; acc[0][2] += a.x * d.z; acc[0][3] += a.x * d.w;
            acc[1][0] += a.y * d.x; acc[1][1] += a.y * d.y; acc[1][2] += a.y * d.z; acc[1][3] += a.y * d.w;
            acc[2][0] += a.z * d.x; acc[2][1] += a.z * d.y; acc[2][2] += a.z * d.z; acc[2][3] += a.z * d.w;
            acc[3][0] += a.w * d.x; acc[3][1] += a.w * d.y; acc[3][2] += a.w * d.z; acc[3][3] += a.w * d.w;
        }
        __syncthreads();
    }
    #pragma unroll
    for (int i = 0; i < 4; i++) {
        int row = m0 + ty + i;
        int s = row & 63;
        #pragma unroll
        for (int j = 0; j < 4; j++) {
            int col = n0 + tx + j;
            g_spre[(size_t)row * HID + col] = acc[i][j] + slot_emb[(size_t)s * HID + col];
        }
    }
}

__global__ __launch_bounds__(256) void ln_rows_kernel(
    const float* __restrict__ src, const float* __restrict__ w,
    const float* __restrict__ bb, float* __restrict__ dst)
{
    __shared__ float red[256];
    int tid = threadIdx.x, rrow = blockIdx.x;
    const float* row = src + (size_t)rrow * HID;

    float v[16];
    #pragma unroll
    for (int i = 0; i < 16; i++) v[i] = row[tid + (i << 8)];
    float sum = 0.f, sq = 0.f;
    #pragma unroll
    for (int i = 0; i < 16; i++) { sum += v[i]; sq += v[i] * v[i]; }
    float tsum = block_reduce_sum256(sum, red);
    float tsq  = block_reduce_sum256(sq, red);
    float mu = tsum * (1.0f / HID);
    float var = tsq * (1.0f / HID) - mu * mu;
    float invs = rsqrtf(var + LN_EPS);
    #pragma unroll
    for (int i = 0; i < 16; i++) {
        int col = tid + (i << 8);
        dst[(size_t)rrow * HID + col] = (v[i] - mu) * invs * w[col] + bb[col];
    }
}

__global__ __launch_bounds__(256) void scores2_kernel()
{
    __shared__ float As[16][64];
    __shared__ float Bs[16][64];
    int tid = threadIdx.x;
    int t0 = blockIdx.x << 6;
    int b = blockIdx.y;
    int r = tid >> 2, c = (tid & 3) << 2;
    int tx = (tid & 15) << 2, ty = (tid >> 4) << 2;

    float acc[4][4] = {};
    for (int k0 = 0; k0 < SD; k0 += 16) {
        float4 av = *(const float4*)(g_kvr + (size_t)(b * NT + t0 + r) * 768 + 512 + k0 + c);
        As[c + 0][r] = av.x; As[c + 1][r] = av.y; As[c + 2][r] = av.z; As[c + 3][r] = av.w;
        float4 kv = *(const float4*)(g_rkv + (size_t)(b * NS + r) * 512 + k0 + c);
        Bs[c + 0][r] = kv.x; Bs[c + 1][r] = kv.y; Bs[c + 2][r] = kv.z; Bs[c + 3][r] = kv.w;
        __syncthreads();
        #pragma unroll
        for (int kk = 0; kk < 16; kk++) {
            float4 a = *(const float4*)&As[kk][ty];
            float4 d = *(const float4*)&Bs[kk][tx];
            acc[0][0] += a.x * d.x; acc[0][1] += a.x * d.y; acc[0][2] += a.x * d.z; acc[0][3] += a.x * d.w;
            acc[1][0] += a.y * d.x; acc[1][1] += a.y * d.y; acc[1][2] += a.y * d.z; acc[1][3] += a.y * d.w;
            acc[2][0] += a.z * d.x; acc[2][1] += a.z * d.y; acc[2][2] += a.z * d.z; acc[2][3] += a.z * d.w;
            acc[3][0] += a.w * d.x; acc[3][1] += a.w * d.y; acc[3][2] += a.w * d.z; acc[3][3] += a.w * d.w;
        }
        __syncthreads();
    }
    #pragma unroll
    for (int i = 0; i < 4; i++)
        #pragma unroll
        for (int j = 0; j < 4; j++)
            g_s2[((size_t)b * NT + t0 + ty + i) * NS + tx + j] = acc[i][j] * ATT_SCALE;
}

// softmax over s (64) per (b,t) row; writes NORMALIZED probs as bf16 to g_p2h
__global__ __launch_bounds__(256) void softmax2_kernel()
{
    int tid = threadIdx.x;
    int row = (blockIdx.x << 3) + (tid >> 5);
    int lane = tid & 31;
    const float* p = g_s2 + (size_t)row * NS;
    float v0 = p[lane], v1 = p[lane + 32];
    float m = fmaxf(v0, v1);
    #pragma unroll
    for (int o = 16; o > 0; o >>= 1) m = fmaxf(m, __shfl_xor_sync(0xffffffffu, m, o));
    float e0 = expf(v0 - m), e1 = expf(v1 - m);
    float s = e0 + e1;
    #pragma unroll
    for (int o = 16; o > 0; o >>= 1) s += __shfl_xor_sync(0xffffffffu, s, o);
    float inv = 1.0f / s;
    g_p2h[(size_t)row * NS + lane]      = __float2bfloat16(e0 * inv);
    g_p2h[(size_t)row * NS + lane + 32] = __float2bfloat16(e1 * inv);
}

// rvWT[b][n][s] = sum_k rv[b][s][k] * Wro[k][n], written transposed as bf16.
// grid (64 n-tiles, 4 batches), 256 threads, 64x64 tile, K=256.
__global__ __launch_bounds__(256) void rvw_gemm(const float* __restrict__ Wro)
{
    __shared__ float As[16][64];
    __shared__ float Bs[16][64];
    int tid = threadIdx.x;
    int n0 = blockIdx.x << 6;
    int b = blockIdx.y;
    int r = tid >> 2, c = (tid & 3) << 2;
    int br = tid >> 4, bc = (tid & 15) << 2;
    int tx = (tid & 15) << 2, ty = (tid >> 4) << 2;

    float acc[4][4] = {};
    for (int k0 = 0; k0 < SD; k0 += 16) {
        float4 av = *(const float4*)(g_rkv + (size_t)(b * NS + r) * 512 + 256 + k0 + c);
        As[c + 0][r] = av.x; As[c + 1][r] = av.y; As[c + 2][r] = av.z; As[c + 3][r] = av.w;
        *(float4*)&Bs[br][bc] = *(const float4*)(Wro + (size_t)(k0 + br) * HID + n0 + bc);
        __syncthreads();
        #pragma unroll
        for (int kk = 0; kk < 16; kk++) {
            float4 a = *(const float4*)&As[kk][ty];
            float4 d = *(const float4*)&Bs[kk][tx];
            acc[0][0] += a.x * d.x; acc[0][1] += a.x * d.y; acc[0][2] += a.x * d.z; acc[0][3] += a.x * d.w;
            acc[1][0] += a.y * d.x; acc[1][1] += a.y * d.y; acc[1][2] += a.y * d.z; acc[1][3] += a.y * d.w;
            acc[2][0] += a.z * d.x; acc[2][1] += a.z * d.y; acc[2][2] += a.z * d.z; acc[2][3] += a.z * d.w;
            acc[3][0] += a.w * d.x; acc[3][1] += a.w * d.y; acc[3][2] += a.w * d.z; acc[3][3] += a.w * d.w;
        }
        __syncthreads();
    }
    __nv_bfloat16* dst = g_rvwt + (size_t)b * HID * NS;
    #pragma unroll
    for (int i = 0; i < 4; i++)
        #pragma unroll
        for (int j = 0; j < 4; j++)
            dst[(size_t)(n0 + tx + j) * NS + ty + i] = __float2bfloat16(acc[i][j]);
}

// ---------------- per-row LN + gate + squared-error accumulation (bf16 input) ------
__global__ __launch_bounds__(256) void loss_ln_kernel(
    const float* __restrict__ seg, const float* __restrict__ lnw,
    const float* __restrict__ lnb, const float* __restrict__ gate_bias)
{
    __shared__ float red[256];
    __shared__ float gsh;
    int tid = threadIdx.x, rrow = blockIdx.x;
    const __nv_bfloat162* row = (const __nv_bfloat162*)(g_routb + (size_t)rrow * HID);

    float2 v[8];
    #pragma unroll
    for (int i = 0; i < 8; i++) {
        __nv_bfloat162 t = row[tid + (i << 8)];
        v[i] = make_float2(__bfloat162float(t.x), __bfloat162float(t.y));
    }

    if (tid == 0) {
        float sg = 0.f;
        for (int i = 0; i < 64; i++) sg += gate_bias[i];
        sg *= (1.0f / 64.0f);
        gsh = 1.0f / (1.0f + expf(-sg));
    }

    float sum = 0.f, sq = 0.f;
    #pragma unroll
    for (int i = 0; i < 8; i++) {
        sum += v[i].x + v[i].y;
        sq += v[i].x * v[i].x + v[i].y * v[i].y;
    }
    float tsum = block_reduce_sum256(sum, red);
    float tsq  = block_reduce_sum256(sq, red);
    float mu = tsum * (1.0f / HID);
    float var = tsq * (1.0f / HID) - mu * mu;
    float invs = rsqrtf(var + LN_EPS);
    float g = gsh;

    const float* segrow = seg + (size_t)rrow * HID;
    float acc = 0.f;
    #pragma unroll
    for (int i = 0; i < 8; i++) {
        int col = (tid + (i << 8)) * 2;
        float2 wv = *(const float2*)(lnw + col);
        float2 bv = *(const float2*)(lnb + col);
        float2 sv = *(const float2*)(segrow + col);
        float r0 = g * ((v[i].x - mu) * invs * wv.x + bv.x) - sv.x;
        float r1 = g * ((v[i].y - mu) * invs * wv.y + bv.y) - sv.y;
        acc += r0 * r0 + r1 * r1;
    }
    float bsum = block_reduce_sum256(acc, red);
    if (tid == 0) atomicAdd(&g_loss, (double)bsum);
}

__global__ void finalize_kernel(const float* __restrict__ gate_bias, float* __restrict__ outp)
{
    float sg = 0.f;
    for (int i = 0; i < 64; i++) sg += gate_bias[i];
    sg *= (1.0f / 64.0f);
    float g = 1.0f / (1.0f + expf(-sg));
    outp[NB * NS * HID]     = (float)(g_loss / (double)((size_t)NB * NT * HID));
    outp[NB * NS * HID + 1] = g;
}

// ---------------- launch ------------------------------------------------------------
extern "C" void kernel_launch(void* const* d_in, const int* in_sizes, int n_in,
                              void* d_out, int out_size)
{
    const float* seg      = (const float*)d_in[0];
    const float* slot_emb = (const float*)d_in[1];
    const float* Wq       = (const float*)d_in[2];
    const float* Wk       = (const float*)d_in[3];
    const float* Wv       = (const float*)d_in[4];
    const float* Wo       = (const float*)d_in[5];
    const float* Wrq      = (const float*)d_in[6];
    const float* Wro      = (const float*)d_in[7];
    const float* gateb    = (const float*)d_in[8];
    const float* snw      = (const float*)d_in[9];
    const float* snb      = (const float*)d_in[10];
    const float* rnw      = (const float*)d_in[11];
    const float* rnb      = (const float*)d_in[12];
    float* outp = (float*)d_out;

    float* kvr;      cudaGetSymbolAddress((void**)&kvr, g_kvr);
    float* qbuf;     cudaGetSymbolAddress((void**)&qbuf, g_q);
    float* out_sd;   cudaGetSymbolAddress((void**)&out_sd, g_out_sd);
    float* spre;     cudaGetSymbolAddress((void**)&spre, g_spre);
    float* rkv;      cudaGetSymbolAddress((void**)&rkv, g_rkv);
    __nv_bfloat16 *segh, *segl, *WTh, *WTl, *p2h, *rvwt, *routb;
    cudaGetSymbolAddress((void**)&segh, g_segh);
    cudaGetSymbolAddress((void**)&segl, g_segl);
    cudaGetSymbolAddress((void**)&WTh, g_WTh);
    cudaGetSymbolAddress((void**)&WTl, g_WTl);
    cudaGetSymbolAddress((void**)&p2h, g_p2h);
    cudaGetSymbolAddress((void**)&rvwt, g_rvwt);
    cudaGetSymbolAddress((void**)&routb, g_routb);

    const int SMEM3 = 3 * 65536;   // 192 KB, TERMS=3
    const int SMEM1 = 3 * 32768;   // 96 KB,  TERMS=1
    cudaFuncSetAttribute(hmma_gemm<3,0>, cudaFuncAttributeMaxDynamicSharedMemorySize, SMEM3);
    cudaFuncSetAttribute(hmma_gemm<1,0>, cudaFuncAttributeMaxDynamicSharedMemorySize, SMEM1);
    cudaFuncSetAttribute(hmma_gemm<1,1>, cudaFuncAttributeMaxDynamicSharedMemorySize, SMEM1);

    init_loss_kernel<<<1, 1>>>();
    cudaMemsetAsync(qbuf, 0, (size_t)NS * SD * sizeof(float));
    cudaMemsetAsync(out_sd, 0, (size_t)NB * NS * SD * sizeof(float));
    cudaMemsetAsync(rkv, 0, (size_t)NB * NS * 512 * sizeof(float));

    // bf16 splits: seg, transposed weights Wk|Wv|Wrq -> WT[768][4096]
    conv_hilo<<<(size_t)BT * HID / 1024, 256>>>(seg, segh, segl);
    transpose_conv<<<dim3(SD / 32, HID / 32), 256>>>(Wk,  WTh,             WTl,             HID, SD);
    transpose_conv<<<dim3(SD / 32, HID / 32), 256>>>(Wv,  WTh + 256 * HID, WTl + 256 * HID, HID, SD);
    transpose_conv<<<dim3(SD / 32, HID / 32), 256>>>(Wrq, WTh + 512 * HID, WTl + 512 * HID, HID, SD);

    // k | v = seg @ {Wk,Wv}  — 3-pass split (feeds updated_slots)
    hmma_gemm<3,0><<<dim3(4, BT / 128), 256, SMEM3>>>(segh, segl, WTh, WTl, kvr, 768, HID);
    // rq = seg @ Wrq — 1-pass bf16 (loss only)
    hmma_gemm<1,0><<<dim3(2, BT / 128), 256, SMEM1>>>(segh, segl, WTh + 512 * HID, WTl + 512 * HID, kvr + 512, 768, HID);

    // q = slot_embeddings @ Wq  (split-K fp32)
    gemm_small<<<dim3(1, 4, 8), 256>>>(slot_emb, HID, Wq, nullptr, qbuf, SD);

    // attn1
    scores1_kernel<<<dim3(64, NB), 256>>>();
    softmax1_kernel<<<NB * NS, 256>>>();
    pv1_kernel<<<dim3(4, 8, NB), 256>>>();

    // slots + out@Wo, LN -> updated_slots in d_out
    wo_gemm<<<dim3(4, 64), 256>>>(Wo, slot_emb);
    ln_rows_kernel<<<NB * NS, 256>>>(spre, snw, snb, outp);

    // rk | rv = updated_slots @ {Wk, Wv}
    gemm_small<<<dim3(4, 8, 8), 256>>>(outp, HID, Wk, Wv, rkv, 512);

    // attn2 scores + softmax (P2 -> bf16)
    scores2_kernel<<<dim3(64, NB), 256>>>();
    softmax2_kernel<<<BT / 8, 256>>>();

    // rvW^T = (rv @ Wro)^T per batch (bf16)
    rvw_gemm<<<dim3(HID / 64, NB), 256>>>(Wro);

    // rout = P2 @ rvW  (K=64, bf16 out) — per batch
    for (int b = 0; b < NB; b++)
        hmma_gemm<1,1><<<dim3(HID / 128, NT / 128), 256, SMEM1>>>(
            p2h + (size_t)b * NT * NS, nullptr,
            rvwt + (size_t)b * HID * NS, nullptr,
            routb + (size_t)b * NT * HID, HID, NS);

    // LN + gate + MSE
    loss_ln_kernel<<<BT, 256>>>(seg, rnw, rnb, gateb);
    finalize_kernel<<<1, 1>>>(gateb, outp);
}

// round 7
// speedup vs baseline: 4.9739x; 1.0189x over previous
#include <cuda_runtime.h>
#include <cuda_bf16.h>
#include <math.h>
#include <stdint.h>

#define HID 4096
#define SD 256
#define NS 64           // slots
#define NB 4            // batch
#define NT 4096         // tokens
#define BT (NB*NT)      // 16384
#define LN_EPS 1e-5f
#define ATT_SCALE 0.0625f  // 256^-0.5
#define KC 512          // split-K chunk for skinny GEMMs

// ---------------- scratch (static device globals; no runtime alloc) ----------------
__device__ float g_kvr[BT * 768];          // [b*T+t][ k(0:256) | v(256:512) | rq(512:768) ]
__device__ float g_q[NS * SD];             // slot queries (batch-independent)
__device__ float g_s1[NB * NS * NT];       // attn1 scores/probs [b][s][t]
__device__ float g_out_sd[NB * NS * SD];   // attn1 output before Wo
__device__ float g_spre[NB * NS * HID];    // slots + out@Wo, before LN
__device__ float g_rkv[NB * NS * 512];     // [b*S+s][ rk(0:256) | rv(256:512) ]
__device__ float g_s2[NB * NT * NS];       // attn2 scores [b][t][s]
__device__ __nv_bfloat16 g_p2h[NB * NT * NS];      // attn2 probs bf16 [b*T+t][s]
__device__ __nv_bfloat16 g_rvwt[NB * HID * NS];    // (rv@Wro)^T per batch: [b][n][s]
__device__ __nv_bfloat16 g_routb[(size_t)BT * HID];// rout before LN, bf16 (128 MB)
__device__ double g_loss;

// bf16 split operands for tensor-core GEMMs
__device__ __nv_bfloat16 g_segh[(size_t)BT * HID];   // seg hi
__device__ __nv_bfloat16 g_segl[(size_t)BT * HID];   // seg lo
__device__ __nv_bfloat16 g_WTh[768 * HID];           // [Wk|Wv|Wrq]^T  [768][4096]
__device__ __nv_bfloat16 g_WTl[768 * HID];

// ================= ptx helpers (sm_80-era: valid on base sm_103 target) =================
__device__ __forceinline__ uint32_t s2u(const void* p) {
    uint32_t a;
    asm("{ .reg .u64 t; cvta.to.shared.u64 t, %1; cvt.u32.u64 %0, t; }" : "=r"(a) : "l"(p));
    return a;
}
__device__ __forceinline__ void cpa16(uint32_t dst, const void* src) {
    asm volatile("cp.async.cg.shared.global [%0], [%1], 16;" :: "r"(dst), "l"(src) : "memory");
}
__device__ __forceinline__ void ldsm_x4(uint32_t* r, uint32_t addr) {
    asm volatile("ldmatrix.sync.aligned.m8n8.x4.shared.b16 {%0,%1,%2,%3}, [%4];"
        : "=r"(r[0]), "=r"(r[1]), "=r"(r[2]), "=r"(r[3]) : "r"(addr));
}
__device__ __forceinline__ void mma16816(float* d, const uint32_t* a, const uint32_t* b) {
    asm volatile("mma.sync.aligned.m16n8k16.row.col.f32.bf16.bf16.f32 "
        "{%0,%1,%2,%3}, {%4,%5,%6,%7}, {%8,%9}, {%0,%1,%2,%3};"
        : "+f"(d[0]), "+f"(d[1]), "+f"(d[2]), "+f"(d[3])
        : "r"(a[0]), "r"(a[1]), "r"(a[2]), "r"(a[3]), "r"(b[0]), "r"(b[1]));
}
__device__ __forceinline__ uint32_t sw128(uint32_t off) { return off ^ ((off >> 3) & 0x70); }

// ===================================================================================
// HMMA split-bf16 GEMM.
//   TERMS==3: C = Ah@Bh^T + Ah@Bl^T + Al@Bh^T   TERMS==1: C = Ah@Bh^T
//   OUTBF16:  C written as bf16 (packed bf16x2) instead of fp32.
// A*: [Mtot][K] K-major bf16.  B*: [Ntot][K] K-major bf16.
// Block tile 128x128, K-chunk 64, 8 warps (64x32 each), 3-stage cp.async pipeline.
// grid (Ntot/128, Mtot/128, nbatch); per-batch strides sA/sB/sC (elements).
// ===================================================================================
template<int TERMS, int OUTBF16>
__global__ void __launch_bounds__(256, 1) hmma_gemm(
    const __nv_bfloat16* __restrict__ Ah, const __nv_bfloat16* __restrict__ Al,
    const __nv_bfloat16* __restrict__ Bh, const __nv_bfloat16* __restrict__ Bl,
    void* __restrict__ Cv, int ldc, int K, size_t sA, size_t sB, size_t sC)
{
    constexpr uint32_t STAGE = (TERMS == 3) ? 65536u : 32768u;
    constexpr uint32_t AL_OFF = 16384u;
    constexpr uint32_t BH_OFF = (TERMS == 3) ? 32768u : 16384u;
    constexpr uint32_t BL_OFF = 49152u;
    extern __shared__ char smem[];
    uint32_t sb = s2u(smem);
    int tid = threadIdx.x, wid = tid >> 5, lane = tid & 31;
    int n0 = blockIdx.x << 7, m0 = blockIdx.y << 7;
    int bz = blockIdx.z;
    Ah += (size_t)bz * sA;
    if (TERMS == 3) Al += (size_t)bz * sA;
    Bh += (size_t)bz * sB;
    if (TERMS == 3) Bl += (size_t)bz * sB;
    const int nch = K >> 6;
    int wm = (wid & 1) << 6;
    int wn = (wid >> 1) << 5;

    #define LOAD_CHUNK(s, c) do { \
        uint32_t base = sb + (uint32_t)(s) * STAGE; \
        int k0 = (c) << 6; \
        _Pragma("unroll") \
        for (int i = 0; i < 4; i++) { \
            int u = tid + (i << 8); \
            int row = u >> 3, cu = u & 7; \
            uint32_t sw = sw128((uint32_t)u << 4); \
            size_t ao = (size_t)(m0 + row) * K + k0 + (cu << 3); \
            size_t bo = (size_t)(n0 + row) * K + k0 + (cu << 3); \
            cpa16(base + sw,          Ah + ao); \
            cpa16(base + BH_OFF + sw, Bh + bo); \
            if (TERMS == 3) { \
                cpa16(base + AL_OFF + sw, Al + ao); \
                cpa16(base + BL_OFF + sw, Bl + bo); \
            } \
        } \
        asm volatile("cp.async.commit_group;" ::: "memory"); \
    } while (0)

    float acc[4][4][4] = {};

    LOAD_CHUNK(0, 0);
    if (nch > 1) LOAD_CHUNK(1, 1);

    for (int c = 0; c < nch; c++) {
        if (c + 2 < nch) {
            LOAD_CHUNK((c + 2) % 3, c + 2);
            asm volatile("cp.async.wait_group 2;" ::: "memory");
        } else if (c + 1 < nch) {
            asm volatile("cp.async.wait_group 1;" ::: "memory");
        } else {
            asm volatile("cp.async.wait_group 0;" ::: "memory");
        }
        __syncthreads();

        uint32_t base = sb + (uint32_t)(c % 3) * STAGE;
        #pragma unroll
        for (int ks = 0; ks < 4; ks++) {
            uint32_t ah[4][4], al[4][4], bh[4][2], bl[4][2];
            uint32_t acb = (uint32_t)((ks << 4) + ((lane >> 4) << 3)) << 1;
            #pragma unroll
            for (int mi = 0; mi < 4; mi++) {
                uint32_t r = (uint32_t)(wm + (mi << 4) + (lane & 15));
                uint32_t sw = sw128((r << 7) + acb);
                ldsm_x4(ah[mi], base + sw);
                if (TERMS == 3) ldsm_x4(al[mi], base + AL_OFF + sw);
            }
            // B: one ldsm_x4 fills two n8k16 fragments:
            // matrix0=(n,k0-7) lanes0-7, matrix1=(n,k8-15) lanes8-15,
            // matrix2=(n+8,k0-7) lanes16-23, matrix3=(n+8,k8-15) lanes24-31
            uint32_t bcb = (uint32_t)((ks << 4) + (((lane >> 3) & 1) << 3)) << 1;
            #pragma unroll
            for (int ni = 0; ni < 4; ni += 2) {
                uint32_t r = (uint32_t)(wn + (ni << 3) + ((lane >> 4) << 3) + (lane & 7));
                uint32_t sw = sw128((r << 7) + bcb);
                uint32_t t4[4];
                ldsm_x4(t4, base + BH_OFF + sw);
                bh[ni][0] = t4[0]; bh[ni][1] = t4[1];
                bh[ni + 1][0] = t4[2]; bh[ni + 1][1] = t4[3];
                if (TERMS == 3) {
                    ldsm_x4(t4, base + BL_OFF + sw);
                    bl[ni][0] = t4[0]; bl[ni][1] = t4[1];
                    bl[ni + 1][0] = t4[2]; bl[ni + 1][1] = t4[3];
                }
            }
            #pragma unroll
            for (int mi = 0; mi < 4; mi++)
                #pragma unroll
                for (int ni = 0; ni < 4; ni++) {
                    mma16816(acc[mi][ni], ah[mi], bh[ni]);
                    if (TERMS == 3) {
                        mma16816(acc[mi][ni], ah[mi], bl[ni]);
                        mma16816(acc[mi][ni], al[mi], bh[ni]);
                    }
                }
        }
        __syncthreads();
    }

    int rbase = m0 + wm + (lane >> 2);
    int cbase = n0 + wn + ((lane & 3) << 1);
    #pragma unroll
    for (int mi = 0; mi < 4; mi++)
        #pragma unroll
        for (int ni = 0; ni < 4; ni++) {
            int row = rbase + (mi << 4);
            int col = cbase + (ni << 3);
            if (OUTBF16) {
                __nv_bfloat16* C = (__nv_bfloat16*)Cv + (size_t)bz * sC;
                *(__nv_bfloat162*)(C + (size_t)row * ldc + col) =
                    __nv_bfloat162(__float2bfloat16(acc[mi][ni][0]), __float2bfloat16(acc[mi][ni][1]));
                *(__nv_bfloat162*)(C + (size_t)(row + 8) * ldc + col) =
                    __nv_bfloat162(__float2bfloat16(acc[mi][ni][2]), __float2bfloat16(acc[mi][ni][3]));
            } else {
                float* C = (float*)Cv + (size_t)bz * sC;
                *(float2*)(C + (size_t)row * ldc + col)       = make_float2(acc[mi][ni][0], acc[mi][ni][1]);
                *(float2*)(C + (size_t)(row + 8) * ldc + col) = make_float2(acc[mi][ni][2], acc[mi][ni][3]);
            }
        }
    #undef LOAD_CHUNK
}

// ---------------- fp32 -> (hi, lo) bf16 split, elementwise ----------------
__global__ void __launch_bounds__(256) conv_hilo(
    const float* __restrict__ src, __nv_bfloat16* __restrict__ h, __nv_bfloat16* __restrict__ l)
{
    size_t i = ((size_t)blockIdx.x * 256 + threadIdx.x) * 4;
    float4 v = *(const float4*)(src + i);
    __nv_bfloat16 h0 = __float2bfloat16(v.x), h1 = __float2bfloat16(v.y);
    __nv_bfloat16 h2 = __float2bfloat16(v.z), h3 = __float2bfloat16(v.w);
    __nv_bfloat16 l0 = __float2bfloat16(v.x - __bfloat162float(h0));
    __nv_bfloat16 l1 = __float2bfloat16(v.y - __bfloat162float(h1));
    __nv_bfloat16 l2 = __float2bfloat16(v.z - __bfloat162float(h2));
    __nv_bfloat16 l3 = __float2bfloat16(v.w - __bfloat162float(h3));
    *(__nv_bfloat162*)(h + i)     = __nv_bfloat162(h0, h1);
    *(__nv_bfloat162*)(h + i + 2) = __nv_bfloat162(h2, h3);
    *(__nv_bfloat162*)(l + i)     = __nv_bfloat162(l0, l1);
    *(__nv_bfloat162*)(l + i + 2) = __nv_bfloat162(l2, l3);
}

// ---------------- transpose + split: W[K][N] fp32 -> dst[N][K] bf16 hi/lo ----------
__global__ void __launch_bounds__(256) transpose_conv(
    const float* __restrict__ W, __nv_bfloat16* __restrict__ dh,
    __nv_bfloat16* __restrict__ dl, int K, int N)
{
    __shared__ float t[32][33];
    int n0 = blockIdx.x << 5, k0 = blockIdx.y << 5;
    int tx = threadIdx.x & 31, ty = threadIdx.x >> 5;
    #pragma unroll
    for (int i = 0; i < 32; i += 8)
        t[ty + i][tx] = W[(size_t)(k0 + ty + i) * N + n0 + tx];
    __syncthreads();
    #pragma unroll
    for (int i = 0; i < 32; i += 8) {
        float x = t[tx][ty + i];
        int n = n0 + ty + i, k = k0 + tx;
        __nv_bfloat16 hh = __float2bfloat16(x);
        dh[(size_t)n * K + k] = hh;
        dl[(size_t)n * K + k] = __float2bfloat16(x - __bfloat162float(hh));
    }
}

// ---------------- helpers ----------------
__device__ __forceinline__ float block_reduce_sum256(float v, float* red) {
    int tid = threadIdx.x;
    red[tid] = v; __syncthreads();
    #pragma unroll
    for (int o = 128; o > 0; o >>= 1) {
        if (tid < o) red[tid] += red[tid + o];
        __syncthreads();
    }
    float r = red[0];
    __syncthreads();
    return r;
}

__global__ void init_loss_kernel() { g_loss = 0.0; }

// ===================================================================================
// Skinny split-K GEMM: 64x64 tile over a K-chunk of KC, atomicAdd into pre-zeroed C.
// ===================================================================================
__global__ __launch_bounds__(256) void gemm_small(
    const float* __restrict__ A, int lda,
    const float* __restrict__ W0, const float* __restrict__ W1,
    float* __restrict__ C, int ldc)
{
    __shared__ float As[16][64];
    __shared__ float Bs[16][64];
    int tid = threadIdx.x;
    int m0 = blockIdx.x << 6;
    int n0 = blockIdx.y << 6;
    int kbase = blockIdx.z * KC;
    const float* W = (n0 >> 8) ? W1 : W0;
    int col0 = n0 & 255;

    int r = tid >> 2, c = (tid & 3) << 2;
    int br = tid >> 4, bc = (tid & 15) << 2;
    int tx = (tid & 15) << 2, ty = (tid >> 4) << 2;

    float acc[4][4] = {};
    for (int k0 = kbase; k0 < kbase + KC; k0 += 16) {
        float4 av = *(const float4*)(A + (size_t)(m0 + r) * lda + k0 + c);
        As[c + 0][r] = av.x; As[c + 1][r] = av.y; As[c + 2][r] = av.z; As[c + 3][r] = av.w;
        *(float4*)&Bs[br][bc] = *(const float4*)(W + (size_t)(k0 + br) * 256 + col0 + bc);
        __syncthreads();
        #pragma unroll
        for (int kk = 0; kk < 16; kk++) {
            float4 a = *(const float4*)&As[kk][ty];
            float4 b = *(const float4*)&Bs[kk][tx];
            acc[0][0] += a.x * b.x; acc[0][1] += a.x * b.y; acc[0][2] += a.x * b.z; acc[0][3] += a.x * b.w;
            acc[1][0] += a.y * b.x; acc[1][1] += a.y * b.y; acc[1][2] += a.y * b.z; acc[1][3] += a.y * b.w;
            acc[2][0] += a.z * b.x; acc[2][1] += a.z * b.y; acc[2][2] += a.z * b.z; acc[2][3] += a.z * b.w;
            acc[3][0] += a.w * b.x; acc[3][1] += a.w * b.y; acc[3][2] += a.w * b.z; acc[3][3] += a.w * b.w;
        }
        __syncthreads();
    }
    #pragma unroll
    for (int i = 0; i < 4; i++)
        #pragma unroll
        for (int j = 0; j < 4; j++)
            atomicAdd(C + (size_t)(m0 + ty + i) * ldc + n0 + tx + j, acc[i][j]);
}

// ---------------- attn1 scores ----------------
__global__ __launch_bounds__(256) void scores1_kernel()
{
    __shared__ float Qs[16][64];
    __shared__ float Ks[16][64];
    int tid = threadIdx.x;
    int t0 = blockIdx.x << 6;
    int b = blockIdx.y;
    int r = tid >> 2, c = (tid & 3) << 2;
    int tx = (tid & 15) << 2, ty = (tid >> 4) << 2;

    float acc[4][4] = {};
    for (int k0 = 0; k0 < SD; k0 += 16) {
        float4 qv = *(const float4*)(g_q + (size_t)r * SD + k0 + c);
        Qs[c + 0][r] = qv.x; Qs[c + 1][r] = qv.y; Qs[c + 2][r] = qv.z; Qs[c + 3][r] = qv.w;
        float4 kv = *(const float4*)(g_kvr + (size_t)(b * NT + t0 + r) * 768 + k0 + c);
        Ks[c + 0][r] = kv.x; Ks[c + 1][r] = kv.y; Ks[c + 2][r] = kv.z; Ks[c + 3][r] = kv.w;
        __syncthreads();
        #pragma unroll
        for (int kk = 0; kk < 16; kk++) {
            float4 a = *(const float4*)&Qs[kk][ty];
            float4 d = *(const float4*)&Ks[kk][tx];
            acc[0][0] += a.x * d.x; acc[0][1] += a.x * d.y; acc[0][2] += a.x * d.z; acc[0][3] += a.x * d.w;
            acc[1][0] += a.y * d.x; acc[1][1] += a.y * d.y; acc[1][2] += a.y * d.z; acc[1][3] += a.y * d.w;
            acc[2][0] += a.z * d.x; acc[2][1] += a.z * d.y; acc[2][2] += a.z * d.z; acc[2][3] += a.z * d.w;
            acc[3][0] += a.w * d.x; acc[3][1] += a.w * d.y; acc[3][2] += a.w * d.z; acc[3][3] += a.w * d.w;
        }
        __syncthreads();
    }
    #pragma unroll
    for (int i = 0; i < 4; i++)
        #pragma unroll
        for (int j = 0; j < 4; j++)
            g_s1[((size_t)b * NS + ty + i) * NT + t0 + tx + j] = acc[i][j] * ATT_SCALE;
}

__global__ __launch_bounds__(256) void softmax1_kernel()
{
    __shared__ float red[256];
    int tid = threadIdx.x;
    float* row = g_s1 + (size_t)blockIdx.x * NT;

    float m = -1e30f;
    for (int t = tid; t < NT; t += 256) m = fmaxf(m, row[t]);
    red[tid] = m; __syncthreads();
    #pragma unroll
    for (int o = 128; o > 0; o >>= 1) { if (tid < o) red[tid] = fmaxf(red[tid], red[tid + o]); __syncthreads(); }
    m = red[0]; __syncthreads();

    float sum = 0.f;
    for (int t = tid; t < NT; t += 256) { float e = expf(row[t] - m); row[t] = e; sum += e; }
    float tot = block_reduce_sum256(sum, red);
    float inv = 1.0f / tot;
    for (int t = tid; t < NT; t += 256) row[t] *= inv;
}

__global__ __launch_bounds__(256) void pv1_kernel()
{
    __shared__ float As[16][64];
    __shared__ float Bs[16][64];
    int tid = threadIdx.x;
    int n0 = blockIdx.x << 6;
    int kbase = blockIdx.y * KC;
    int b = blockIdx.z;
    int r = tid >> 2, c = (tid & 3) << 2;
    int br = tid >> 4, bc = (tid & 15) << 2;
    int tx = (tid & 15) << 2, ty = (tid >> 4) << 2;

    float acc[4][4] = {};
    for (int k0 = kbase; k0 < kbase + KC; k0 += 16) {
        float4 av = *(const float4*)(g_s1 + ((size_t)b * NS + r) * NT + k0 + c);
        As[c + 0][r] = av.x; As[c + 1][r] = av.y; As[c + 2][r] = av.z; As[c + 3][r] = av.w;
        *(float4*)&Bs[br][bc] = *(const float4*)(g_kvr + (size_t)(b * NT + k0 + br) * 768 + 256 + n0 + bc);
        __syncthreads();
        #pragma unroll
        for (int kk = 0; kk < 16; kk++) {
            float4 a = *(const float4*)&As[kk][ty];
            float4 d = *(const float4*)&Bs[kk][tx];
            acc[0][0] += a.x * d.x; acc[0][1] += a.x * d.y; acc[0][2] += a.x * d.z; acc[0][3] += a.x * d.w;
            acc[1][0] += a.y * d.x; acc[1][1] += a.y * d.y; acc[1][2] += a.y * d.z; acc[1][3] += a.y * d.w;
            acc[2][0] += a.z * d.x; acc[2][1] += a.z * d.y; acc[2][2] += a.z * d.z; acc[2][3] += a.z * d.w;
            acc[3][0] += a.w * d.x; acc[3][1] += a.w * d.y; acc[3][2] += a.w * d.z; acc[3][3] += a.w * d.w;
        }
        __syncthreads();
    }
    #pragma unroll
    for (int i = 0; i < 4; i++)
        #pragma unroll
        for (int j = 0; j < 4; j++)
            atomicAdd(g_out_sd + ((size_t)b * NS + ty + i) * SD + n0 + tx + j, acc[i][j]);
}

__global__ __launch_bounds__(256) void wo_gemm(
    const float* __restrict__ Wo, const float* __restrict__ slot_emb)
{
    __shared__ float As[16][64];
    __shared__ float Bs[16][64];
    int tid = threadIdx.x;
    int m0 = blockIdx.x << 6;
    int n0 = blockIdx.y << 6;
    int r = tid >> 2, c = (tid & 3) << 2;
    int br = tid >> 4, bc = (tid & 15) << 2;
    int tx = (tid & 15) << 2, ty = (tid >> 4) << 2;

    float acc[4][4] = {};
    for (int k0 = 0; k0 < SD; k0 += 16) {
        float4 av = *(const float4*)(g_out_sd + (size_t)(m0 + r) * SD + k0 + c);
        As[c + 0][r] = av.x; As[c + 1][r] = av.y; As[c + 2][r] = av.z; As[c + 3][r] = av.w;
        *(float4*)&Bs[br][bc] = *(const float4*)(Wo + (size_t)(k0 + br) * HID + n0 + bc);
        __syncthreads();
        #pragma unroll
        for (int kk = 0; kk < 16; kk++) {
            float4 a = *(const float4*)&As[kk][ty];
            float4 d = *(const float4*)&Bs[kk][tx];
            acc[0][0] += a.x * d.x; acc[0][1] += a.x * d.y; acc[0][2] += a.x * d.z; acc[0][3] += a.x * d.w;
            acc[1][0] += a.y * d.x; acc[1][1] += a.y * d.y; acc[1][2] += a.y * d.z; acc[1][3] += a.y * d.w;
            acc[2][0] += a.z * d.x; acc[2][1] += a.z * d.y; acc[2][2] += a.z * d.z; acc[2][3] += a.z * d.w;
            acc[3][0] += a.w * d.x; acc[3][1] += a.w * d.y; acc[3][2] += a.w * d.z; acc[3][3] += a.w * d.w;
        }
        __syncthreads();
    }
    #pragma unroll
    for (int i = 0; i < 4; i++) {
        int row = m0 + ty + i;
        int s = row & 63;
        #pragma unroll
        for (int j = 0; j < 4; j++) {
            int col = n0 + tx + j;
            g_spre[(size_t)row * HID + col] = acc[i][j] + slot_emb[(size_t)s * HID + col];
        }
    }
}

__global__ __launch_bounds__(256) void ln_rows_kernel(
    const float* __restrict__ src, const float* __restrict__ w,
    const float* __restrict__ bb, float* __restrict__ dst)
{
    __shared__ float red[256];
    int tid = threadIdx.x, rrow = blockIdx.x;
    const float* row = src + (size_t)rrow * HID;

    float v[16];
    #pragma unroll
    for (int i = 0; i < 16; i++) v[i] = row[tid + (i << 8)];
    float sum = 0.f, sq = 0.f;
    #pragma unroll
    for (int i = 0; i < 16; i++) { sum += v[i]; sq += v[i] * v[i]; }
    float tsum = block_reduce_sum256(sum, red);
    float tsq  = block_reduce_sum256(sq, red);
    float mu = tsum * (1.0f / HID);
    float var = tsq * (1.0f / HID) - mu * mu;
    float invs = rsqrtf(var + LN_EPS);
    #pragma unroll
    for (int i = 0; i < 16; i++) {
        int col = tid + (i << 8);
        dst[(size_t)rrow * HID + col] = (v[i] - mu) * invs * w[col] + bb[col];
    }
}

__global__ __launch_bounds__(256) void scores2_kernel()
{
    __shared__ float As[16][64];
    __shared__ float Bs[16][64];
    int tid = threadIdx.x;
    int t0 = blockIdx.x << 6;
    int b = blockIdx.y;
    int r = tid >> 2, c = (tid & 3) << 2;
    int tx = (tid & 15) << 2, ty = (tid >> 4) << 2;

    float acc[4][4] = {};
    for (int k0 = 0; k0 < SD; k0 += 16) {
        float4 av = *(const float4*)(g_kvr + (size_t)(b * NT + t0 + r) * 768 + 512 + k0 + c);
        As[c + 0][r] = av.x; As[c + 1][r] = av.y; As[c + 2][r] = av.z; As[c + 3][r] = av.w;
        float4 kv = *(const float4*)(g_rkv + (size_t)(b * NS + r) * 512 + k0 + c);
        Bs[c + 0][r] = kv.x; Bs[c + 1][r] = kv.y; Bs[c + 2][r] = kv.z; Bs[c + 3][r] = kv.w;
        __syncthreads();
        #pragma unroll
        for (int kk = 0; kk < 16; kk++) {
            float4 a = *(const float4*)&As[kk][ty];
            float4 d = *(const float4*)&Bs[kk][tx];
            acc[0][0] += a.x * d.x; acc[0][1] += a.x * d.y; acc[0][2] += a.x * d.z; acc[0][3] += a.x * d.w;
            acc[1][0] += a.y * d.x; acc[1][1] += a.y * d.y; acc[1][2] += a.y * d.z; acc[1][3] += a.y * d.w;
            acc[2][0] += a.z * d.x; acc[2][1] += a.z * d.y; acc[2][2] += a.z * d.z; acc[2][3] += a.z * d.w;
            acc[3][0] += a.w * d.x; acc[3][1] += a.w * d.y; acc[3][2] += a.w * d.z; acc[3][3] += a.w * d.w;
        }
        __syncthreads();
    }
    #pragma unroll
    for (int i = 0; i < 4; i++)
        #pragma unroll
        for (int j = 0; j < 4; j++)
            g_s2[((size_t)b * NT + t0 + ty + i) * NS + tx + j] = acc[i][j] * ATT_SCALE;
}

// softmax over s (64) per (b,t) row; writes NORMALIZED probs as bf16 to g_p2h
__global__ __launch_bounds__(256) void softmax2_kernel()
{
    int tid = threadIdx.x;
    int row = (blockIdx.x << 3) + (tid >> 5);
    int lane = tid & 31;
    const float* p = g_s2 + (size_t)row * NS;
    float v0 = p[lane], v1 = p[lane + 32];
    float m = fmaxf(v0, v1);
    #pragma unroll
    for (int o = 16; o > 0; o >>= 1) m = fmaxf(m, __shfl_xor_sync(0xffffffffu, m, o));
    float e0 = expf(v0 - m), e1 = expf(v1 - m);
    float s = e0 + e1;
    #pragma unroll
    for (int o = 16; o > 0; o >>= 1) s += __shfl_xor_sync(0xffffffffu, s, o);
    float inv = 1.0f / s;
    g_p2h[(size_t)row * NS + lane]      = __float2bfloat16(e0 * inv);
    g_p2h[(size_t)row * NS + lane + 32] = __float2bfloat16(e1 * inv);
}

// rvWT[b][n][s] = sum_k rv[b][s][k] * Wro[k][n], written transposed as bf16.
__global__ __launch_bounds__(256) void rvw_gemm(const float* __restrict__ Wro)
{
    __shared__ float As[16][64];
    __shared__ float Bs[16][64];
    int tid = threadIdx.x;
    int n0 = blockIdx.x << 6;
    int b = blockIdx.y;
    int r = tid >> 2, c = (tid & 3) << 2;
    int br = tid >> 4, bc = (tid & 15) << 2;
    int tx = (tid & 15) << 2, ty = (tid >> 4) << 2;

    float acc[4][4] = {};
    for (int k0 = 0; k0 < SD; k0 += 16) {
        float4 av = *(const float4*)(g_rkv + (size_t)(b * NS + r) * 512 + 256 + k0 + c);
        As[c + 0][r] = av.x; As[c + 1][r] = av.y; As[c + 2][r] = av.z; As[c + 3][r] = av.w;
        *(float4*)&Bs[br][bc] = *(const float4*)(Wro + (size_t)(k0 + br) * HID + n0 + bc);
        __syncthreads();
        #pragma unroll
        for (int kk = 0; kk < 16; kk++) {
            float4 a = *(const float4*)&As[kk][ty];
            float4 d = *(const float4*)&Bs[kk][tx];
            acc[0][0] += a.x * d.x; acc[0][1] += a.x * d.y; acc[0][2] += a.x * d.z; acc[0][3] += a.x * d.w;
            acc[1][0] += a.y * d.x; acc[1][1] += a.y * d.y; acc[1][2] += a.y * d.z; acc[1][3] += a.y * d.w;
            acc[2][0] += a.z * d.x; acc[2][1] += a.z * d.y; acc[2][2] += a.z * d.z; acc[2][3] += a.z * d.w;
            acc[3][0] += a.w * d.x; acc[3][1] += a.w * d.y; acc[3][2] += a.w * d.z; acc[3][3] += a.w * d.w;
        }
        __syncthreads();
    }
    __nv_bfloat16* dst = g_rvwt + (size_t)b * HID * NS;
    #pragma unroll
    for (int i = 0; i < 4; i++)
        #pragma unroll
        for (int j = 0; j < 4; j++)
            dst[(size_t)(n0 + tx + j) * NS + ty + i] = __float2bfloat16(acc[i][j]);
}

// ---------------- per-row LN + gate + squared-error accumulation (bf16 inputs) ------
__global__ __launch_bounds__(256) void loss_ln_kernel(
    const float* __restrict__ lnw, const float* __restrict__ lnb,
    const float* __restrict__ gate_bias)
{
    __shared__ float red[256];
    __shared__ float gsh;
    int tid = threadIdx.x, rrow = blockIdx.x;
    const __nv_bfloat162* row = (const __nv_bfloat162*)(g_routb + (size_t)rrow * HID);

    float2 v[8];
    #pragma unroll
    for (int i = 0; i < 8; i++) {
        __nv_bfloat162 t = row[tid + (i << 8)];
        v[i] = make_float2(__bfloat162float(t.x), __bfloat162float(t.y));
    }

    if (tid == 0) {
        float sg = 0.f;
        for (int i = 0; i < 64; i++) sg += gate_bias[i];
        sg *= (1.0f / 64.0f);
        gsh = 1.0f / (1.0f + expf(-sg));
    }

    float sum = 0.f, sq = 0.f;
    #pragma unroll
    for (int i = 0; i < 8; i++) {
        sum += v[i].x + v[i].y;
        sq += v[i].x * v[i].x + v[i].y * v[i].y;
    }
    float tsum = block_reduce_sum256(sum, red);
    float tsq  = block_reduce_sum256(sq, red);
    float mu = tsum * (1.0f / HID);
    float var = tsq * (1.0f / HID) - mu * mu;
    float invs = rsqrtf(var + LN_EPS);
    float g = gsh;

    const __nv_bfloat162* segrow = (const __nv_bfloat162*)(g_segh + (size_t)rrow * HID);
    float acc = 0.f;
    #pragma unroll
    for (int i = 0; i < 8; i++) {
        int col = (tid + (i << 8)) * 2;
        float2 wv = *(const float2*)(lnw + col);
        float2 bv = *(const float2*)(lnb + col);
        __nv_bfloat162 st = segrow[tid + (i << 8)];
        float r0 = g * ((v[i].x - mu) * invs * wv.x + bv.x) - __bfloat162float(st.x);
        float r1 = g * ((v[i].y - mu) * invs * wv.y + bv.y) - __bfloat162float(st.y);
        acc += r0 * r0 + r1 * r1;
    }
    float bsum = block_reduce_sum256(acc, red);
    if (tid == 0) atomicAdd(&g_loss, (double)bsum);
}

__global__ void finalize_kernel(const float* __restrict__ gate_bias, float* __restrict__ outp)
{
    float sg = 0.f;
    for (int i = 0; i < 64; i++) sg += gate_bias[i];
    sg *= (1.0f / 64.0f);
    float g = 1.0f / (1.0f + expf(-sg));
    outp[NB * NS * HID]     = (float)(g_loss / (double)((size_t)NB * NT * HID));
    outp[NB * NS * HID + 1] = g;
}

// ---------------- launch ------------------------------------------------------------
extern "C" void kernel_launch(void* const* d_in, const int* in_sizes, int n_in,
                              void* d_out, int out_size)
{
    const float* seg      = (const float*)d_in[0];
    const float* slot_emb = (const float*)d_in[1];
    const float* Wq       = (const float*)d_in[2];
    const float* Wk       = (const float*)d_in[3];
    const float* Wv       = (const float*)d_in[4];
    const float* Wo       = (const float*)d_in[5];
    const float* Wrq      = (const float*)d_in[6];
    const float* Wro      = (const float*)d_in[7];
    const float* gateb    = (const float*)d_in[8];
    const float* snw      = (const float*)d_in[9];
    const float* snb      = (const float*)d_in[10];
    const float* rnw      = (const float*)d_in[11];
    const float* rnb      = (const float*)d_in[12];
    float* outp = (float*)d_out;

    float* kvr;      cudaGetSymbolAddress((void**)&kvr, g_kvr);
    float* qbuf;     cudaGetSymbolAddress((void**)&qbuf, g_q);
    float* out_sd;   cudaGetSymbolAddress((void**)&out_sd, g_out_sd);
    float* spre;     cudaGetSymbolAddress((void**)&spre, g_spre);
    float* rkv;      cudaGetSymbolAddress((void**)&rkv, g_rkv);
    __nv_bfloat16 *segh, *segl, *WTh, *WTl, *p2h, *rvwt, *routb;
    cudaGetSymbolAddress((void**)&segh, g_segh);
    cudaGetSymbolAddress((void**)&segl, g_segl);
    cudaGetSymbolAddress((void**)&WTh, g_WTh);
    cudaGetSymbolAddress((void**)&WTl, g_WTl);
    cudaGetSymbolAddress((void**)&p2h, g_p2h);
    cudaGetSymbolAddress((void**)&rvwt, g_rvwt);
    cudaGetSymbolAddress((void**)&routb, g_routb);

    const int SMEM3 = 3 * 65536;   // 192 KB, TERMS=3
    const int SMEM1 = 3 * 32768;   // 96 KB,  TERMS=1
    cudaFuncSetAttribute(hmma_gemm<3,0>, cudaFuncAttributeMaxDynamicSharedMemorySize, SMEM3);
    cudaFuncSetAttribute(hmma_gemm<1,0>, cudaFuncAttributeMaxDynamicSharedMemorySize, SMEM1);
    cudaFuncSetAttribute(hmma_gemm<1,1>, cudaFuncAttributeMaxDynamicSharedMemorySize, SMEM1);

    init_loss_kernel<<<1, 1>>>();
    cudaMemsetAsync(qbuf, 0, (size_t)NS * SD * sizeof(float));
    cudaMemsetAsync(out_sd, 0, (size_t)NB * NS * SD * sizeof(float));
    cudaMemsetAsync(rkv, 0, (size_t)NB * NS * 512 * sizeof(float));

    // bf16 splits: seg, transposed weights Wk|Wv|Wrq -> WT[768][4096]
    conv_hilo<<<(size_t)BT * HID / 1024, 256>>>(seg, segh, segl);
    transpose_conv<<<dim3(SD / 32, HID / 32), 256>>>(Wk,  WTh,             WTl,             HID, SD);
    transpose_conv<<<dim3(SD / 32, HID / 32), 256>>>(Wv,  WTh + 256 * HID, WTl + 256 * HID, HID, SD);
    transpose_conv<<<dim3(SD / 32, HID / 32), 256>>>(Wrq, WTh + 512 * HID, WTl + 512 * HID, HID, SD);

    // k | v = seg @ {Wk,Wv}  — 3-pass split (feeds updated_slots)
    hmma_gemm<3,0><<<dim3(4, BT / 128), 256, SMEM3>>>(segh, segl, WTh, WTl, kvr, 768, HID, 0, 0, 0);
    // rq = seg @ Wrq — 1-pass bf16 (loss only)
    hmma_gemm<1,0><<<dim3(2, BT / 128), 256, SMEM1>>>(segh, segl, WTh + 512 * HID, WTl + 512 * HID, kvr + 512, 768, HID, 0, 0, 0);

    // q = slot_embeddings @ Wq  (split-K fp32)
    gemm_small<<<dim3(1, 4, 8), 256>>>(slot_emb, HID, Wq, nullptr, qbuf, SD);

    // attn1
    scores1_kernel<<<dim3(64, NB), 256>>>();
    softmax1_kernel<<<NB * NS, 256>>>();
    pv1_kernel<<<dim3(4, 8, NB), 256>>>();

    // slots + out@Wo, LN -> updated_slots in d_out
    wo_gemm<<<dim3(4, 64), 256>>>(Wo, slot_emb);
    ln_rows_kernel<<<NB * NS, 256>>>(spre, snw, snb, outp);

    // rk | rv = updated_slots @ {Wk, Wv}
    gemm_small<<<dim3(4, 8, 8), 256>>>(outp, HID, Wk, Wv, rkv, 512);

    // attn2 scores + softmax (P2 -> bf16)
    scores2_kernel<<<dim3(64, NB), 256>>>();
    softmax2_kernel<<<BT / 8, 256>>>();

    // rvW^T = (rv @ Wro)^T per batch (bf16)
    rvw_gemm<<<dim3(HID / 64, NB), 256>>>(Wro);

    // rout = P2 @ rvW  (K=64, bf16 out), batched over grid.z
    hmma_gemm<1,1><<<dim3(HID / 128, NT / 128, NB), 256, SMEM1>>>(
        p2h, nullptr, rvwt, nullptr, routb, HID, NS,
        (size_t)NT * NS, (size_t)HID * NS, (size_t)NT * HID);

    // LN + gate + MSE
    loss_ln_kernel<<<BT, 256>>>(rnw, rnb, gateb);
    finalize_kernel<<<1, 1>>>(gateb, outp);
}

// round 8
// speedup vs baseline: 5.1651x; 1.0385x over previous
#include <cuda_runtime.h>
#include <cuda_bf16.h>
#include <math.h>
#include <stdint.h>

#define HID 4096
#define SD 256
#define NS 64           // slots
#define NB 4            // batch
#define NT 4096         // tokens
#define BT (NB*NT)      // 16384
#define LN_EPS 1e-5f
#define ATT_SCALE 0.0625f  // 256^-0.5
#define KC 512          // split-K chunk for skinny GEMMs

// ---------------- scratch (static device globals; no runtime alloc) ----------------
__device__ float g_kvr[BT * 768];          // [b*T+t][ k(0:256) | v(256:512) | rq(512:768) ]
__device__ float g_q[NS * SD];             // slot queries (batch-independent)
__device__ float g_s1[NB * NS * NT];       // attn1 scores/probs [b][s][t]
__device__ float g_out_sd[NB * NS * SD];   // attn1 output before Wo
__device__ float g_spre[NB * NS * HID];    // slots + out@Wo, before LN
__device__ float g_rkv[NB * NS * 512];     // [b*S+s][ rk(0:256) | rv(256:512) ]
__device__ float g_s2[NB * NT * NS];       // attn2 scores [b][t][s]
__device__ __nv_bfloat16 g_p2h[NB * NT * NS];      // attn2 probs bf16 [b*T+t][s]
__device__ __nv_bfloat16 g_rvwt[NB * HID * NS];    // (rv@Wro)^T per batch: [b][n][s]
__device__ __nv_bfloat16 g_routb[(size_t)BT * HID];// rout before LN, bf16 (128 MB)
__device__ double g_loss;

// bf16 split operands for tensor-core GEMMs
__device__ __nv_bfloat16 g_segh[(size_t)BT * HID];   // seg hi
__device__ __nv_bfloat16 g_segl[(size_t)BT * HID];   // seg lo
__device__ __nv_bfloat16 g_WTh[768 * HID];           // [Wk|Wv|Wrq]^T  [768][4096]
__device__ __nv_bfloat16 g_WTl[768 * HID];

// ================= ptx helpers (sm_80-era: valid on base sm_103 target) =================
__device__ __forceinline__ uint32_t s2u(const void* p) {
    uint32_t a;
    asm("{ .reg .u64 t; cvta.to.shared.u64 t, %1; cvt.u32.u64 %0, t; }" : "=r"(a) : "l"(p));
    return a;
}
__device__ __forceinline__ void cpa16(uint32_t dst, const void* src) {
    asm volatile("cp.async.cg.shared.global [%0], [%1], 16;" :: "r"(dst), "l"(src) : "memory");
}
__device__ __forceinline__ void ldsm_x4(uint32_t* r, uint32_t addr) {
    asm volatile("ldmatrix.sync.aligned.m8n8.x4.shared.b16 {%0,%1,%2,%3}, [%4];"
        : "=r"(r[0]), "=r"(r[1]), "=r"(r[2]), "=r"(r[3]) : "r"(addr));
}
__device__ __forceinline__ void mma16816(float* d, const uint32_t* a, const uint32_t* b) {
    asm volatile("mma.sync.aligned.m16n8k16.row.col.f32.bf16.bf16.f32 "
        "{%0,%1,%2,%3}, {%4,%5,%6,%7}, {%8,%9}, {%0,%1,%2,%3};"
        : "+f"(d[0]), "+f"(d[1]), "+f"(d[2]), "+f"(d[3])
        : "r"(a[0]), "r"(a[1]), "r"(a[2]), "r"(a[3]), "r"(b[0]), "r"(b[1]));
}
__device__ __forceinline__ uint32_t sw128(uint32_t off) { return off ^ ((off >> 3) & 0x70); }

// ===================================================================================
// HMMA split-bf16 GEMM.
//   TERMS==3: C = Ah@Bh^T + Ah@Bl^T + Al@Bh^T   TERMS==1: C = Ah@Bh^T
//   OUTBF16:  C written as bf16 instead of fp32.
//   BN: block N-tile (128 or 256). Block M-tile fixed 128. Warps 2x4; warp tile 64x(BN/4).
// A*: [Mtot][K] K-major bf16.  B*: [Ntot][K] K-major bf16.
// K-chunk 64, 2-stage cp.async pipeline.
// grid (Ntot/BN, Mtot/128, nbatch); per-batch strides sA/sB/sC (elements).
// ===================================================================================
template<int TERMS, int OUTBF16, int BN>
__global__ void __launch_bounds__(256, 1) hmma_gemm(
    const __nv_bfloat16* __restrict__ Ah, const __nv_bfloat16* __restrict__ Al,
    const __nv_bfloat16* __restrict__ Bh, const __nv_bfloat16* __restrict__ Bl,
    void* __restrict__ Cv, int ldc, int K, size_t sA, size_t sB, size_t sC)
{
    constexpr int NI = BN / 32;                       // n8-fragments per warp
    constexpr uint32_t A_SZ = 16384u * (TERMS == 3 ? 2 : 1);
    constexpr uint32_t B_MAT = (uint32_t)BN * 128u;   // one B matrix per stage
    constexpr uint32_t B_SZ = B_MAT * (TERMS == 3 ? 2 : 1);
    constexpr uint32_t STAGE = A_SZ + B_SZ;
    constexpr uint32_t AL_OFF = 16384u;
    constexpr uint32_t BH_OFF = A_SZ;
    constexpr uint32_t BL_OFF = A_SZ + B_MAT;
    extern __shared__ char smem[];
    uint32_t sb = s2u(smem);
    int tid = threadIdx.x, wid = tid >> 5, lane = tid & 31;
    int n0 = blockIdx.x * BN, m0 = blockIdx.y << 7;
    int bz = blockIdx.z;
    Ah += (size_t)bz * sA;
    if (TERMS == 3) Al += (size_t)bz * sA;
    Bh += (size_t)bz * sB;
    if (TERMS == 3) Bl += (size_t)bz * sB;
    const int nch = K >> 6;
    int wm = (wid & 1) << 6;
    int wn = (wid >> 1) * (BN / 4);

    #define LOAD_CHUNK(s, c) do { \
        uint32_t base = sb + (uint32_t)(s) * STAGE; \
        int k0 = (c) << 6; \
        _Pragma("unroll") \
        for (int i = 0; i < 4; i++) { \
            int u = tid + (i << 8); \
            int row = u >> 3, cu = u & 7; \
            uint32_t sw = sw128((uint32_t)u << 4); \
            size_t ao = (size_t)(m0 + row) * K + k0 + (cu << 3); \
            cpa16(base + sw, Ah + ao); \
            if (TERMS == 3) cpa16(base + AL_OFF + sw, Al + ao); \
        } \
        _Pragma("unroll") \
        for (int i = 0; i < BN / 32; i++) { \
            int u = tid + (i << 8); \
            int row = u >> 3, cu = u & 7; \
            uint32_t sw = sw128((uint32_t)u << 4); \
            size_t bo = (size_t)(n0 + row) * K + k0 + (cu << 3); \
            cpa16(base + BH_OFF + sw, Bh + bo); \
            if (TERMS == 3) cpa16(base + BL_OFF + sw, Bl + bo); \
        } \
        asm volatile("cp.async.commit_group;" ::: "memory"); \
    } while (0)

    float acc[4][NI][4] = {};

    LOAD_CHUNK(0, 0);

    for (int c = 0; c < nch; c++) {
        if (c + 1 < nch) {
            LOAD_CHUNK((c + 1) & 1, c + 1);
            asm volatile("cp.async.wait_group 1;" ::: "memory");
        } else {
            asm volatile("cp.async.wait_group 0;" ::: "memory");
        }
        __syncthreads();

        uint32_t base = sb + (uint32_t)(c & 1) * STAGE;
        #pragma unroll
        for (int ks = 0; ks < 4; ks++) {
            uint32_t ah[4][4], al[4][4];
            uint32_t acb = (uint32_t)((ks << 4) + ((lane >> 4) << 3)) << 1;
            #pragma unroll
            for (int mi = 0; mi < 4; mi++) {
                uint32_t r = (uint32_t)(wm + (mi << 4) + (lane & 15));
                uint32_t sw = sw128((r << 7) + acb);
                ldsm_x4(ah[mi], base + sw);
                if (TERMS == 3) ldsm_x4(al[mi], base + AL_OFF + sw);
            }
            // B: one ldsm_x4 fills two adjacent n8k16 fragments
            uint32_t bcb = (uint32_t)((ks << 4) + (((lane >> 3) & 1) << 3)) << 1;
            #pragma unroll
            for (int ni = 0; ni < NI; ni += 2) {
                uint32_t r = (uint32_t)(wn + (ni << 3) + ((lane >> 4) << 3) + (lane & 7));
                uint32_t sw = sw128((r << 7) + bcb);
                uint32_t bh2[4];
                ldsm_x4(bh2, base + BH_OFF + sw);
                #pragma unroll
                for (int mi = 0; mi < 4; mi++) {
                    mma16816(acc[mi][ni],     ah[mi], bh2);
                    mma16816(acc[mi][ni + 1], ah[mi], bh2 + 2);
                    if (TERMS == 3) {
                        mma16816(acc[mi][ni],     al[mi], bh2);
                        mma16816(acc[mi][ni + 1], al[mi], bh2 + 2);
                    }
                }
                if (TERMS == 3) {
                    uint32_t bl2[4];
                    ldsm_x4(bl2, base + BL_OFF + sw);
                    #pragma unroll
                    for (int mi = 0; mi < 4; mi++) {
                        mma16816(acc[mi][ni],     ah[mi], bl2);
                        mma16816(acc[mi][ni + 1], ah[mi], bl2 + 2);
                    }
                }
            }
        }
        __syncthreads();
    }

    int rbase = m0 + wm + (lane >> 2);
    int cbase = n0 + wn + ((lane & 3) << 1);
    #pragma unroll
    for (int mi = 0; mi < 4; mi++)
        #pragma unroll
        for (int ni = 0; ni < NI; ni++) {
            int row = rbase + (mi << 4);
            int col = cbase + (ni << 3);
            if (OUTBF16) {
                __nv_bfloat16* C = (__nv_bfloat16*)Cv + (size_t)bz * sC;
                *(__nv_bfloat162*)(C + (size_t)row * ldc + col) =
                    __nv_bfloat162(__float2bfloat16(acc[mi][ni][0]), __float2bfloat16(acc[mi][ni][1]));
                *(__nv_bfloat162*)(C + (size_t)(row + 8) * ldc + col) =
                    __nv_bfloat162(__float2bfloat16(acc[mi][ni][2]), __float2bfloat16(acc[mi][ni][3]));
            } else {
                float* C = (float*)Cv + (size_t)bz * sC;
                *(float2*)(C + (size_t)row * ldc + col)       = make_float2(acc[mi][ni][0], acc[mi][ni][1]);
                *(float2*)(C + (size_t)(row + 8) * ldc + col) = make_float2(acc[mi][ni][2], acc[mi][ni][3]);
            }
        }
    #undef LOAD_CHUNK
}

// ---------------- fp32 -> (hi, lo) bf16 split, elementwise ----------------
__global__ void __launch_bounds__(256) conv_hilo(
    const float* __restrict__ src, __nv_bfloat16* __restrict__ h, __nv_bfloat16* __restrict__ l)
{
    size_t i = ((size_t)blockIdx.x * 256 + threadIdx.x) * 4;
    float4 v = *(const float4*)(src + i);
    __nv_bfloat16 h0 = __float2bfloat16(v.x), h1 = __float2bfloat16(v.y);
    __nv_bfloat16 h2 = __float2bfloat16(v.z), h3 = __float2bfloat16(v.w);
    __nv_bfloat16 l0 = __float2bfloat16(v.x - __bfloat162float(h0));
    __nv_bfloat16 l1 = __float2bfloat16(v.y - __bfloat162float(h1));
    __nv_bfloat16 l2 = __float2bfloat16(v.z - __bfloat162float(h2));
    __nv_bfloat16 l3 = __float2bfloat16(v.w - __bfloat162float(h3));
    *(__nv_bfloat162*)(h + i)     = __nv_bfloat162(h0, h1);
    *(__nv_bfloat162*)(h + i + 2) = __nv_bfloat162(h2, h3);
    *(__nv_bfloat162*)(l + i)     = __nv_bfloat162(l0, l1);
    *(__nv_bfloat162*)(l + i + 2) = __nv_bfloat162(l2, l3);
}

// ---------------- transpose + split, 3 weights in one launch -----------------------
// W[z]: [HID][256] fp32 -> dst[z*256 + n][HID] bf16 hi/lo
__global__ void __launch_bounds__(256) transpose_conv3(
    const float* __restrict__ W0, const float* __restrict__ W1, const float* __restrict__ W2,
    __nv_bfloat16* __restrict__ dh, __nv_bfloat16* __restrict__ dl)
{
    __shared__ float t[32][33];
    int z = blockIdx.z;
    const float* W = (z == 0) ? W0 : ((z == 1) ? W1 : W2);
    int n0 = blockIdx.x << 5, k0 = blockIdx.y << 5;
    int tx = threadIdx.x & 31, ty = threadIdx.x >> 5;
    #pragma unroll
    for (int i = 0; i < 32; i += 8)
        t[ty + i][tx] = W[(size_t)(k0 + ty + i) * SD + n0 + tx];
    __syncthreads();
    #pragma unroll
    for (int i = 0; i < 32; i += 8) {
        float x = t[tx][ty + i];
        int n = z * SD + n0 + ty + i, k = k0 + tx;
        __nv_bfloat16 hh = __float2bfloat16(x);
        dh[(size_t)n * HID + k] = hh;
        dl[(size_t)n * HID + k] = __float2bfloat16(x - __bfloat162float(hh));
    }
}

// ---------------- helpers ----------------
__device__ __forceinline__ float block_reduce_sum256(float v, float* red) {
    int tid = threadIdx.x;
    red[tid] = v; __syncthreads();
    #pragma unroll
    for (int o = 128; o > 0; o >>= 1) {
        if (tid < o) red[tid] += red[tid + o];
        __syncthreads();
    }
    float r = red[0];
    __syncthreads();
    return r;
}

__global__ void init_loss_kernel() { g_loss = 0.0; }

// ===================================================================================
// Skinny split-K GEMM: 64x64 tile over a K-chunk of KC, atomicAdd into pre-zeroed C.
// ===================================================================================
__global__ __launch_bounds__(256) void gemm_small(
    const float* __restrict__ A, int lda,
    const float* __restrict__ W0, const float* __restrict__ W1,
    float* __restrict__ C, int ldc)
{
    __shared__ float As[16][64];
    __shared__ float Bs[16][64];
    int tid = threadIdx.x;
    int m0 = blockIdx.x << 6;
    int n0 = blockIdx.y << 6;
    int kbase = blockIdx.z * KC;
    const float* W = (n0 >> 8) ? W1 : W0;
    int col0 = n0 & 255;

    int r = tid >> 2, c = (tid & 3) << 2;
    int br = tid >> 4, bc = (tid & 15) << 2;
    int tx = (tid & 15) << 2, ty = (tid >> 4) << 2;

    float acc[4][4] = {};
    for (int k0 = kbase; k0 < kbase + KC; k0 += 16) {
        float4 av = *(const float4*)(A + (size_t)(m0 + r) * lda + k0 + c);
        As[c + 0][r] = av.x; As[c + 1][r] = av.y; As[c + 2][r] = av.z; As[c + 3][r] = av.w;
        *(float4*)&Bs[br][bc] = *(const float4*)(W + (size_t)(k0 + br) * 256 + col0 + bc);
        __syncthreads();
        #pragma unroll
        for (int kk = 0; kk < 16; kk++) {
            float4 a = *(const float4*)&As[kk][ty];
            float4 b = *(const float4*)&Bs[kk][tx];
            acc[0][0] += a.x * b.x; acc[0][1] += a.x * b.y; acc[0][2] += a.x * b.z; acc[0][3] += a.x * b.w;
            acc[1][0] += a.y * b.x; acc[1][1] += a.y * b.y; acc[1][2] += a.y * b.z; acc[1][3] += a.y * b.w;
            acc[2][0] += a.z * b.x; acc[2][1] += a.z * b.y; acc[2][2] += a.z * b.z; acc[2][3] += a.z * b.w;
            acc[3][0] += a.w * b.x; acc[3][1] += a.w * b.y; acc[3][2] += a.w * b.z; acc[3][3] += a.w * b.w;
        }
        __syncthreads();
    }
    #pragma unroll
    for (int i = 0; i < 4; i++)
        #pragma unroll
        for (int j = 0; j < 4; j++)
            atomicAdd(C + (size_t)(m0 + ty + i) * ldc + n0 + tx + j, acc[i][j]);
}

// ---------------- attn1 scores ----------------
__global__ __launch_bounds__(256) void scores1_kernel()
{
    __shared__ float Qs[16][64];
    __shared__ float Ks[16][64];
    int tid = threadIdx.x;
    int t0 = blockIdx.x << 6;
    int b = blockIdx.y;
    int r = tid >> 2, c = (tid & 3) << 2;
    int tx = (tid & 15) << 2, ty = (tid >> 4) << 2;

    float acc[4][4] = {};
    for (int k0 = 0; k0 < SD; k0 += 16) {
        float4 qv = *(const float4*)(g_q + (size_t)r * SD + k0 + c);
        Qs[c + 0][r] = qv.x; Qs[c + 1][r] = qv.y; Qs[c + 2][r] = qv.z; Qs[c + 3][r] = qv.w;
        float4 kv = *(const float4*)(g_kvr + (size_t)(b * NT + t0 + r) * 768 + k0 + c);
        Ks[c + 0][r] = kv.x; Ks[c + 1][r] = kv.y; Ks[c + 2][r] = kv.z; Ks[c + 3][r] = kv.w;
        __syncthreads();
        #pragma unroll
        for (int kk = 0; kk < 16; kk++) {
            float4 a = *(const float4*)&Qs[kk][ty];
            float4 d = *(const float4*)&Ks[kk][tx];
            acc[0][0] += a.x * d.x; acc[0][1] += a.x * d.y; acc[0][2] += a.x * d.z; acc[0][3] += a.x * d.w;
            acc[1][0] += a.y * d.x; acc[1][1] += a.y * d.y; acc[1][2] += a.y * d.z; acc[1][3] += a.y * d.w;
            acc[2][0] += a.z * d.x; acc[2][1] += a.z * d.y; acc[2][2] += a.z * d.z; acc[2][3] += a.z * d.w;
            acc[3][0] += a.w * d.x; acc[3][1] += a.w * d.y; acc[3][2] += a.w * d.z; acc[3][3] += a.w * d.w;
        }
        __syncthreads();
    }
    #pragma unroll
    for (int i = 0; i < 4; i++)
        #pragma unroll
        for (int j = 0; j < 4; j++)
            g_s1[((size_t)b * NS + ty + i) * NT + t0 + tx + j] = acc[i][j] * ATT_SCALE;
}

__global__ __launch_bounds__(256) void softmax1_kernel()
{
    __shared__ float red[256];
    int tid = threadIdx.x;
    float* row = g_s1 + (size_t)blockIdx.x * NT;

    float m = -1e30f;
    for (int t = tid; t < NT; t += 256) m = fmaxf(m, row[t]);
    red[tid] = m; __syncthreads();
    #pragma unroll
    for (int o = 128; o > 0; o >>= 1) { if (tid < o) red[tid] = fmaxf(red[tid], red[tid + o]); __syncthreads(); }
    m = red[0]; __syncthreads();

    float sum = 0.f;
    for (int t = tid; t < NT; t += 256) { float e = expf(row[t] - m); row[t] = e; sum += e; }
    float tot = block_reduce_sum256(sum, red);
    float inv = 1.0f / tot;
    for (int t = tid; t < NT; t += 256) row[t] *= inv;
}

__global__ __launch_bounds__(256) void pv1_kernel()
{
    __shared__ float As[16][64];
    __shared__ float Bs[16][64];
    int tid = threadIdx.x;
    int n0 = blockIdx.x << 6;
    int kbase = blockIdx.y * KC;
    int b = blockIdx.z;
    int r = tid >> 2, c = (tid & 3) << 2;
    int br = tid >> 4, bc = (tid & 15) << 2;
    int tx = (tid & 15) << 2, ty = (tid >> 4) << 2;

    float acc[4][4] = {};
    for (int k0 = kbase; k0 < kbase + KC; k0 += 16) {
        float4 av = *(const float4*)(g_s1 + ((size_t)b * NS + r) * NT + k0 + c);
        As[c + 0][r] = av.x; As[c + 1][r] = av.y; As[c + 2][r] = av.z; As[c + 3][r] = av.w;
        *(float4*)&Bs[br][bc] = *(const float4*)(g_kvr + (size_t)(b * NT + k0 + br) * 768 + 256 + n0 + bc);
        __syncthreads();
        #pragma unroll
        for (int kk = 0; kk < 16; kk++) {
            float4 a = *(const float4*)&As[kk][ty];
            float4 d = *(const float4*)&Bs[kk][tx];
            acc[0][0] += a.x * d.x; acc[0][1] += a.x * d.y; acc[0][2] += a.x * d.z; acc[0][3] += a.x * d.w;
            acc[1][0] += a.y * d.x; acc[1][1] += a.y * d.y; acc[1][2] += a.y * d.z; acc[1][3] += a.y * d.w;
            acc[2][0] += a.z * d.x; acc[2][1] += a.z * d.y; acc[2][2] += a.z * d.z; acc[2][3] += a.z * d.w;
            acc[3][0] += a.w * d.x; acc[3][1] += a.w * d.y; acc[3][2] += a.w * d.z; acc[3][3] += a.w * d.w;
        }
        __syncthreads();
    }
    #pragma unroll
    for (int i = 0; i < 4; i++)
        #pragma unroll
        for (int j = 0; j < 4; j++)
            atomicAdd(g_out_sd + ((size_t)b * NS + ty + i) * SD + n0 + tx + j, acc[i][j]);
}

__global__ __launch_bounds__(256) void wo_gemm(
    const float* __restrict__ Wo, const float* __restrict__ slot_emb)
{
    __shared__ float As[16][64];
    __shared__ float Bs[16][64];
    int tid = threadIdx.x;
    int m0 = blockIdx.x << 6;
    int n0 = blockIdx.y << 6;
    int r = tid >> 2, c = (tid & 3) << 2;
    int br = tid >> 4, bc = (tid & 15) << 2;
    int tx = (tid & 15) << 2, ty = (tid >> 4) << 2;

    float acc[4][4] = {};
    for (int k0 = 0; k0 < SD; k0 += 16) {
        float4 av = *(const float4*)(g_out_sd + (size_t)(m0 + r) * SD + k0 + c);
        As[c + 0][r] = av.x; As[c + 1][r] = av.y; As[c + 2][r] = av.z; As[c + 3][r] = av.w;
        *(float4*)&Bs[br][bc] = *(const float4*)(Wo + (size_t)(k0 + br) * HID + n0 + bc);
        __syncthreads();
        #pragma unroll
        for (int kk = 0; kk < 16; kk++) {
            float4 a = *(const float4*)&As[kk][ty];
            float4 d = *(const float4*)&Bs[kk][tx];
            acc[0][0] += a.x * d.x; acc[0][1] += a.x * d.y; acc[0][2] += a.x * d.z; acc[0][3] += a.x * d.w;
            acc[1][0] += a.y * d.x; acc[1][1] += a.y * d.y; acc[1][2] += a.y * d.z; acc[1][3] += a.y * d.w;
            acc[2][0] += a.z * d.x; acc[2][1] += a.z * d.y; acc[2][2] += a.z * d.z; acc[2][3] += a.z * d.w;
            acc[3][0] += a.w * d.x; acc[3][1] += a.w * d.y; acc[3][2] += a.w * d.z; acc[3][3] += a.w * d.w;
        }
        __syncthreads();
    }
    #pragma unroll
    for (int i = 0; i < 4; i++) {
        int row = m0 + ty + i;
        int s = row & 63;
        #pragma unroll
        for (int j = 0; j < 4; j++) {
            int col = n0 + tx + j;
            g_spre[(size_t)row * HID + col] = acc[i][j] + slot_emb[(size_t)s * HID + col];
        }
    }
}

__global__ __launch_bounds__(256) void ln_rows_kernel(
    const float* __restrict__ src, const float* __restrict__ w,
    const float* __restrict__ bb, float* __restrict__ dst)
{
    __shared__ float red[256];
    int tid = threadIdx.x, rrow = blockIdx.x;
    const float* row = src + (size_t)rrow * HID;

    float v[16];
    #pragma unroll
    for (int i = 0; i < 16; i++) v[i] = row[tid + (i << 8)];
    float sum = 0.f, sq = 0.f;
    #pragma unroll
    for (int i = 0; i < 16; i++) { sum += v[i]; sq += v[i] * v[i]; }
    float tsum = block_reduce_sum256(sum, red);
    float tsq  = block_reduce_sum256(sq, red);
    float mu = tsum * (1.0f / HID);
    float var = tsq * (1.0f / HID) - mu * mu;
    float invs = rsqrtf(var + LN_EPS);
    #pragma unroll
    for (int i = 0; i < 16; i++) {
        int col = tid + (i << 8);
        dst[(size_t)rrow * HID + col] = (v[i] - mu) * invs * w[col] + bb[col];
    }
}

__global__ __launch_bounds__(256) void scores2_kernel()
{
    __shared__ float As[16][64];
    __shared__ float Bs[16][64];
    int tid = threadIdx.x;
    int t0 = blockIdx.x << 6;
    int b = blockIdx.y;
    int r = tid >> 2, c = (tid & 3) << 2;
    int tx = (tid & 15) << 2, ty = (tid >> 4) << 2;

    float acc[4][4] = {};
    for (int k0 = 0; k0 < SD; k0 += 16) {
        float4 av = *(const float4*)(g_kvr + (size_t)(b * NT + t0 + r) * 768 + 512 + k0 + c);
        As[c + 0][r] = av.x; As[c + 1][r] = av.y; As[c + 2][r] = av.z; As[c + 3][r] = av.w;
        float4 kv = *(const float4*)(g_rkv + (size_t)(b * NS + r) * 512 + k0 + c);
        Bs[c + 0][r] = kv.x; Bs[c + 1][r] = kv.y; Bs[c + 2][r] = kv.z; Bs[c + 3][r] = kv.w;
        __syncthreads();
        #pragma unroll
        for (int kk = 0; kk < 16; kk++) {
            float4 a = *(const float4*)&As[kk][ty];
            float4 d = *(const float4*)&Bs[kk][tx];
            acc[0][0] += a.x * d.x; acc[0][1] += a.x * d.y; acc[0][2] += a.x * d.z; acc[0][3] += a.x * d.w;
            acc[1][0] += a.y * d.x; acc[1][1] += a.y * d.y; acc[1][2] += a.y * d.z; acc[1][3] += a.y * d.w;
            acc[2][0] += a.z * d.x; acc[2][1] += a.z * d.y; acc[2][2] += a.z * d.z; acc[2][3] += a.z * d.w;
            acc[3][0] += a.w * d.x; acc[3][1] += a.w * d.y; acc[3][2] += a.w * d.z; acc[3][3] += a.w * d.w;
        }
        __syncthreads();
    }
    #pragma unroll
    for (int i = 0; i < 4; i++)
        #pragma unroll
        for (int j = 0; j < 4; j++)
            g_s2[((size_t)b * NT + t0 + ty + i) * NS + tx + j] = acc[i][j] * ATT_SCALE;
}

// softmax over s (64) per (b,t) row; writes NORMALIZED probs as bf16 to g_p2h
__global__ __launch_bounds__(256) void softmax2_kernel()
{
    int tid = threadIdx.x;
    int row = (blockIdx.x << 3) + (tid >> 5);
    int lane = tid & 31;
    const float* p = g_s2 + (size_t)row * NS;
    float v0 = p[lane], v1 = p[lane + 32];
    float m = fmaxf(v0, v1);
    #pragma unroll
    for (int o = 16; o > 0; o >>= 1) m = fmaxf(m, __shfl_xor_sync(0xffffffffu, m, o));
    float e0 = expf(v0 - m), e1 = expf(v1 - m);
    float s = e0 + e1;
    #pragma unroll
    for (int o = 16; o > 0; o >>= 1) s += __shfl_xor_sync(0xffffffffu, s, o);
    float inv = 1.0f / s;
    g_p2h[(size_t)row * NS + lane]      = __float2bfloat16(e0 * inv);
    g_p2h[(size_t)row * NS + lane + 32] = __float2bfloat16(e1 * inv);
}

// rvWT[b][n][s] = sum_k rv[b][s][k] * Wro[k][n], written transposed as bf16.
__global__ __launch_bounds__(256) void rvw_gemm(const float* __restrict__ Wro)
{
    __shared__ float As[16][64];
    __shared__ float Bs[16][64];
    int tid = threadIdx.x;
    int n0 = blockIdx.x << 6;
    int b = blockIdx.y;
    int r = tid >> 2, c = (tid & 3) << 2;
    int br = tid >> 4, bc = (tid & 15) << 2;
    int tx = (tid & 15) << 2, ty = (tid >> 4) << 2;

    float acc[4][4] = {};
    for (int k0 = 0; k0 < SD; k0 += 16) {
        float4 av = *(const float4*)(g_rkv + (size_t)(b * NS + r) * 512 + 256 + k0 + c);
        As[c + 0][r] = av.x; As[c + 1][r] = av.y; As[c + 2][r] = av.z; As[c + 3][r] = av.w;
        *(float4*)&Bs[br][bc] = *(const float4*)(Wro + (size_t)(k0 + br) * HID + n0 + bc);
        __syncthreads();
        #pragma unroll
        for (int kk = 0; kk < 16; kk++) {
            float4 a = *(const float4*)&As[kk][ty];
            float4 d = *(const float4*)&Bs[kk][tx];
            acc[0][0] += a.x * d.x; acc[0][1] += a.x * d.y; acc[0][2] += a.x * d.z; acc[0][3] += a.x * d.w;
            acc[1][0] += a.y * d.x; acc[1][1] += a.y * d.y; acc[1][2] += a.y * d.z; acc[1][3] += a.y * d.w;
            acc[2][0] += a.z * d.x; acc[2][1] += a.z * d.y; acc[2][2] += a.z * d.z; acc[2][3] += a.z * d.w;
            acc[3][0] += a.w * d.x; acc[3][1] += a.w * d.y; acc[3][2] += a.w * d.z; acc[3][3] += a.w * d.w;
        }
        __syncthreads();
    }
    __nv_bfloat16* dst = g_rvwt + (size_t)b * HID * NS;
    #pragma unroll
    for (int i = 0; i < 4; i++)
        #pragma unroll
        for (int j = 0; j < 4; j++)
            dst[(size_t)(n0 + tx + j) * NS + ty + i] = __float2bfloat16(acc[i][j]);
}

// ---------------- per-row LN + gate + squared-error accumulation (bf16 inputs) ------
__global__ __launch_bounds__(256) void loss_ln_kernel(
    const float* __restrict__ lnw, const float* __restrict__ lnb,
    const float* __restrict__ gate_bias)
{
    __shared__ float red[256];
    __shared__ float gsh;
    int tid = threadIdx.x, rrow = blockIdx.x;
    const __nv_bfloat162* row = (const __nv_bfloat162*)(g_routb + (size_t)rrow * HID);

    float2 v[8];
    #pragma unroll
    for (int i = 0; i < 8; i++) {
        __nv_bfloat162 t = row[tid + (i << 8)];
        v[i] = make_float2(__bfloat162float(t.x), __bfloat162float(t.y));
    }

    if (tid == 0) {
        float sg = 0.f;
        for (int i = 0; i < 64; i++) sg += gate_bias[i];
        sg *= (1.0f / 64.0f);
        gsh = 1.0f / (1.0f + expf(-sg));
    }

    float sum = 0.f, sq = 0.f;
    #pragma unroll
    for (int i = 0; i < 8; i++) {
        sum += v[i].x + v[i].y;
        sq += v[i].x * v[i].x + v[i].y * v[i].y;
    }
    float tsum = block_reduce_sum256(sum, red);
    float tsq  = block_reduce_sum256(sq, red);
    float mu = tsum * (1.0f / HID);
    float var = tsq * (1.0f / HID) - mu * mu;
    float invs = rsqrtf(var + LN_EPS);
    float g = gsh;

    const __nv_bfloat162* segrow = (const __nv_bfloat162*)(g_segh + (size_t)rrow * HID);
    float acc = 0.f;
    #pragma unroll
    for (int i = 0; i < 8; i++) {
        int col = (tid + (i << 8)) * 2;
        float2 wv = *(const float2*)(lnw + col);
        float2 bv = *(const float2*)(lnb + col);
        __nv_bfloat162 st = segrow[tid + (i << 8)];
        float r0 = g * ((v[i].x - mu) * invs * wv.x + bv.x) - __bfloat162float(st.x);
        float r1 = g * ((v[i].y - mu) * invs * wv.y + bv.y) - __bfloat162float(st.y);
        acc += r0 * r0 + r1 * r1;
    }
    float bsum = block_reduce_sum256(acc, red);
    if (tid == 0) atomicAdd(&g_loss, (double)bsum);
}

__global__ void finalize_kernel(const float* __restrict__ gate_bias, float* __restrict__ outp)
{
    float sg = 0.f;
    for (int i = 0; i < 64; i++) sg += gate_bias[i];
    sg *= (1.0f / 64.0f);
    float g = 1.0f / (1.0f + expf(-sg));
    outp[NB * NS * HID]     = (float)(g_loss / (double)((size_t)NB * NT * HID));
    outp[NB * NS * HID + 1] = g;
}

// ---------------- launch ------------------------------------------------------------
extern "C" void kernel_launch(void* const* d_in, const int* in_sizes, int n_in,
                              void* d_out, int out_size)
{
    const float* seg      = (const float*)d_in[0];
    const float* slot_emb = (const float*)d_in[1];
    const float* Wq       = (const float*)d_in[2];
    const float* Wk       = (const float*)d_in[3];
    const float* Wv       = (const float*)d_in[4];
    const float* Wo       = (const float*)d_in[5];
    const float* Wrq      = (const float*)d_in[6];
    const float* Wro      = (const float*)d_in[7];
    const float* gateb    = (const float*)d_in[8];
    const float* snw      = (const float*)d_in[9];
    const float* snb      = (const float*)d_in[10];
    const float* rnw      = (const float*)d_in[11];
    const float* rnb      = (const float*)d_in[12];
    float* outp = (float*)d_out;

    float* kvr;      cudaGetSymbolAddress((void**)&kvr, g_kvr);
    float* qbuf;     cudaGetSymbolAddress((void**)&qbuf, g_q);
    float* out_sd;   cudaGetSymbolAddress((void**)&out_sd, g_out_sd);
    float* spre;     cudaGetSymbolAddress((void**)&spre, g_spre);
    float* rkv;      cudaGetSymbolAddress((void**)&rkv, g_rkv);
    __nv_bfloat16 *segh, *segl, *WTh, *WTl, *p2h, *rvwt, *routb;
    cudaGetSymbolAddress((void**)&segh, g_segh);
    cudaGetSymbolAddress((void**)&segl, g_segl);
    cudaGetSymbolAddress((void**)&WTh, g_WTh);
    cudaGetSymbolAddress((void**)&WTl, g_WTl);
    cudaGetSymbolAddress((void**)&p2h, g_p2h);
    cudaGetSymbolAddress((void**)&rvwt, g_rvwt);
    cudaGetSymbolAddress((void**)&routb, g_routb);

    const int SMEM_KV   = 2 * (32768 + 65536);  // TERMS=3, BN=256: 192 KB
    const int SMEM_RQ   = 2 * (16384 + 32768);  // TERMS=1, BN=256: 96 KB
    const int SMEM_ROUT = 2 * (16384 + 16384);  // TERMS=1, BN=128: 64 KB
    cudaFuncSetAttribute(hmma_gemm<3,0,256>, cudaFuncAttributeMaxDynamicSharedMemorySize, SMEM_KV);
    cudaFuncSetAttribute(hmma_gemm<1,0,256>, cudaFuncAttributeMaxDynamicSharedMemorySize, SMEM_RQ);
    cudaFuncSetAttribute(hmma_gemm<1,1,128>, cudaFuncAttributeMaxDynamicSharedMemorySize, SMEM_ROUT);

    init_loss_kernel<<<1, 1>>>();
    cudaMemsetAsync(qbuf, 0, (size_t)NS * SD * sizeof(float));
    cudaMemsetAsync(out_sd, 0, (size_t)NB * NS * SD * sizeof(float));
    cudaMemsetAsync(rkv, 0, (size_t)NB * NS * 512 * sizeof(float));

    // bf16 splits: seg, transposed weights Wk|Wv|Wrq -> WT[768][4096] (one launch)
    conv_hilo<<<(size_t)BT * HID / 1024, 256>>>(seg, segh, segl);
    transpose_conv3<<<dim3(SD / 32, HID / 32, 3), 256>>>(Wk, Wv, Wrq, WTh, WTl);

    // k | v = seg @ {Wk,Wv}  — 3-pass split, 128x256 tiles (A read 2x)
    hmma_gemm<3,0,256><<<dim3(2, BT / 128), 256, SMEM_KV>>>(segh, segl, WTh, WTl, kvr, 768, HID, 0, 0, 0);
    // rq = seg @ Wrq — 1-pass bf16, 128x256 tile (A read 1x)
    hmma_gemm<1,0,256><<<dim3(1, BT / 128), 256, SMEM_RQ>>>(segh, segl, WTh + 512 * HID, WTl + 512 * HID, kvr + 512, 768, HID, 0, 0, 0);

    // q = slot_embeddings @ Wq  (split-K fp32)
    gemm_small<<<dim3(1, 4, 8), 256>>>(slot_emb, HID, Wq, nullptr, qbuf, SD);

    // attn1
    scores1_kernel<<<dim3(64, NB), 256>>>();
    softmax1_kernel<<<NB * NS, 256>>>();
    pv1_kernel<<<dim3(4, 8, NB), 256>>>();

    // slots + out@Wo, LN -> updated_slots in d_out
    wo_gemm<<<dim3(4, 64), 256>>>(Wo, slot_emb);
    ln_rows_kernel<<<NB * NS, 256>>>(spre, snw, snb, outp);

    // rk | rv = updated_slots @ {Wk, Wv}
    gemm_small<<<dim3(4, 8, 8), 256>>>(outp, HID, Wk, Wv, rkv, 512);

    // attn2 scores + softmax (P2 -> bf16)
    scores2_kernel<<<dim3(64, NB), 256>>>();
    softmax2_kernel<<<BT / 8, 256>>>();

    // rvW^T = (rv @ Wro)^T per batch (bf16)
    rvw_gemm<<<dim3(HID / 64, NB), 256>>>(Wro);

    // rout = P2 @ rvW  (K=64, bf16 out), batched over grid.z
    hmma_gemm<1,1,128><<<dim3(HID / 128, NT / 128, NB), 256, SMEM_ROUT>>>(
        p2h, nullptr, rvwt, nullptr, routb, HID, NS,
        (size_t)NT * NS, (size_t)HID * NS, (size_t)NT * HID);

    // LN + gate + MSE
    loss_ln_kernel<<<BT, 256>>>(rnw, rnb, gateb);
    finalize_kernel<<<1, 1>>>(gateb, outp);
}

// round 9
// speedup vs baseline: 6.0129x; 1.1641x over previous
#include <cuda_runtime.h>
#include <cuda_bf16.h>
#include <math.h>
#include <stdint.h>

#define HID 4096
#define SD 256
#define NS 64           // slots
#define NB 4            // batch
#define NT 4096         // tokens
#define BT (NB*NT)      // 16384
#define LN_EPS 1e-5f
#define ATT_SCALE 0.0625f  // 256^-0.5
#define KC 512          // split-K chunk for skinny GEMMs

// ---------------- scratch (static device globals; no runtime alloc) ----------------
// kvr layout: [b*T+t][ k(0:256) | rq(256:512) | v(512:768) ]
__device__ float g_kvr[BT * 768];
__device__ float g_q[NS * SD];             // slot queries (batch-independent)
__device__ float g_s1[NB * NS * NT];       // attn1 scores/probs [b][s][t]
__device__ float g_out_sd[NB * NS * SD];   // attn1 output before Wo
__device__ float g_spre[NB * NS * HID];    // slots + out@Wo, before LN
__device__ float g_rkv[NB * NS * 512];     // [b*S+s][ rk(0:256) | rv(256:512) ]
__device__ float g_s2[NB * NT * NS];       // attn2 scores [b][t][s]
__device__ __nv_bfloat16 g_p2h[NB * NT * NS];      // attn2 probs bf16 [b*T+t][s]
__device__ __nv_bfloat16 g_rvwt[NB * HID * NS];    // (rv@Wro)^T per batch: [b][n][s]
__device__ __nv_bfloat16 g_routb[(size_t)BT * HID];// rout before LN, bf16 (128 MB)
__device__ double g_loss;

// bf16 split operands for tensor-core GEMMs
__device__ __nv_bfloat16 g_segh[(size_t)BT * HID];   // seg hi
__device__ __nv_bfloat16 g_segl[(size_t)BT * HID];   // seg lo
__device__ __nv_bfloat16 g_WTh[768 * HID];           // [Wk|Wrq|Wv]^T  [768][4096]
__device__ __nv_bfloat16 g_WTl[768 * HID];

// ================= ptx helpers (sm_80-era: valid on base sm_103 target) =================
__device__ __forceinline__ uint32_t s2u(const void* p) {
    uint32_t a;
    asm("{ .reg .u64 t; cvta.to.shared.u64 t, %1; cvt.u32.u64 %0, t; }" : "=r"(a) : "l"(p));
    return a;
}
__device__ __forceinline__ void cpa16(uint32_t dst, const void* src) {
    asm volatile("cp.async.cg.shared.global [%0], [%1], 16;" :: "r"(dst), "l"(src) : "memory");
}
__device__ __forceinline__ void ldsm_x4(uint32_t* r, uint32_t addr) {
    asm volatile("ldmatrix.sync.aligned.m8n8.x4.shared.b16 {%0,%1,%2,%3}, [%4];"
        : "=r"(r[0]), "=r"(r[1]), "=r"(r[2]), "=r"(r[3]) : "r"(addr));
}
__device__ __forceinline__ void mma16816(float* d, const uint32_t* a, const uint32_t* b) {
    asm volatile("mma.sync.aligned.m16n8k16.row.col.f32.bf16.bf16.f32 "
        "{%0,%1,%2,%3}, {%4,%5,%6,%7}, {%8,%9}, {%0,%1,%2,%3};"
        : "+f"(d[0]), "+f"(d[1]), "+f"(d[2]), "+f"(d[3])
        : "r"(a[0]), "r"(a[1]), "r"(a[2]), "r"(a[3]), "r"(b[0]), "r"(b[1]));
}
__device__ __forceinline__ uint32_t sw128(uint32_t off) { return off ^ ((off >> 3) & 0x70); }

// ===================================================================================
// HMMA split-bf16 GEMM.
//   TERMS==3: C = Ah@Bh^T + Ah@Bl^T + Al@Bh^T   TERMS==1: C = Ah@Bh^T
//   OUTBF16:  C written as bf16 instead of fp32.
//   BN: block N-tile (128 or 256). Block M-tile fixed 128. Warps 2x4; warp tile 64x(BN/4).
// A*: [Mtot][K] K-major bf16.  B*: [Ntot][K] K-major bf16.
// K-chunk 64, 2-stage cp.async pipeline.
// grid (Ntot/BN, Mtot/128, nbatch); per-batch strides sA/sB/sC (elements).
// ===================================================================================
template<int TERMS, int OUTBF16, int BN>
__global__ void __launch_bounds__(256, 1) hmma_gemm(
    const __nv_bfloat16* __restrict__ Ah, const __nv_bfloat16* __restrict__ Al,
    const __nv_bfloat16* __restrict__ Bh, const __nv_bfloat16* __restrict__ Bl,
    void* __restrict__ Cv, int ldc, int K, size_t sA, size_t sB, size_t sC)
{
    constexpr int NI = BN / 32;                       // n8-fragments per warp
    constexpr uint32_t A_SZ = 16384u * (TERMS == 3 ? 2 : 1);
    constexpr uint32_t B_MAT = (uint32_t)BN * 128u;   // one B matrix per stage
    constexpr uint32_t B_SZ = B_MAT * (TERMS == 3 ? 2 : 1);
    constexpr uint32_t STAGE = A_SZ + B_SZ;
    constexpr uint32_t AL_OFF = 16384u;
    constexpr uint32_t BH_OFF = A_SZ;
    constexpr uint32_t BL_OFF = A_SZ + B_MAT;
    extern __shared__ char smem[];
    uint32_t sb = s2u(smem);
    int tid = threadIdx.x, wid = tid >> 5, lane = tid & 31;
    int n0 = blockIdx.x * BN, m0 = blockIdx.y << 7;
    int bz = blockIdx.z;
    Ah += (size_t)bz * sA;
    if (TERMS == 3) Al += (size_t)bz * sA;
    Bh += (size_t)bz * sB;
    if (TERMS == 3) Bl += (size_t)bz * sB;
    const int nch = K >> 6;
    int wm = (wid & 1) << 6;
    int wn = (wid >> 1) * (BN / 4);

    #define LOAD_CHUNK(s, c) do { \
        uint32_t base = sb + (uint32_t)(s) * STAGE; \
        int k0 = (c) << 6; \
        _Pragma("unroll") \
        for (int i = 0; i < 4; i++) { \
            int u = tid + (i << 8); \
            int row = u >> 3, cu = u & 7; \
            uint32_t sw = sw128((uint32_t)u << 4); \
            size_t ao = (size_t)(m0 + row) * K + k0 + (cu << 3); \
            cpa16(base + sw, Ah + ao); \
            if (TERMS == 3) cpa16(base + AL_OFF + sw, Al + ao); \
        } \
        _Pragma("unroll") \
        for (int i = 0; i < BN / 32; i++) { \
            int u = tid + (i << 8); \
            int row = u >> 3, cu = u & 7; \
            uint32_t sw = sw128((uint32_t)u << 4); \
            size_t bo = (size_t)(n0 + row) * K + k0 + (cu << 3); \
            cpa16(base + BH_OFF + sw, Bh + bo); \
            if (TERMS == 3) cpa16(base + BL_OFF + sw, Bl + bo); \
        } \
        asm volatile("cp.async.commit_group;" ::: "memory"); \
    } while (0)

    float acc[4][NI][4] = {};

    LOAD_CHUNK(0, 0);

    for (int c = 0; c < nch; c++) {
        if (c + 1 < nch) {
            LOAD_CHUNK((c + 1) & 1, c + 1);
            asm volatile("cp.async.wait_group 1;" ::: "memory");
        } else {
            asm volatile("cp.async.wait_group 0;" ::: "memory");
        }
        __syncthreads();

        uint32_t base = sb + (uint32_t)(c & 1) * STAGE;
        #pragma unroll
        for (int ks = 0; ks < 4; ks++) {
            uint32_t ah[4][4], al[4][4];
            uint32_t acb = (uint32_t)((ks << 4) + ((lane >> 4) << 3)) << 1;
            #pragma unroll
            for (int mi = 0; mi < 4; mi++) {
                uint32_t r = (uint32_t)(wm + (mi << 4) + (lane & 15));
                uint32_t sw = sw128((r << 7) + acb);
                ldsm_x4(ah[mi], base + sw);
                if (TERMS == 3) ldsm_x4(al[mi], base + AL_OFF + sw);
            }
            // B: one ldsm_x4 fills two adjacent n8k16 fragments
            uint32_t bcb = (uint32_t)((ks << 4) + (((lane >> 3) & 1) << 3)) << 1;
            #pragma unroll
            for (int ni = 0; ni < NI; ni += 2) {
                uint32_t r = (uint32_t)(wn + (ni << 3) + ((lane >> 4) << 3) + (lane & 7));
                uint32_t sw = sw128((r << 7) + bcb);
                uint32_t bh2[4];
                ldsm_x4(bh2, base + BH_OFF + sw);
                #pragma unroll
                for (int mi = 0; mi < 4; mi++) {
                    mma16816(acc[mi][ni],     ah[mi], bh2);
                    mma16816(acc[mi][ni + 1], ah[mi], bh2 + 2);
                    if (TERMS == 3) {
                        mma16816(acc[mi][ni],     al[mi], bh2);
                        mma16816(acc[mi][ni + 1], al[mi], bh2 + 2);
                    }
                }
                if (TERMS == 3) {
                    uint32_t bl2[4];
                    ldsm_x4(bl2, base + BL_OFF + sw);
                    #pragma unroll
                    for (int mi = 0; mi < 4; mi++) {
                        mma16816(acc[mi][ni],     ah[mi], bl2);
                        mma16816(acc[mi][ni + 1], ah[mi], bl2 + 2);
                    }
                }
            }
        }
        __syncthreads();
    }

    int rbase = m0 + wm + (lane >> 2);
    int cbase = n0 + wn + ((lane & 3) << 1);
    #pragma unroll
    for (int mi = 0; mi < 4; mi++)
        #pragma unroll
        for (int ni = 0; ni < NI; ni++) {
            int row = rbase + (mi << 4);
            int col = cbase + (ni << 3);
            if (OUTBF16) {
                __nv_bfloat16* C = (__nv_bfloat16*)Cv + (size_t)bz * sC;
                *(__nv_bfloat162*)(C + (size_t)row * ldc + col) =
                    __nv_bfloat162(__float2bfloat16(acc[mi][ni][0]), __float2bfloat16(acc[mi][ni][1]));
                *(__nv_bfloat162*)(C + (size_t)(row + 8) * ldc + col) =
                    __nv_bfloat162(__float2bfloat16(acc[mi][ni][2]), __float2bfloat16(acc[mi][ni][3]));
            } else {
                float* C = (float*)Cv + (size_t)bz * sC;
                *(float2*)(C + (size_t)row * ldc + col)       = make_float2(acc[mi][ni][0], acc[mi][ni][1]);
                *(float2*)(C + (size_t)(row + 8) * ldc + col) = make_float2(acc[mi][ni][2], acc[mi][ni][3]);
            }
        }
    #undef LOAD_CHUNK
}

// ---------------- fp32 -> (hi, lo) bf16 split, elementwise ----------------
__global__ void __launch_bounds__(256) conv_hilo(
    const float* __restrict__ src, __nv_bfloat16* __restrict__ h, __nv_bfloat16* __restrict__ l)
{
    size_t i = ((size_t)blockIdx.x * 256 + threadIdx.x) * 4;
    float4 v = *(const float4*)(src + i);
    __nv_bfloat16 h0 = __float2bfloat16(v.x), h1 = __float2bfloat16(v.y);
    __nv_bfloat16 h2 = __float2bfloat16(v.z), h3 = __float2bfloat16(v.w);
    __nv_bfloat16 l0 = __float2bfloat16(v.x - __bfloat162float(h0));
    __nv_bfloat16 l1 = __float2bfloat16(v.y - __bfloat162float(h1));
    __nv_bfloat16 l2 = __float2bfloat16(v.z - __bfloat162float(h2));
    __nv_bfloat16 l3 = __float2bfloat16(v.w - __bfloat162float(h3));
    *(__nv_bfloat162*)(h + i)     = __nv_bfloat162(h0, h1);
    *(__nv_bfloat162*)(h + i + 2) = __nv_bfloat162(h2, h3);
    *(__nv_bfloat162*)(l + i)     = __nv_bfloat162(l0, l1);
    *(__nv_bfloat162*)(l + i + 2) = __nv_bfloat162(l2, l3);
}

// ---------------- transpose + split, 3 weights in one launch -----------------------
// z=0:Wk -> rows 0-255, z=1:Wrq -> rows 256-511, z=2:Wv -> rows 512-767
__global__ void __launch_bounds__(256) transpose_conv3(
    const float* __restrict__ W0, const float* __restrict__ W1, const float* __restrict__ W2,
    __nv_bfloat16* __restrict__ dh, __nv_bfloat16* __restrict__ dl)
{
    __shared__ float t[32][33];
    int z = blockIdx.z;
    const float* W = (z == 0) ? W0 : ((z == 1) ? W1 : W2);
    int n0 = blockIdx.x << 5, k0 = blockIdx.y << 5;
    int tx = threadIdx.x & 31, ty = threadIdx.x >> 5;
    #pragma unroll
    for (int i = 0; i < 32; i += 8)
        t[ty + i][tx] = W[(size_t)(k0 + ty + i) * SD + n0 + tx];
    __syncthreads();
    #pragma unroll
    for (int i = 0; i < 32; i += 8) {
        float x = t[tx][ty + i];
        int n = z * SD + n0 + ty + i, k = k0 + tx;
        __nv_bfloat16 hh = __float2bfloat16(x);
        dh[(size_t)n * HID + k] = hh;
        dl[(size_t)n * HID + k] = __float2bfloat16(x - __bfloat162float(hh));
    }
}

// ---------------- helpers ----------------
__device__ __forceinline__ float block_reduce_sum256(float v, float* red) {
    int tid = threadIdx.x;
    red[tid] = v; __syncthreads();
    #pragma unroll
    for (int o = 128; o > 0; o >>= 1) {
        if (tid < o) red[tid] += red[tid + o];
        __syncthreads();
    }
    float r = red[0];
    __syncthreads();
    return r;
}

__global__ void init_loss_kernel() { g_loss = 0.0; }

// ===================================================================================
// Skinny split-K GEMM: 64x64 tile over a K-chunk of KC, atomicAdd into pre-zeroed C.
// ===================================================================================
__global__ __launch_bounds__(256) void gemm_small(
    const float* __restrict__ A, int lda,
    const float* __restrict__ W0, const float* __restrict__ W1,
    float* __restrict__ C, int ldc)
{
    __shared__ float As[16][64];
    __shared__ float Bs[16][64];
    int tid = threadIdx.x;
    int m0 = blockIdx.x << 6;
    int n0 = blockIdx.y << 6;
    int kbase = blockIdx.z * KC;
    const float* W = (n0 >> 8) ? W1 : W0;
    int col0 = n0 & 255;

    int r = tid >> 2, c = (tid & 3) << 2;
    int br = tid >> 4, bc = (tid & 15) << 2;
    int tx = (tid & 15) << 2, ty = (tid >> 4) << 2;

    float acc[4][4] = {};
    for (int k0 = kbase; k0 < kbase + KC; k0 += 16) {
        float4 av = *(const float4*)(A + (size_t)(m0 + r) * lda + k0 + c);
        As[c + 0][r] = av.x; As[c + 1][r] = av.y; As[c + 2][r] = av.z; As[c + 3][r] = av.w;
        *(float4*)&Bs[br][bc] = *(const float4*)(W + (size_t)(k0 + br) * 256 + col0 + bc);
        __syncthreads();
        #pragma unroll
        for (int kk = 0; kk < 16; kk++) {
            float4 a = *(const float4*)&As[kk][ty];
            float4 b = *(const float4*)&Bs[kk][tx];
            acc[0][0] += a.x * b.x; acc[0][1] += a.x * b.y; acc[0][2] += a.x * b.z; acc[0][3] += a.x * b.w;
            acc[1][0] += a.y * b.x; acc[1][1] += a.y * b.y; acc[1][2] += a.y * b.z; acc[1][3] += a.y * b.w;
            acc[2][0] += a.z * b.x; acc[2][1] += a.z * b.y; acc[2][2] += a.z * b.z; acc[2][3] += a.z * b.w;
            acc[3][0] += a.w * b.x; acc[3][1] += a.w * b.y; acc[3][2] += a.w * b.z; acc[3][3] += a.w * b.w;
        }
        __syncthreads();
    }
    #pragma unroll
    for (int i = 0; i < 4; i++)
        #pragma unroll
        for (int j = 0; j < 4; j++)
            atomicAdd(C + (size_t)(m0 + ty + i) * ldc + n0 + tx + j, acc[i][j]);
}

// ---------------- attn1 scores (k at kvr offset 0) ----------------
__global__ __launch_bounds__(256) void scores1_kernel()
{
    __shared__ float Qs[16][64];
    __shared__ float Ks[16][64];
    int tid = threadIdx.x;
    int t0 = blockIdx.x << 6;
    int b = blockIdx.y;
    int r = tid >> 2, c = (tid & 3) << 2;
    int tx = (tid & 15) << 2, ty = (tid >> 4) << 2;

    float acc[4][4] = {};
    for (int k0 = 0; k0 < SD; k0 += 16) {
        float4 qv = *(const float4*)(g_q + (size_t)r * SD + k0 + c);
        Qs[c + 0][r] = qv.x; Qs[c + 1][r] = qv.y; Qs[c + 2][r] = qv.z; Qs[c + 3][r] = qv.w;
        float4 kv = *(const float4*)(g_kvr + (size_t)(b * NT + t0 + r) * 768 + k0 + c);
        Ks[c + 0][r] = kv.x; Ks[c + 1][r] = kv.y; Ks[c + 2][r] = kv.z; Ks[c + 3][r] = kv.w;
        __syncthreads();
        #pragma unroll
        for (int kk = 0; kk < 16; kk++) {
            float4 a = *(const float4*)&Qs[kk][ty];
            float4 d = *(const float4*)&Ks[kk][tx];
            acc[0][0] += a.x * d.x; acc[0][1] += a.x * d.y; acc[0][2] += a.x * d.z; acc[0][3] += a.x * d.w;
            acc[1][0] += a.y * d.x; acc[1][1] += a.y * d.y; acc[1][2] += a.y * d.z; acc[1][3] += a.y * d.w;
            acc[2][0] += a.z * d.x; acc[2][1] += a.z * d.y; acc[2][2] += a.z * d.z; acc[2][3] += a.z * d.w;
            acc[3][0] += a.w * d.x; acc[3][1] += a.w * d.y; acc[3][2] += a.w * d.z; acc[3][3] += a.w * d.w;
        }
        __syncthreads();
    }
    #pragma unroll
    for (int i = 0; i < 4; i++)
        #pragma unroll
        for (int j = 0; j < 4; j++)
            g_s1[((size_t)b * NS + ty + i) * NT + t0 + tx + j] = acc[i][j] * ATT_SCALE;
}

__global__ __launch_bounds__(256) void softmax1_kernel()
{
    __shared__ float red[256];
    int tid = threadIdx.x;
    float* row = g_s1 + (size_t)blockIdx.x * NT;

    float m = -1e30f;
    for (int t = tid; t < NT; t += 256) m = fmaxf(m, row[t]);
    red[tid] = m; __syncthreads();
    #pragma unroll
    for (int o = 128; o > 0; o >>= 1) { if (tid < o) red[tid] = fmaxf(red[tid], red[tid + o]); __syncthreads(); }
    m = red[0]; __syncthreads();

    float sum = 0.f;
    for (int t = tid; t < NT; t += 256) { float e = expf(row[t] - m); row[t] = e; sum += e; }
    float tot = block_reduce_sum256(sum, red);
    float inv = 1.0f / tot;
    for (int t = tid; t < NT; t += 256) row[t] *= inv;
}

// pv1: v at kvr offset 512
__global__ __launch_bounds__(256) void pv1_kernel()
{
    __shared__ float As[16][64];
    __shared__ float Bs[16][64];
    int tid = threadIdx.x;
    int n0 = blockIdx.x << 6;
    int kbase = blockIdx.y * KC;
    int b = blockIdx.z;
    int r = tid >> 2, c = (tid & 3) << 2;
    int br = tid >> 4, bc = (tid & 15) << 2;
    int tx = (tid & 15) << 2, ty = (tid >> 4) << 2;

    float acc[4][4] = {};
    for (int k0 = kbase; k0 < kbase + KC; k0 += 16) {
        float4 av = *(const float4*)(g_s1 + ((size_t)b * NS + r) * NT + k0 + c);
        As[c + 0][r] = av.x; As[c + 1][r] = av.y; As[c + 2][r] = av.z; As[c + 3][r] = av.w;
        *(float4*)&Bs[br][bc] = *(const float4*)(g_kvr + (size_t)(b * NT + k0 + br) * 768 + 512 + n0 + bc);
        __syncthreads();
        #pragma unroll
        for (int kk = 0; kk < 16; kk++) {
            float4 a = *(const float4*)&As[kk][ty];
            float4 d = *(const float4*)&Bs[kk][tx];
            acc[0][0] += a.x * d.x; acc[0][1] += a.x * d.y; acc[0][2] += a.x * d.z; acc[0][3] += a.x * d.w;
            acc[1][0] += a.y * d.x; acc[1][1] += a.y * d.y; acc[1][2] += a.y * d.z; acc[1][3] += a.y * d.w;
            acc[2][0] += a.z * d.x; acc[2][1] += a.z * d.y; acc[2][2] += a.z * d.z; acc[2][3] += a.z * d.w;
            acc[3][0] += a.w * d.x; acc[3][1] += a.w * d.y; acc[3][2] += a.w * d.z; acc[3][3] += a.w * d.w;
        }
        __syncthreads();
    }
    #pragma unroll
    for (int i = 0; i < 4; i++)
        #pragma unroll
        for (int j = 0; j < 4; j++)
            atomicAdd(g_out_sd + ((size_t)b * NS + ty + i) * SD + n0 + tx + j, acc[i][j]);
}

__global__ __launch_bounds__(256) void wo_gemm(
    const float* __restrict__ Wo, const float* __restrict__ slot_emb)
{
    __shared__ float As[16][64];
    __shared__ float Bs[16][64];
    int tid = threadIdx.x;
    int m0 = blockIdx.x << 6;
    int n0 = blockIdx.y << 6;
    int r = tid >> 2, c = (tid & 3) << 2;
    int br = tid >> 4, bc = (tid & 15) << 2;
    int tx = (tid & 15) << 2, ty = (tid >> 4) << 2;

    float acc[4][4] = {};
    for (int k0 = 0; k0 < SD; k0 += 16) {
        float4 av = *(const float4*)(g_out_sd + (size_t)(m0 + r) * SD + k0 + c);
        As[c + 0][r] = av.x; As[c + 1][r] = av.y; As[c + 2][r] = av.z; As[c + 3][r] = av.w;
        *(float4*)&Bs[br][bc] = *(const float4*)(Wo + (size_t)(k0 + br) * HID + n0 + bc);
        __syncthreads();
        #pragma unroll
        for (int kk = 0; kk < 16; kk++) {
            float4 a = *(const float4*)&As[kk][ty];
            float4 d = *(const float4*)&Bs[kk][tx];
            acc[0][0] += a.x * d.x; acc[0][1] += a.x * d.y; acc[0][2] += a.x * d.z; acc[0][3] += a.x * d.w;
            acc[1][0] += a.y * d.x; acc[1][1] += a.y * d.y; acc[1][2] += a.y * d.z; acc[1][3] += a.y * d.w;
            acc[2][0] += a.z * d.x; acc[2][1] += a.z * d.y; acc[2][2] += a.z * d.z; acc[2][3] += a.z * d.w;
            acc[3][0] += a.w * d.x; acc[3][1] += a.w * d.y; acc[3][2] += a.w * d.z; acc[3][3] += a.w * d.w;
        }
        __syncthreads();
    }
    #pragma unroll
    for (int i = 0; i < 4; i++) {
        int row = m0 + ty + i;
        int s = row & 63;
        #pragma unroll
        for (int j = 0; j < 4; j++) {
            int col = n0 + tx + j;
            g_spre[(size_t)row * HID + col] = acc[i][j] + slot_emb[(size_t)s * HID + col];
        }
    }
}

__global__ __launch_bounds__(256) void ln_rows_kernel(
    const float* __restrict__ src, const float* __restrict__ w,
    const float* __restrict__ bb, float* __restrict__ dst)
{
    __shared__ float red[256];
    int tid = threadIdx.x, rrow = blockIdx.x;
    const float* row = src + (size_t)rrow * HID;

    float v[16];
    #pragma unroll
    for (int i = 0; i < 16; i++) v[i] = row[tid + (i << 8)];
    float sum = 0.f, sq = 0.f;
    #pragma unroll
    for (int i = 0; i < 16; i++) { sum += v[i]; sq += v[i] * v[i]; }
    float tsum = block_reduce_sum256(sum, red);
    float tsq  = block_reduce_sum256(sq, red);
    float mu = tsum * (1.0f / HID);
    float var = tsq * (1.0f / HID) - mu * mu;
    float invs = rsqrtf(var + LN_EPS);
    #pragma unroll
    for (int i = 0; i < 16; i++) {
        int col = tid + (i << 8);
        dst[(size_t)rrow * HID + col] = (v[i] - mu) * invs * w[col] + bb[col];
    }
}

// scores2: rq at kvr offset 256
__global__ __launch_bounds__(256) void scores2_kernel()
{
    __shared__ float As[16][64];
    __shared__ float Bs[16][64];
    int tid = threadIdx.x;
    int t0 = blockIdx.x << 6;
    int b = blockIdx.y;
    int r = tid >> 2, c = (tid & 3) << 2;
    int tx = (tid & 15) << 2, ty = (tid >> 4) << 2;

    float acc[4][4] = {};
    for (int k0 = 0; k0 < SD; k0 += 16) {
        float4 av = *(const float4*)(g_kvr + (size_t)(b * NT + t0 + r) * 768 + 256 + k0 + c);
        As[c + 0][r] = av.x; As[c + 1][r] = av.y; As[c + 2][r] = av.z; As[c + 3][r] = av.w;
        float4 kv = *(const float4*)(g_rkv + (size_t)(b * NS + r) * 512 + k0 + c);
        Bs[c + 0][r] = kv.x; Bs[c + 1][r] = kv.y; Bs[c + 2][r] = kv.z; Bs[c + 3][r] = kv.w;
        __syncthreads();
        #pragma unroll
        for (int kk = 0; kk < 16; kk++) {
            float4 a = *(const float4*)&As[kk][ty];
            float4 d = *(const float4*)&Bs[kk][tx];
            acc[0][0] += a.x * d.x; acc[0][1] += a.x * d.y; acc[0][2] += a.x * d.z; acc[0][3] += a.x * d.w;
            acc[1][0] += a.y * d.x; acc[1][1] += a.y * d.y; acc[1][2] += a.y * d.z; acc[1][3] += a.y * d.w;
            acc[2][0] += a.z * d.x; acc[2][1] += a.z * d.y; acc[2][2] += a.z * d.z; acc[2][3] += a.z * d.w;
            acc[3][0] += a.w * d.x; acc[3][1] += a.w * d.y; acc[3][2] += a.w * d.z; acc[3][3] += a.w * d.w;
        }
        __syncthreads();
    }
    #pragma unroll
    for (int i = 0; i < 4; i++)
        #pragma unroll
        for (int j = 0; j < 4; j++)
            g_s2[((size_t)b * NT + t0 + ty + i) * NS + tx + j] = acc[i][j] * ATT_SCALE;
}

// softmax over s (64) per (b,t) row; writes NORMALIZED probs as bf16 to g_p2h
__global__ __launch_bounds__(256) void softmax2_kernel()
{
    int tid = threadIdx.x;
    int row = (blockIdx.x << 3) + (tid >> 5);
    int lane = tid & 31;
    const float* p = g_s2 + (size_t)row * NS;
    float v0 = p[lane], v1 = p[lane + 32];
    float m = fmaxf(v0, v1);
    #pragma unroll
    for (int o = 16; o > 0; o >>= 1) m = fmaxf(m, __shfl_xor_sync(0xffffffffu, m, o));
    float e0 = expf(v0 - m), e1 = expf(v1 - m);
    float s = e0 + e1;
    #pragma unroll
    for (int o = 16; o > 0; o >>= 1) s += __shfl_xor_sync(0xffffffffu, s, o);
    float inv = 1.0f / s;
    g_p2h[(size_t)row * NS + lane]      = __float2bfloat16(e0 * inv);
    g_p2h[(size_t)row * NS + lane + 32] = __float2bfloat16(e1 * inv);
}

// rvWT[b][n][s] = sum_k rv[b][s][k] * Wro[k][n], written transposed as bf16.
__global__ __launch_bounds__(256) void rvw_gemm(const float* __restrict__ Wro)
{
    __shared__ float As[16][64];
    __shared__ float Bs[16][64];
    int tid = threadIdx.x;
    int n0 = blockIdx.x << 6;
    int b = blockIdx.y;
    int r = tid >> 2, c = (tid & 3) << 2;
    int br = tid >> 4, bc = (tid & 15) << 2;
    int tx = (tid & 15) << 2, ty = (tid >> 4) << 2;

    float acc[4][4] = {};
    for (int k0 = 0; k0 < SD; k0 += 16) {
        float4 av = *(const float4*)(g_rkv + (size_t)(b * NS + r) * 512 + 256 + k0 + c);
        As[c + 0][r] = av.x; As[c + 1][r] = av.y; As[c + 2][r] = av.z; As[c + 3][r] = av.w;
        *(float4*)&Bs[br][bc] = *(const float4*)(Wro + (size_t)(k0 + br) * HID + n0 + bc);
        __syncthreads();
        #pragma unroll
        for (int kk = 0; kk < 16; kk++) {
            float4 a = *(const float4*)&As[kk][ty];
            float4 d = *(const float4*)&Bs[kk][tx];
            acc[0][0] += a.x * d.x; acc[0][1] += a.x * d.y; acc[0][2] += a.x * d.z; acc[0][3] += a.x * d.w;
            acc[1][0] += a.y * d.x; acc[1][1] += a.y * d.y; acc[1][2] += a.y * d.z; acc[1][3] += a.y * d.w;
            acc[2][0] += a.z * d.x; acc[2][1] += a.z * d.y; acc[2][2] += a.z * d.z; acc[2][3] += a.z * d.w;
            acc[3][0] += a.w * d.x; acc[3][1] += a.w * d.y; acc[3][2] += a.w * d.z; acc[3][3] += a.w * d.w;
        }
        __syncthreads();
    }
    __nv_bfloat16* dst = g_rvwt + (size_t)b * HID * NS;
    #pragma unroll
    for (int i = 0; i < 4; i++)
        #pragma unroll
        for (int j = 0; j < 4; j++)
            dst[(size_t)(n0 + tx + j) * NS + ty + i] = __float2bfloat16(acc[i][j]);
}

// ---------------- per-row LN + gate + squared-error accumulation (bf16 inputs) ------
__global__ __launch_bounds__(256) void loss_ln_kernel(
    const float* __restrict__ lnw, const float* __restrict__ lnb,
    const float* __restrict__ gate_bias)
{
    __shared__ float red[256];
    __shared__ float gsh;
    int tid = threadIdx.x, rrow = blockIdx.x;
    const __nv_bfloat162* row = (const __nv_bfloat162*)(g_routb + (size_t)rrow * HID);

    float2 v[8];
    #pragma unroll
    for (int i = 0; i < 8; i++) {
        __nv_bfloat162 t = row[tid + (i << 8)];
        v[i] = make_float2(__bfloat162float(t.x), __bfloat162float(t.y));
    }

    if (tid == 0) {
        float sg = 0.f;
        for (int i = 0; i < 64; i++) sg += gate_bias[i];
        sg *= (1.0f / 64.0f);
        gsh = 1.0f / (1.0f + expf(-sg));
    }

    float sum = 0.f, sq = 0.f;
    #pragma unroll
    for (int i = 0; i < 8; i++) {
        sum += v[i].x + v[i].y;
        sq += v[i].x * v[i].x + v[i].y * v[i].y;
    }
    float tsum = block_reduce_sum256(sum, red);
    float tsq  = block_reduce_sum256(sq, red);
    float mu = tsum * (1.0f / HID);
    float var = tsq * (1.0f / HID) - mu * mu;
    float invs = rsqrtf(var + LN_EPS);
    float g = gsh;

    const __nv_bfloat162* segrow = (const __nv_bfloat162*)(g_segh + (size_t)rrow * HID);
    float acc = 0.f;
    #pragma unroll
    for (int i = 0; i < 8; i++) {
        int col = (tid + (i << 8)) * 2;
        float2 wv = *(const float2*)(lnw + col);
        float2 bv = *(const float2*)(lnb + col);
        __nv_bfloat162 st = segrow[tid + (i << 8)];
        float r0 = g * ((v[i].x - mu) * invs * wv.x + bv.x) - __bfloat162float(st.x);
        float r1 = g * ((v[i].y - mu) * invs * wv.y + bv.y) - __bfloat162float(st.y);
        acc += r0 * r0 + r1 * r1;
    }
    float bsum = block_reduce_sum256(acc, red);
    if (tid == 0) atomicAdd(&g_loss, (double)bsum);
}

__global__ void finalize_kernel(const float* __restrict__ gate_bias, float* __restrict__ outp)
{
    float sg = 0.f;
    for (int i = 0; i < 64; i++) sg += gate_bias[i];
    sg *= (1.0f / 64.0f);
    float g = 1.0f / (1.0f + expf(-sg));
    outp[NB * NS * HID]     = (float)(g_loss / (double)((size_t)NB * NT * HID));
    outp[NB * NS * HID + 1] = g;
}

// ---------------- launch ------------------------------------------------------------
extern "C" void kernel_launch(void* const* d_in, const int* in_sizes, int n_in,
                              void* d_out, int out_size)
{
    const float* seg      = (const float*)d_in[0];
    const float* slot_emb = (const float*)d_in[1];
    const float* Wq       = (const float*)d_in[2];
    const float* Wk       = (const float*)d_in[3];
    const float* Wv       = (const float*)d_in[4];
    const float* Wo       = (const float*)d_in[5];
    const float* Wrq      = (const float*)d_in[6];
    const float* Wro      = (const float*)d_in[7];
    const float* gateb    = (const float*)d_in[8];
    const float* snw      = (const float*)d_in[9];
    const float* snb      = (const float*)d_in[10];
    const float* rnw      = (const float*)d_in[11];
    const float* rnb      = (const float*)d_in[12];
    float* outp = (float*)d_out;

    float* kvr;      cudaGetSymbolAddress((void**)&kvr, g_kvr);
    float* qbuf;     cudaGetSymbolAddress((void**)&qbuf, g_q);
    float* out_sd;   cudaGetSymbolAddress((void**)&out_sd, g_out_sd);
    float* spre;     cudaGetSymbolAddress((void**)&spre, g_spre);
    float* rkv;      cudaGetSymbolAddress((void**)&rkv, g_rkv);
    __nv_bfloat16 *segh, *segl, *WTh, *WTl, *p2h, *rvwt, *routb;
    cudaGetSymbolAddress((void**)&segh, g_segh);
    cudaGetSymbolAddress((void**)&segl, g_segl);
    cudaGetSymbolAddress((void**)&WTh, g_WTh);
    cudaGetSymbolAddress((void**)&WTl, g_WTl);
    cudaGetSymbolAddress((void**)&p2h, g_p2h);
    cudaGetSymbolAddress((void**)&rvwt, g_rvwt);
    cudaGetSymbolAddress((void**)&routb, g_routb);

    const int SMEM_V    = 2 * (32768 + 65536);  // TERMS=3, BN=256: 192 KB
    const int SMEM_KRQ  = 2 * (16384 + 32768);  // TERMS=1, BN=256: 96 KB
    const int SMEM_ROUT = 2 * (16384 + 16384);  // TERMS=1, BN=128: 64 KB
    cudaFuncSetAttribute(hmma_gemm<3,0,256>, cudaFuncAttributeMaxDynamicSharedMemorySize, SMEM_V);
    cudaFuncSetAttribute(hmma_gemm<1,0,256>, cudaFuncAttributeMaxDynamicSharedMemorySize, SMEM_KRQ);
    cudaFuncSetAttribute(hmma_gemm<1,1,128>, cudaFuncAttributeMaxDynamicSharedMemorySize, SMEM_ROUT);

    init_loss_kernel<<<1, 1>>>();
    cudaMemsetAsync(qbuf, 0, (size_t)NS * SD * sizeof(float));
    cudaMemsetAsync(out_sd, 0, (size_t)NB * NS * SD * sizeof(float));
    cudaMemsetAsync(rkv, 0, (size_t)NB * NS * 512 * sizeof(float));

    // bf16 splits: seg, transposed weights [Wk|Wrq|Wv] -> WT[768][4096]
    conv_hilo<<<(size_t)BT * HID / 1024, 256>>>(seg, segh, segl);
    transpose_conv3<<<dim3(SD / 32, HID / 32, 3), 256>>>(Wk, Wrq, Wv, WTh, WTl);

    // v = seg @ Wv — 3-pass split (feeds updated_slots), single wave (128 blocks)
    hmma_gemm<3,0,256><<<dim3(1, BT / 128), 256, SMEM_V>>>(
        segh, segl, WTh + 512 * HID, WTl + 512 * HID, kvr + 512, 768, HID, 0, 0, 0);
    // k | rq = seg @ {Wk,Wrq} — 1-pass bf16 (score paths: softmax-damped / loss-only)
    hmma_gemm<1,0,256><<<dim3(2, BT / 128), 256, SMEM_KRQ>>>(
        segh, segl, WTh, WTl, kvr, 768, HID, 0, 0, 0);

    // q = slot_embeddings @ Wq  (split-K fp32)
    gemm_small<<<dim3(1, 4, 8), 256>>>(slot_emb, HID, Wq, nullptr, qbuf, SD);

    // attn1
    scores1_kernel<<<dim3(64, NB), 256>>>();
    softmax1_kernel<<<NB * NS, 256>>>();
    pv1_kernel<<<dim3(4, 8, NB), 256>>>();

    // slots + out@Wo, LN -> updated_slots in d_out
    wo_gemm<<<dim3(4, 64), 256>>>(Wo, slot_emb);
    ln_rows_kernel<<<NB * NS, 256>>>(spre, snw, snb, outp);

    // rk | rv = updated_slots @ {Wk, Wv}
    gemm_small<<<dim3(4, 8, 8), 256>>>(outp, HID, Wk, Wv, rkv, 512);

    // attn2 scores + softmax (P2 -> bf16)
    scores2_kernel<<<dim3(64, NB), 256>>>();
    softmax2_kernel<<<BT / 8, 256>>>();

    // rvW^T = (rv @ Wro)^T per batch (bf16)
    rvw_gemm<<<dim3(HID / 64, NB), 256>>>(Wro);

    // rout = P2 @ rvW  (K=64, bf16 out), batched over grid.z
    hmma_gemm<1,1,128><<<dim3(HID / 128, NT / 128, NB), 256, SMEM_ROUT>>>(
        p2h, nullptr, rvwt, nullptr, routb, HID, NS,
        (size_t)NT * NS, (size_t)HID * NS, (size_t)NT * HID);

    // LN + gate + MSE
    loss_ln_kernel<<<BT, 256>>>(rnw, rnb, gateb);
    finalize_kernel<<<1, 1>>>(gateb, outp);
}